// round 6
// baseline (speedup 1.0000x reference)
#include <cuda_runtime.h>
#include <cuda_fp16.h>
#include <stdint.h>

#define DIM 64
#define NT 1024
#define MQ 128                  // queries per CTA
#define NCH 128                 // codes per chunk
#define NCHUNKS (NT / NCH)      // 8
#define MAX_Q (64 * 4096)
// Hard bound: |score err| <= 2^-10 * ||x|| (<= 11) + accum eps; pairwise <= 0.023
#define DELTA 0.025f

// ---------------- global scratch (no allocation allowed) ----------------
__device__ int    g_ids[MAX_Q];
__device__ float  g_hcsq[NT];           // 0.5*||c||^2
__device__ __half g_Bh[NT * DIM];       // codebook fp16, swizzled chunk-major tiles
__device__ int    g_nrescue;
__device__ int    g_rescue[MAX_Q];

// ---------------- helpers ----------------
__device__ __forceinline__ uint32_t smem_u32(const void* p) {
    uint32_t a;
    asm("{ .reg .u64 t; cvta.to.shared.u64 t, %1; cvt.u32.u64 %0, t; }"
        : "=r"(a) : "l"(p));
    return a;
}
__device__ __forceinline__ void ldm_x4(uint32_t* r, uint32_t addr) {
    asm volatile("ldmatrix.sync.aligned.m8n8.x4.shared.b16 {%0,%1,%2,%3}, [%4];"
                 : "=r"(r[0]), "=r"(r[1]), "=r"(r[2]), "=r"(r[3]) : "r"(addr));
}
__device__ __forceinline__ void mma_f16(float* c, const uint32_t* a,
                                        uint32_t b0, uint32_t b1) {
    asm volatile(
        "mma.sync.aligned.m16n8k16.row.col.f32.f16.f16.f32 "
        "{%0,%1,%2,%3}, {%4,%5,%6,%7}, {%8,%9}, {%0,%1,%2,%3};"
        : "+f"(c[0]), "+f"(c[1]), "+f"(c[2]), "+f"(c[3])
        : "r"(a[0]), "r"(a[1]), "r"(a[2]), "r"(a[3]), "r"(b0), "r"(b1));
}
__device__ __forceinline__ void cpa16(uint32_t dst, const void* src) {
    asm volatile("cp.async.cg.shared.global [%0], [%1], 16;" :: "r"(dst), "l"(src));
}
#define CPA_COMMIT() asm volatile("cp.async.commit_group;" ::: "memory")
#define CPA_WAIT0()  asm volatile("cp.async.wait_group 0;" ::: "memory")

// Tile geometry: rows x 128 bytes (64 fp16). 16B-chunk XOR swizzle (proven R4).
__device__ __forceinline__ uint32_t sw_off(int row, int chunk) {
    return (uint32_t)row * 128u + (uint32_t)((chunk ^ (row & 7)) << 4);
}

// ---------------- smem map (dynamic, 53248 B) ----------------
#define SM_A   0          // 16 KB (query tile fp16, swizzled)
#define SM_B   16384      // 2 stages x 16 KB = 32 KB
#define SM_HC  49152      // 4 KB
#define SMEM_TOTAL 53248

// ---------------------------------------------------------------------------
// prep: hcsq + codebook fp16 swizzled chunk-major tiles; reset rescue counter.
// ---------------------------------------------------------------------------
__global__ void prep_kernel(const float* __restrict__ cb) {
    int t = blockIdx.x * blockDim.x + threadIdx.x;
    if (t == 0) g_nrescue = 0;
    if (t >= NT * 16) return;
    int n = t >> 4, kq = t & 15;                 // kq: float4 index 0..15
    float4 v = *(const float4*)(cb + (size_t)n * DIM + kq * 4);
    __half h[4];
    h[0] = __float2half_rn(v.x); h[1] = __float2half_rn(v.y);
    h[2] = __float2half_rn(v.z); h[3] = __float2half_rn(v.w);
    int ch = n >> 7, ln = n & 127;
    uint32_t off = (uint32_t)ch * 16384u + sw_off(ln, kq >> 1) + (kq & 1) * 8;
    *(uint2*)((char*)g_Bh + off) = *(uint2*)h;
    if (kq == 0) {
        const float4* row = (const float4*)(cb + (size_t)n * DIM);
        float s = 0.f;
#pragma unroll
        for (int i = 0; i < 16; i++) {
            float4 w = row[i];
            s += w.x * w.x + w.y * w.y + w.z * w.z + w.w * w.w;
        }
        g_hcsq[n] = 0.5f * s;
    }
}

// ---------------------------------------------------------------------------
// main: single-pass fp16 mma.sync GEMM + running top-2 argmax.
// 8 warps = 2(m) x 4(n); warp tile 64 x 32; full K=64 per chunk.
// ---------------------------------------------------------------------------
__global__ void __launch_bounds__(256, 1)
vq_mma_kernel(const float* __restrict__ codes) {
    extern __shared__ char smem[];
    const uint32_t sb = smem_u32(smem);
    const int tid  = threadIdx.x;
    const int wid  = tid >> 5, lane = tid & 31;
    const int wm   = wid >> 2;           // 0..1 -> m offset 0/64
    const int wn   = wid & 3;            // 0..3 -> n offset 0/32/64/96
    const int qbase = blockIdx.x * MQ;

    // prefetch B chunk 0 -> stage 0
    for (int i = tid; i < 1024; i += 256)
        cpa16(sb + SM_B + i * 16, (const char*)g_Bh + i * 16);
    CPA_COMMIT();

    // hcsq -> smem
    for (int i = tid; i < NT / 4; i += 256)
        ((float4*)(smem + SM_HC))[i] = ((const float4*)g_hcsq)[i];

    // A tile: load fp32, convert fp16, store swizzled
    for (int i = tid; i < MQ * 16; i += 256) {
        int m = i >> 4, kq = i & 15;
        float4 v = *(const float4*)(codes + (size_t)(qbase + m) * DIM + kq * 4);
        __half h[4];
        h[0] = __float2half_rn(v.x); h[1] = __float2half_rn(v.y);
        h[2] = __float2half_rn(v.z); h[3] = __float2half_rn(v.w);
        uint32_t off = sw_off(m, kq >> 1) + (kq & 1) * 8;
        *(uint2*)(smem + SM_A + off) = *(uint2*)h;
    }

    float b1[8], b2[8];
    int   i1[8];
#pragma unroll
    for (int r = 0; r < 8; r++) { b1[r] = -1e30f; b2[r] = -1e30f; i1[r] = 0; }

    const float* hc = (const float*)(smem + SM_HC);

    for (int c = 0; c < NCHUNKS; c++) {
        const int st = c & 1;
        CPA_WAIT0();
        __syncthreads();          // chunk c resident; all warps done with prev stage

        if (c + 1 < NCHUNKS) {    // prefetch chunk c+1 into the other stage
            const char* bh = (const char*)g_Bh + (size_t)(c + 1) * 16384;
            uint32_t dst = sb + SM_B + (st ^ 1) * 16384;
            for (int i = tid; i < 1024; i += 256)
                cpa16(dst + i * 16, bh + i * 16);
            CPA_COMMIT();
        }

        float acc[4][4][4];
#pragma unroll
        for (int mi = 0; mi < 4; mi++)
#pragma unroll
            for (int nj = 0; nj < 4; nj++)
#pragma unroll
                for (int e = 0; e < 4; e++) acc[mi][nj][e] = 0.f;

        const uint32_t aBase = sb + SM_A;
        const uint32_t bBase = sb + SM_B + st * 16384;

#pragma unroll
        for (int ks = 0; ks < 4; ks++) {
            uint32_t af[4][4];
#pragma unroll
            for (int mi = 0; mi < 4; mi++) {
                int ra = wm * 64 + mi * 16 + (lane & 15);
                ldm_x4(af[mi], aBase + sw_off(ra, ks * 2 + (lane >> 4)));
            }
            uint32_t bf[2][4];
#pragma unroll
            for (int ni2 = 0; ni2 < 2; ni2++) {
                int rb = wn * 32 + ni2 * 16 + (lane & 7) + ((lane & 16) ? 8 : 0);
                ldm_x4(bf[ni2], bBase + sw_off(rb, ks * 2 + ((lane >> 3) & 1)));
            }
#pragma unroll
            for (int mi = 0; mi < 4; mi++)
#pragma unroll
                for (int nj = 0; nj < 4; nj++)
                    mma_f16(acc[mi][nj], af[mi],
                            bf[nj >> 1][(nj & 1) * 2], bf[nj >> 1][(nj & 1) * 2 + 1]);
        }

        // epilogue: top-2 update (n ascending in scan order per row)
#pragma unroll
        for (int mi = 0; mi < 4; mi++)
#pragma unroll
            for (int h = 0; h < 2; h++) {
                int ri = mi * 2 + h;
                float v1 = b1[ri], v2 = b2[ri];
                int   ii = i1[ri];
#pragma unroll
                for (int nj = 0; nj < 4; nj++)
#pragma unroll
                    for (int p = 0; p < 2; p++) {
                        int n = c * NCH + wn * 32 + nj * 8 + (lane & 3) * 2 + p;
                        float v = acc[mi][nj][h * 2 + p] - hc[n];
                        bool gt = v > v1;
                        v2 = gt ? v1 : fmaxf(v2, v);
                        ii = gt ? n : ii;
                        v1 = gt ? v : v1;
                    }
                b1[ri] = v1; b2[ri] = v2; i1[ri] = ii;
            }
    }

    // intra-warp merge over the 4 lanes sharing each row
#pragma unroll
    for (int r = 0; r < 8; r++) {
#pragma unroll
        for (int d = 1; d <= 2; d <<= 1) {
            float ov  = __shfl_xor_sync(0xffffffffu, b1[r], d);
            int   oi  = __shfl_xor_sync(0xffffffffu, i1[r], d);
            float ov2 = __shfl_xor_sync(0xffffffffu, b2[r], d);
            bool take = (ov > b1[r]) || (ov == b1[r] && oi < i1[r]);
            float lose = take ? b1[r] : ov;
            b2[r] = fmaxf(fmaxf(b2[r], ov2), lose);
            if (take) { b1[r] = ov; i1[r] = oi; }
        }
    }

    // cross-warp (wn) merge via smem
    __syncthreads();
    float* rv  = (float*)(smem + SM_A);            // [128][4]
    int*   rix = (int*)(smem + SM_A + 2048);       // [128][4]
    float* r2  = (float*)(smem + SM_A + 4096);     // [128][4]
    if ((lane & 3) == 0) {
#pragma unroll
        for (int mi = 0; mi < 4; mi++)
#pragma unroll
            for (int h = 0; h < 2; h++) {
                int r = mi * 2 + h;
                int row = wm * 64 + mi * 16 + h * 8 + (lane >> 2);
                rv[row * 4 + wn] = b1[r];
                rix[row * 4 + wn] = i1[r];
                r2[row * 4 + wn] = b2[r];
            }
    }
    __syncthreads();
    if (tid < MQ) {
        float bv = rv[tid * 4], bb2 = r2[tid * 4];
        int   bi = rix[tid * 4];
#pragma unroll
        for (int w = 1; w < 4; w++) {
            float ov = rv[tid * 4 + w], ov2 = r2[tid * 4 + w];
            int   oi = rix[tid * 4 + w];
            bool take = (ov > bv) || (ov == bv && oi < bi);
            float lose = take ? bv : ov;
            bb2 = fmaxf(fmaxf(bb2, ov2), lose);
            if (take) { bv = ov; bi = oi; }
        }
        g_ids[qbase + tid] = bi;
        if (bv - bb2 < DELTA) {
            int r = atomicAdd(&g_nrescue, 1);
            g_rescue[r] = qbase + tid;
        }
    }
}

// ---------------------------------------------------------------------------
// rescue: exact fp32 rescan; 8 queries share one codebook sweep per block.
// ---------------------------------------------------------------------------
#define QB 8
__global__ void rescue_kernel(const float* __restrict__ codes,
                              const float* __restrict__ cb) {
    __shared__ float sx[QB][DIM];
    __shared__ float sv[QB][256];
    __shared__ int   si[QB][256];
    int nres = g_nrescue;
    for (int base = blockIdx.x * QB; base < nres; base += gridDim.x * QB) {
        int cnt = min(QB, nres - base);
        __syncthreads();
        for (int i = threadIdx.x; i < cnt * 16; i += 256) {
            int q = i >> 4, kq = i & 15;
            ((float4*)sx[q])[kq] =
                ((const float4*)(codes + (size_t)g_rescue[base + q] * DIM))[kq];
        }
        __syncthreads();
        float bv[QB]; int bi[QB];
#pragma unroll
        for (int q = 0; q < QB; q++) { bv[q] = -1e30f; bi[q] = 0; }
        for (int j = 0; j < 4; j++) {
            int n = threadIdx.x + j * 256;
            const float* cr = cb + (size_t)n * DIM;
            float dot[QB];
#pragma unroll
            for (int q = 0; q < QB; q++) dot[q] = 0.f;
#pragma unroll
            for (int k = 0; k < DIM; k++) {
                float ck = __ldg(&cr[k]);
#pragma unroll
                for (int q = 0; q < QB; q++) dot[q] += sx[q][k] * ck;
            }
            float hcv = g_hcsq[n];
#pragma unroll
            for (int q = 0; q < QB; q++) {
                float s = dot[q] - hcv;
                if (s > bv[q]) { bv[q] = s; bi[q] = n; }
            }
        }
#pragma unroll
        for (int q = 0; q < QB; q++) { sv[q][threadIdx.x] = bv[q]; si[q][threadIdx.x] = bi[q]; }
        __syncthreads();
        int w = threadIdx.x >> 5, lane = threadIdx.x & 31;
        if (w < QB && w < cnt) {
            float v = sv[w][lane]; int ix = si[w][lane];
            for (int t = lane + 32; t < 256; t += 32) {
                float ov = sv[w][t]; int oi = si[w][t];
                if (ov > v || (ov == v && oi < ix)) { v = ov; ix = oi; }
            }
#pragma unroll
            for (int d = 16; d > 0; d >>= 1) {
                float ov = __shfl_down_sync(0xffffffffu, v, d);
                int   oi = __shfl_down_sync(0xffffffffu, ix, d);
                if (ov > v || (ov == v && oi < ix)) { v = ov; ix = oi; }
            }
            if (lane == 0) g_ids[g_rescue[base + w]] = ix;
        }
        __syncthreads();
    }
}

// ---------------------------------------------------------------------------
// gather: codebook[best] -> out_codes; ids as float.
// ---------------------------------------------------------------------------
__global__ void gather_kernel(const float* __restrict__ cb,
                              float* __restrict__ out_codes,
                              float* __restrict__ out_ids,
                              int nq, int write_ids) {
    int t = blockIdx.x * blockDim.x + threadIdx.x;
    if (t < nq * (DIM / 4)) {
        int q = t >> 4, part = t & 15;
        int id = g_ids[q];
        float4 v = *(const float4*)(cb + (size_t)id * DIM + part * 4);
        *(float4*)(out_codes + (size_t)q * DIM + part * 4) = v;
    }
    if (write_ids && t < nq) out_ids[t] = (float)g_ids[t];
}

// ---------------------------------------------------------------------------
extern "C" void kernel_launch(void* const* d_in, const int* in_sizes, int n_in,
                              void* d_out, int out_size) {
    const float* codes = (const float*)d_in[0];
    const float* cb    = (const float*)d_in[1];
    float* out = (float*)d_out;

    int nq = in_sizes[0] / DIM;
    if (nq > MAX_Q) nq = MAX_Q;

    static int attr_done = 0;
    if (!attr_done) {
        cudaFuncSetAttribute(vq_mma_kernel,
                             cudaFuncAttributeMaxDynamicSharedMemorySize, SMEM_TOTAL);
        attr_done = 1;
    }

    prep_kernel<<<(NT * 16 + 255) / 256, 256>>>(cb);
    vq_mma_kernel<<<nq / MQ, 256, SMEM_TOTAL>>>(codes);
    rescue_kernel<<<2048, 256>>>(codes, cb);

    int write_ids = (out_size >= nq * DIM + nq) ? 1 : 0;
    float* out_ids = out + (size_t)nq * DIM;
    int total = nq * (DIM / 4);
    gather_kernel<<<(total + 255) / 256, 256>>>(cb, out, out_ids, nq, write_ids);
}

// round 7
// speedup vs baseline: 1.4183x; 1.4183x over previous
#include <cuda_runtime.h>
#include <cuda_bf16.h>
#include <stdint.h>

#define DIM 64
#define NT 1024
#define MQ 128                  // queries per CTA
#define NCH 128                 // codes per chunk
#define NCHUNKS (NT / NCH)      // 8
#define MAX_Q (64 * 4096)
// 2-pass bf16: score-err std ~1.1e-3 (missing x.c_lo term); 7.5 sigma margin.
#define DELTA 0.012f

// ---------------- global scratch (no allocation allowed) ----------------
__device__ int           g_ids[MAX_Q];
__device__ float         g_hcsq[NT];          // 0.5*||c||^2
__device__ __nv_bfloat16 g_Bh[NT * DIM];      // codebook bf16(hi), swizzled tiles
__device__ int           g_nrescue;
__device__ int           g_rescue[MAX_Q];

// ---------------- helpers ----------------
__device__ __forceinline__ uint32_t smem_u32(const void* p) {
    uint32_t a;
    asm("{ .reg .u64 t; cvta.to.shared.u64 t, %1; cvt.u32.u64 %0, t; }"
        : "=r"(a) : "l"(p));
    return a;
}
__device__ __forceinline__ void ldm_x4(uint32_t* r, uint32_t addr) {
    asm volatile("ldmatrix.sync.aligned.m8n8.x4.shared.b16 {%0,%1,%2,%3}, [%4];"
                 : "=r"(r[0]), "=r"(r[1]), "=r"(r[2]), "=r"(r[3]) : "r"(addr));
}
__device__ __forceinline__ void mma_bf16(float* c, const uint32_t* a,
                                         uint32_t b0, uint32_t b1) {
    asm volatile(
        "mma.sync.aligned.m16n8k16.row.col.f32.bf16.bf16.f32 "
        "{%0,%1,%2,%3}, {%4,%5,%6,%7}, {%8,%9}, {%0,%1,%2,%3};"
        : "+f"(c[0]), "+f"(c[1]), "+f"(c[2]), "+f"(c[3])
        : "r"(a[0]), "r"(a[1]), "r"(a[2]), "r"(a[3]), "r"(b0), "r"(b1));
}
__device__ __forceinline__ void cpa16(uint32_t dst, const void* src) {
    asm volatile("cp.async.cg.shared.global [%0], [%1], 16;" :: "r"(dst), "l"(src));
}
#define CPA_COMMIT() asm volatile("cp.async.commit_group;" ::: "memory")
#define CPA_WAIT0()  asm volatile("cp.async.wait_group 0;" ::: "memory")

// Tile geometry: rows x 128 bytes (64 bf16). 16B-chunk XOR swizzle (proven R4).
__device__ __forceinline__ uint32_t sw_off(int row, int chunk) {
    return (uint32_t)row * 128u + (uint32_t)((chunk ^ (row & 7)) << 4);
}
__device__ __forceinline__ void split2(float x, __nv_bfloat16& h, __nv_bfloat16& l) {
    h = __float2bfloat16_rn(x);
    l = __float2bfloat16_rn(x - __bfloat162float(h));
}

// ---------------- smem map (dynamic, 69632 B) ----------------
#define SM_AHI 0          // 16 KB
#define SM_ALO 16384      // 16 KB
#define SM_B   32768      // 2 stages x 16 KB = 32 KB (B hi only)
#define SM_HC  65536      // 4 KB
#define SMEM_TOTAL 69632

// ---------------------------------------------------------------------------
// prep: hcsq + codebook bf16(hi) swizzled chunk-major tiles; reset counter.
// ---------------------------------------------------------------------------
__global__ void prep_kernel(const float* __restrict__ cb) {
    int t = blockIdx.x * blockDim.x + threadIdx.x;
    if (t == 0) g_nrescue = 0;
    if (t >= NT * 16) return;
    int n = t >> 4, kq = t & 15;
    float4 v = *(const float4*)(cb + (size_t)n * DIM + kq * 4);
    __nv_bfloat16 h[4];
    h[0] = __float2bfloat16_rn(v.x); h[1] = __float2bfloat16_rn(v.y);
    h[2] = __float2bfloat16_rn(v.z); h[3] = __float2bfloat16_rn(v.w);
    int ch = n >> 7, ln = n & 127;
    uint32_t off = (uint32_t)ch * 16384u + sw_off(ln, kq >> 1) + (kq & 1) * 8;
    *(uint2*)((char*)g_Bh + off) = *(uint2*)h;
    if (kq == 0) {
        const float4* row = (const float4*)(cb + (size_t)n * DIM);
        float s = 0.f;
#pragma unroll
        for (int i = 0; i < 16; i++) {
            float4 w = row[i];
            s += w.x * w.x + w.y * w.y + w.z * w.z + w.w * w.w;
        }
        g_hcsq[n] = 0.5f * s;
    }
}

// ---------------------------------------------------------------------------
// main: 2-pass bf16 mma.sync GEMM (Ah*Bh + Al*Bh) + running top-2 argmax.
// 8 warps = 2(m) x 4(n); warp tile 64 x 32; full K=64 per chunk.
// ---------------------------------------------------------------------------
__global__ void __launch_bounds__(256, 1)
vq_mma_kernel(const float* __restrict__ codes) {
    extern __shared__ char smem[];
    const uint32_t sb = smem_u32(smem);
    const int tid  = threadIdx.x;
    const int wid  = tid >> 5, lane = tid & 31;
    const int wm   = wid >> 2;
    const int wn   = wid & 3;
    const int qbase = blockIdx.x * MQ;

    // prefetch B chunk 0 -> stage 0
    for (int i = tid; i < 1024; i += 256)
        cpa16(sb + SM_B + i * 16, (const char*)g_Bh + i * 16);
    CPA_COMMIT();

    // hcsq -> smem
    for (int i = tid; i < NT / 4; i += 256)
        ((float4*)(smem + SM_HC))[i] = ((const float4*)g_hcsq)[i];

    // A tile: load fp32, split hi/lo bf16, store swizzled
    for (int i = tid; i < MQ * 16; i += 256) {
        int m = i >> 4, kq = i & 15;
        float4 v = *(const float4*)(codes + (size_t)(qbase + m) * DIM + kq * 4);
        __nv_bfloat16 h[4], l[4];
        split2(v.x, h[0], l[0]); split2(v.y, h[1], l[1]);
        split2(v.z, h[2], l[2]); split2(v.w, h[3], l[3]);
        uint32_t off = sw_off(m, kq >> 1) + (kq & 1) * 8;
        *(uint2*)(smem + SM_AHI + off) = *(uint2*)h;
        *(uint2*)(smem + SM_ALO + off) = *(uint2*)l;
    }

    float b1[8], b2[8];
    int   i1[8];
#pragma unroll
    for (int r = 0; r < 8; r++) { b1[r] = -1e30f; b2[r] = -1e30f; i1[r] = 0; }

    const float* hc = (const float*)(smem + SM_HC);

    for (int c = 0; c < NCHUNKS; c++) {
        const int st = c & 1;
        CPA_WAIT0();
        __syncthreads();

        if (c + 1 < NCHUNKS) {
            const char* bh = (const char*)g_Bh + (size_t)(c + 1) * 16384;
            uint32_t dst = sb + SM_B + (st ^ 1) * 16384;
            for (int i = tid; i < 1024; i += 256)
                cpa16(dst + i * 16, bh + i * 16);
            CPA_COMMIT();
        }

        float acc[4][4][4];
#pragma unroll
        for (int mi = 0; mi < 4; mi++)
#pragma unroll
            for (int nj = 0; nj < 4; nj++)
#pragma unroll
                for (int e = 0; e < 4; e++) acc[mi][nj][e] = 0.f;

        const uint32_t aHi = sb + SM_AHI, aLo = sb + SM_ALO;
        const uint32_t bBase = sb + SM_B + st * 16384;

#pragma unroll
        for (int ks = 0; ks < 4; ks++) {
            uint32_t ah[4][4], al[4][4];
#pragma unroll
            for (int mi = 0; mi < 4; mi++) {
                int ra = wm * 64 + mi * 16 + (lane & 15);
                uint32_t off = sw_off(ra, ks * 2 + (lane >> 4));
                ldm_x4(ah[mi], aHi + off);
                ldm_x4(al[mi], aLo + off);
            }
            uint32_t bf[2][4];
#pragma unroll
            for (int ni2 = 0; ni2 < 2; ni2++) {
                int rb = wn * 32 + ni2 * 16 + (lane & 7) + ((lane & 16) ? 8 : 0);
                ldm_x4(bf[ni2], bBase + sw_off(rb, ks * 2 + ((lane >> 3) & 1)));
            }
#pragma unroll
            for (int mi = 0; mi < 4; mi++)
#pragma unroll
                for (int nj = 0; nj < 4; nj++) {
                    uint32_t h0 = bf[nj >> 1][(nj & 1) * 2];
                    uint32_t h1 = bf[nj >> 1][(nj & 1) * 2 + 1];
                    mma_bf16(acc[mi][nj], ah[mi], h0, h1);
                    mma_bf16(acc[mi][nj], al[mi], h0, h1);
                }
        }

        // epilogue: top-2 update (proven R4 indexing)
#pragma unroll
        for (int mi = 0; mi < 4; mi++)
#pragma unroll
            for (int h = 0; h < 2; h++) {
                int ri = mi * 2 + h;
                float v1 = b1[ri], v2 = b2[ri];
                int   ii = i1[ri];
#pragma unroll
                for (int nj = 0; nj < 4; nj++)
#pragma unroll
                    for (int p = 0; p < 2; p++) {
                        int n = c * NCH + wn * 32 + nj * 8 + (lane & 3) * 2 + p;
                        float v = acc[mi][nj][h * 2 + p] - hc[n];
                        bool gt = v > v1;
                        v2 = gt ? v1 : fmaxf(v2, v);
                        ii = gt ? n : ii;
                        v1 = gt ? v : v1;
                    }
                b1[ri] = v1; b2[ri] = v2; i1[ri] = ii;
            }
    }

    // intra-warp merge over the 4 lanes sharing each row
#pragma unroll
    for (int r = 0; r < 8; r++) {
#pragma unroll
        for (int d = 1; d <= 2; d <<= 1) {
            float ov  = __shfl_xor_sync(0xffffffffu, b1[r], d);
            int   oi  = __shfl_xor_sync(0xffffffffu, i1[r], d);
            float ov2 = __shfl_xor_sync(0xffffffffu, b2[r], d);
            bool take = (ov > b1[r]) || (ov == b1[r] && oi < i1[r]);
            float lose = take ? b1[r] : ov;
            b2[r] = fmaxf(fmaxf(b2[r], ov2), lose);
            if (take) { b1[r] = ov; i1[r] = oi; }
        }
    }

    // cross-warp (wn) merge via smem
    __syncthreads();
    float* rv  = (float*)(smem + SM_AHI);          // [128][4]
    int*   rix = (int*)(smem + SM_AHI + 2048);     // [128][4]
    float* r2  = (float*)(smem + SM_AHI + 4096);   // [128][4]
    if ((lane & 3) == 0) {
#pragma unroll
        for (int mi = 0; mi < 4; mi++)
#pragma unroll
            for (int h = 0; h < 2; h++) {
                int r = mi * 2 + h;
                int row = wm * 64 + mi * 16 + h * 8 + (lane >> 2);
                rv[row * 4 + wn] = b1[r];
                rix[row * 4 + wn] = i1[r];
                r2[row * 4 + wn] = b2[r];
            }
    }
    __syncthreads();

    // per-query final merge + block-aggregated rescue enqueue (1 global atomic/CTA)
    __shared__ int s_cnt, s_base;
    if (tid == 0) s_cnt = 0;
    __syncthreads();
    int slot = -1;
    if (tid < MQ) {
        float bv = rv[tid * 4], bb2 = r2[tid * 4];
        int   bi = rix[tid * 4];
#pragma unroll
        for (int w = 1; w < 4; w++) {
            float ov = rv[tid * 4 + w], ov2 = r2[tid * 4 + w];
            int   oi = rix[tid * 4 + w];
            bool take = (ov > bv) || (ov == bv && oi < bi);
            float lose = take ? bv : ov;
            bb2 = fmaxf(fmaxf(bb2, ov2), lose);
            if (take) { bv = ov; bi = oi; }
        }
        g_ids[qbase + tid] = bi;
        if (bv - bb2 < DELTA) slot = atomicAdd(&s_cnt, 1);
    }
    __syncthreads();
    if (tid == 0 && s_cnt > 0) s_base = atomicAdd(&g_nrescue, s_cnt);
    __syncthreads();
    if (slot >= 0) g_rescue[s_base + slot] = qbase + tid;
}

// ---------------------------------------------------------------------------
// rescue: exact fp32 rescan; 8 queries share one codebook sweep per block.
// ---------------------------------------------------------------------------
#define QB 8
__global__ void rescue_kernel(const float* __restrict__ codes,
                              const float* __restrict__ cb) {
    __shared__ float sx[QB][DIM];
    __shared__ float sv[QB][256];
    __shared__ int   si[QB][256];
    int nres = g_nrescue;
    for (int base = blockIdx.x * QB; base < nres; base += gridDim.x * QB) {
        int cnt = min(QB, nres - base);
        __syncthreads();
        for (int i = threadIdx.x; i < cnt * 16; i += 256) {
            int q = i >> 4, kq = i & 15;
            ((float4*)sx[q])[kq] =
                ((const float4*)(codes + (size_t)g_rescue[base + q] * DIM))[kq];
        }
        __syncthreads();
        float bv[QB]; int bi[QB];
#pragma unroll
        for (int q = 0; q < QB; q++) { bv[q] = -1e30f; bi[q] = 0; }
        for (int j = 0; j < 4; j++) {
            int n = threadIdx.x + j * 256;
            const float* cr = cb + (size_t)n * DIM;
            float dot[QB];
#pragma unroll
            for (int q = 0; q < QB; q++) dot[q] = 0.f;
#pragma unroll
            for (int k = 0; k < DIM; k++) {
                float ck = __ldg(&cr[k]);
#pragma unroll
                for (int q = 0; q < QB; q++) dot[q] += sx[q][k] * ck;
            }
            float hcv = g_hcsq[n];
#pragma unroll
            for (int q = 0; q < QB; q++) {
                float s = dot[q] - hcv;
                if (s > bv[q]) { bv[q] = s; bi[q] = n; }
            }
        }
#pragma unroll
        for (int q = 0; q < QB; q++) { sv[q][threadIdx.x] = bv[q]; si[q][threadIdx.x] = bi[q]; }
        __syncthreads();
        int w = threadIdx.x >> 5, lane = threadIdx.x & 31;
        if (w < QB && w < cnt) {
            float v = sv[w][lane]; int ix = si[w][lane];
            for (int t = lane + 32; t < 256; t += 32) {
                float ov = sv[w][t]; int oi = si[w][t];
                if (ov > v || (ov == v && oi < ix)) { v = ov; ix = oi; }
            }
#pragma unroll
            for (int d = 16; d > 0; d >>= 1) {
                float ov = __shfl_down_sync(0xffffffffu, v, d);
                int   oi = __shfl_down_sync(0xffffffffu, ix, d);
                if (ov > v || (ov == v && oi < ix)) { v = ov; ix = oi; }
            }
            if (lane == 0) g_ids[g_rescue[base + w]] = ix;
        }
        __syncthreads();
    }
}

// ---------------------------------------------------------------------------
// gather: codebook[best] -> out_codes; ids as float.
// ---------------------------------------------------------------------------
__global__ void gather_kernel(const float* __restrict__ cb,
                              float* __restrict__ out_codes,
                              float* __restrict__ out_ids,
                              int nq, int write_ids) {
    int t = blockIdx.x * blockDim.x + threadIdx.x;
    if (t < nq * (DIM / 4)) {
        int q = t >> 4, part = t & 15;
        int id = g_ids[q];
        float4 v = *(const float4*)(cb + (size_t)id * DIM + part * 4);
        *(float4*)(out_codes + (size_t)q * DIM + part * 4) = v;
    }
    if (write_ids && t < nq) out_ids[t] = (float)g_ids[t];
}

// ---------------------------------------------------------------------------
extern "C" void kernel_launch(void* const* d_in, const int* in_sizes, int n_in,
                              void* d_out, int out_size) {
    const float* codes = (const float*)d_in[0];
    const float* cb    = (const float*)d_in[1];
    float* out = (float*)d_out;

    int nq = in_sizes[0] / DIM;
    if (nq > MAX_Q) nq = MAX_Q;

    static int attr_done = 0;
    if (!attr_done) {
        cudaFuncSetAttribute(vq_mma_kernel,
                             cudaFuncAttributeMaxDynamicSharedMemorySize, SMEM_TOTAL);
        attr_done = 1;
    }

    prep_kernel<<<(NT * 16 + 255) / 256, 256>>>(cb);
    vq_mma_kernel<<<nq / MQ, 256, SMEM_TOTAL>>>(codes);
    rescue_kernel<<<2048, 256>>>(codes, cb);

    int write_ids = (out_size >= nq * DIM + nq) ? 1 : 0;
    float* out_ids = out + (size_t)nq * DIM;
    int total = nq * (DIM / 4);
    gather_kernel<<<(total + 255) / 256, 256>>>(cb, out, out_ids, nq, write_ids);
}

// round 8
// speedup vs baseline: 1.4225x; 1.0029x over previous
#include <cuda_runtime.h>
#include <cuda_bf16.h>
#include <stdint.h>

#define DIM 64
#define NT 1024
#define MQ 128                  // queries per CTA
#define NCH 128                 // codes per chunk
#define NCHUNKS (NT / NCH)      // 8
#define MAX_Q (64 * 4096)
// 2-pass bf16: score-err std ~1.1e-3 (missing x.c_lo term); 7.5 sigma margin.
#define DELTA 0.012f

// ---------------- global scratch (no allocation allowed) ----------------
__device__ int           g_ids[MAX_Q];
__device__ float         g_hcsq[NT];          // 0.5*||c||^2
__device__ __nv_bfloat16 g_Bh[NT * DIM];      // codebook bf16(hi), swizzled tiles
__device__ int           g_nrescue;
__device__ int           g_rescue[MAX_Q];

// ---------------- helpers ----------------
__device__ __forceinline__ uint32_t smem_u32(const void* p) {
    uint32_t a;
    asm("{ .reg .u64 t; cvta.to.shared.u64 t, %1; cvt.u32.u64 %0, t; }"
        : "=r"(a) : "l"(p));
    return a;
}
__device__ __forceinline__ void ldm_x4(uint32_t* r, uint32_t addr) {
    asm volatile("ldmatrix.sync.aligned.m8n8.x4.shared.b16 {%0,%1,%2,%3}, [%4];"
                 : "=r"(r[0]), "=r"(r[1]), "=r"(r[2]), "=r"(r[3]) : "r"(addr));
}
__device__ __forceinline__ void mma_bf16(float* c, const uint32_t* a,
                                         uint32_t b0, uint32_t b1) {
    asm volatile(
        "mma.sync.aligned.m16n8k16.row.col.f32.bf16.bf16.f32 "
        "{%0,%1,%2,%3}, {%4,%5,%6,%7}, {%8,%9}, {%0,%1,%2,%3};"
        : "+f"(c[0]), "+f"(c[1]), "+f"(c[2]), "+f"(c[3])
        : "r"(a[0]), "r"(a[1]), "r"(a[2]), "r"(a[3]), "r"(b0), "r"(b1));
}
__device__ __forceinline__ void cpa16(uint32_t dst, const void* src) {
    asm volatile("cp.async.cg.shared.global [%0], [%1], 16;" :: "r"(dst), "l"(src));
}
#define CPA_COMMIT() asm volatile("cp.async.commit_group;" ::: "memory")
#define CPA_WAIT0()  asm volatile("cp.async.wait_group 0;" ::: "memory")

// Tile geometry: rows x 128 bytes (64 bf16). 16B-chunk XOR swizzle (proven R4).
__device__ __forceinline__ uint32_t sw_off(int row, int chunk) {
    return (uint32_t)row * 128u + (uint32_t)((chunk ^ (row & 7)) << 4);
}
__device__ __forceinline__ void split2(float x, __nv_bfloat16& h, __nv_bfloat16& l) {
    h = __float2bfloat16_rn(x);
    l = __float2bfloat16_rn(x - __bfloat162float(h));
}

// ---------------- smem map (dynamic, 69632 B) ----------------
#define SM_AHI 0          // 16 KB
#define SM_ALO 16384      // 16 KB
#define SM_B   32768      // 2 stages x 16 KB = 32 KB (B hi only)
#define SM_HC  65536      // 4 KB
#define SMEM_TOTAL 69632

// ---------------------------------------------------------------------------
// prep: hcsq + codebook bf16(hi) swizzled chunk-major tiles; reset counter.
// ---------------------------------------------------------------------------
__global__ void prep_kernel(const float* __restrict__ cb) {
    int t = blockIdx.x * blockDim.x + threadIdx.x;
    if (t == 0) g_nrescue = 0;
    if (t >= NT * 16) return;
    int n = t >> 4, kq = t & 15;
    float4 v = *(const float4*)(cb + (size_t)n * DIM + kq * 4);
    __nv_bfloat16 h[4];
    h[0] = __float2bfloat16_rn(v.x); h[1] = __float2bfloat16_rn(v.y);
    h[2] = __float2bfloat16_rn(v.z); h[3] = __float2bfloat16_rn(v.w);
    int ch = n >> 7, ln = n & 127;
    uint32_t off = (uint32_t)ch * 16384u + sw_off(ln, kq >> 1) + (kq & 1) * 8;
    *(uint2*)((char*)g_Bh + off) = *(uint2*)h;
    if (kq == 0) {
        const float4* row = (const float4*)(cb + (size_t)n * DIM);
        float s = 0.f;
#pragma unroll
        for (int i = 0; i < 16; i++) {
            float4 w = row[i];
            s += w.x * w.x + w.y * w.y + w.z * w.z + w.w * w.w;
        }
        g_hcsq[n] = 0.5f * s;
    }
}

// ---------------------------------------------------------------------------
// main: 2-pass bf16 mma.sync GEMM (Ah*Bh + Al*Bh) + running top-2 argmax.
// 8 warps = 2(m) x 4(n); warp tile 64 x 32; full K=64 per chunk.
// ---------------------------------------------------------------------------
__global__ void __launch_bounds__(256, 1)
vq_mma_kernel(const float* __restrict__ codes) {
    extern __shared__ char smem[];
    const uint32_t sb = smem_u32(smem);
    const int tid  = threadIdx.x;
    const int wid  = tid >> 5, lane = tid & 31;
    const int wm   = wid >> 2;
    const int wn   = wid & 3;
    const int qbase = blockIdx.x * MQ;

    // prefetch B chunk 0 -> stage 0
    for (int i = tid; i < 1024; i += 256)
        cpa16(sb + SM_B + i * 16, (const char*)g_Bh + i * 16);
    CPA_COMMIT();

    // hcsq -> smem
    for (int i = tid; i < NT / 4; i += 256)
        ((float4*)(smem + SM_HC))[i] = ((const float4*)g_hcsq)[i];

    // A tile: load fp32, split hi/lo bf16, store swizzled
    for (int i = tid; i < MQ * 16; i += 256) {
        int m = i >> 4, kq = i & 15;
        float4 v = *(const float4*)(codes + (size_t)(qbase + m) * DIM + kq * 4);
        __nv_bfloat16 h[4], l[4];
        split2(v.x, h[0], l[0]); split2(v.y, h[1], l[1]);
        split2(v.z, h[2], l[2]); split2(v.w, h[3], l[3]);
        uint32_t off = sw_off(m, kq >> 1) + (kq & 1) * 8;
        *(uint2*)(smem + SM_AHI + off) = *(uint2*)h;
        *(uint2*)(smem + SM_ALO + off) = *(uint2*)l;
    }

    float b1[8], b2[8];
    int   i1[8];
#pragma unroll
    for (int r = 0; r < 8; r++) { b1[r] = -1e30f; b2[r] = -1e30f; i1[r] = 0; }

    const float* hc = (const float*)(smem + SM_HC);

    for (int c = 0; c < NCHUNKS; c++) {
        const int st = c & 1;
        CPA_WAIT0();
        __syncthreads();

        if (c + 1 < NCHUNKS) {
            const char* bh = (const char*)g_Bh + (size_t)(c + 1) * 16384;
            uint32_t dst = sb + SM_B + (st ^ 1) * 16384;
            for (int i = tid; i < 1024; i += 256)
                cpa16(dst + i * 16, bh + i * 16);
            CPA_COMMIT();
        }

        float acc[4][4][4];
#pragma unroll
        for (int mi = 0; mi < 4; mi++)
#pragma unroll
            for (int nj = 0; nj < 4; nj++)
#pragma unroll
                for (int e = 0; e < 4; e++) acc[mi][nj][e] = 0.f;

        const uint32_t aHi = sb + SM_AHI, aLo = sb + SM_ALO;
        const uint32_t bBase = sb + SM_B + st * 16384;

#pragma unroll
        for (int ks = 0; ks < 4; ks++) {
            uint32_t ah[4][4], al[4][4];
#pragma unroll
            for (int mi = 0; mi < 4; mi++) {
                int ra = wm * 64 + mi * 16 + (lane & 15);
                uint32_t off = sw_off(ra, ks * 2 + (lane >> 4));
                ldm_x4(ah[mi], aHi + off);
                ldm_x4(al[mi], aLo + off);
            }
            uint32_t bf[2][4];
#pragma unroll
            for (int ni2 = 0; ni2 < 2; ni2++) {
                int rb = wn * 32 + ni2 * 16 + (lane & 7) + ((lane & 16) ? 8 : 0);
                ldm_x4(bf[ni2], bBase + sw_off(rb, ks * 2 + ((lane >> 3) & 1)));
            }
#pragma unroll
            for (int mi = 0; mi < 4; mi++)
#pragma unroll
                for (int nj = 0; nj < 4; nj++) {
                    uint32_t h0 = bf[nj >> 1][(nj & 1) * 2];
                    uint32_t h1 = bf[nj >> 1][(nj & 1) * 2 + 1];
                    mma_bf16(acc[mi][nj], ah[mi], h0, h1);
                    mma_bf16(acc[mi][nj], al[mi], h0, h1);
                }
        }

        // epilogue: top-2 update (proven R4 indexing)
#pragma unroll
        for (int mi = 0; mi < 4; mi++)
#pragma unroll
            for (int h = 0; h < 2; h++) {
                int ri = mi * 2 + h;
                float v1 = b1[ri], v2 = b2[ri];
                int   ii = i1[ri];
#pragma unroll
                for (int nj = 0; nj < 4; nj++)
#pragma unroll
                    for (int p = 0; p < 2; p++) {
                        int n = c * NCH + wn * 32 + nj * 8 + (lane & 3) * 2 + p;
                        float v = acc[mi][nj][h * 2 + p] - hc[n];
                        bool gt = v > v1;
                        v2 = gt ? v1 : fmaxf(v2, v);
                        ii = gt ? n : ii;
                        v1 = gt ? v : v1;
                    }
                b1[ri] = v1; b2[ri] = v2; i1[ri] = ii;
            }
    }

    // intra-warp merge over the 4 lanes sharing each row
#pragma unroll
    for (int r = 0; r < 8; r++) {
#pragma unroll
        for (int d = 1; d <= 2; d <<= 1) {
            float ov  = __shfl_xor_sync(0xffffffffu, b1[r], d);
            int   oi  = __shfl_xor_sync(0xffffffffu, i1[r], d);
            float ov2 = __shfl_xor_sync(0xffffffffu, b2[r], d);
            bool take = (ov > b1[r]) || (ov == b1[r] && oi < i1[r]);
            float lose = take ? b1[r] : ov;
            b2[r] = fmaxf(fmaxf(b2[r], ov2), lose);
            if (take) { b1[r] = ov; i1[r] = oi; }
        }
    }

    // cross-warp (wn) merge via smem
    __syncthreads();
    float* rv  = (float*)(smem + SM_AHI);          // [128][4]
    int*   rix = (int*)(smem + SM_AHI + 2048);     // [128][4]
    float* r2  = (float*)(smem + SM_AHI + 4096);   // [128][4]
    if ((lane & 3) == 0) {
#pragma unroll
        for (int mi = 0; mi < 4; mi++)
#pragma unroll
            for (int h = 0; h < 2; h++) {
                int r = mi * 2 + h;
                int row = wm * 64 + mi * 16 + h * 8 + (lane >> 2);
                rv[row * 4 + wn] = b1[r];
                rix[row * 4 + wn] = i1[r];
                r2[row * 4 + wn] = b2[r];
            }
    }
    __syncthreads();

    // per-query final merge + block-aggregated rescue enqueue (1 global atomic/CTA)
    __shared__ int s_cnt, s_base;
    if (tid == 0) s_cnt = 0;
    __syncthreads();
    int slot = -1;
    if (tid < MQ) {
        float bv = rv[tid * 4], bb2 = r2[tid * 4];
        int   bi = rix[tid * 4];
#pragma unroll
        for (int w = 1; w < 4; w++) {
            float ov = rv[tid * 4 + w], ov2 = r2[tid * 4 + w];
            int   oi = rix[tid * 4 + w];
            bool take = (ov > bv) || (ov == bv && oi < bi);
            float lose = take ? bv : ov;
            bb2 = fmaxf(fmaxf(bb2, ov2), lose);
            if (take) { bv = ov; bi = oi; }
        }
        g_ids[qbase + tid] = bi;
        if (bv - bb2 < DELTA) slot = atomicAdd(&s_cnt, 1);
    }
    __syncthreads();
    if (tid == 0 && s_cnt > 0) s_base = atomicAdd(&g_nrescue, s_cnt);
    __syncthreads();
    if (slot >= 0) g_rescue[s_base + slot] = qbase + tid;
}

// ---------------------------------------------------------------------------
// rescue: exact fp32 rescan; 8 queries share one codebook sweep per block.
// ---------------------------------------------------------------------------
#define QB 8
__global__ void rescue_kernel(const float* __restrict__ codes,
                              const float* __restrict__ cb) {
    __shared__ float sx[QB][DIM];
    __shared__ float sv[QB][256];
    __shared__ int   si[QB][256];
    int nres = g_nrescue;
    for (int base = blockIdx.x * QB; base < nres; base += gridDim.x * QB) {
        int cnt = min(QB, nres - base);
        __syncthreads();
        for (int i = threadIdx.x; i < cnt * 16; i += 256) {
            int q = i >> 4, kq = i & 15;
            ((float4*)sx[q])[kq] =
                ((const float4*)(codes + (size_t)g_rescue[base + q] * DIM))[kq];
        }
        __syncthreads();
        float bv[QB]; int bi[QB];
#pragma unroll
        for (int q = 0; q < QB; q++) { bv[q] = -1e30f; bi[q] = 0; }
        for (int j = 0; j < 4; j++) {
            int n = threadIdx.x + j * 256;
            const float* cr = cb + (size_t)n * DIM;
            float dot[QB];
#pragma unroll
            for (int q = 0; q < QB; q++) dot[q] = 0.f;
#pragma unroll
            for (int k = 0; k < DIM; k++) {
                float ck = __ldg(&cr[k]);
#pragma unroll
                for (int q = 0; q < QB; q++) dot[q] += sx[q][k] * ck;
            }
            float hcv = g_hcsq[n];
#pragma unroll
            for (int q = 0; q < QB; q++) {
                float s = dot[q] - hcv;
                if (s > bv[q]) { bv[q] = s; bi[q] = n; }
            }
        }
#pragma unroll
        for (int q = 0; q < QB; q++) { sv[q][threadIdx.x] = bv[q]; si[q][threadIdx.x] = bi[q]; }
        __syncthreads();
        int w = threadIdx.x >> 5, lane = threadIdx.x & 31;
        if (w < QB && w < cnt) {
            float v = sv[w][lane]; int ix = si[w][lane];
            for (int t = lane + 32; t < 256; t += 32) {
                float ov = sv[w][t]; int oi = si[w][t];
                if (ov > v || (ov == v && oi < ix)) { v = ov; ix = oi; }
            }
#pragma unroll
            for (int d = 16; d > 0; d >>= 1) {
                float ov = __shfl_down_sync(0xffffffffu, v, d);
                int   oi = __shfl_down_sync(0xffffffffu, ix, d);
                if (ov > v || (ov == v && oi < ix)) { v = ov; ix = oi; }
            }
            if (lane == 0) g_ids[g_rescue[base + w]] = ix;
        }
        __syncthreads();
    }
}

// ---------------------------------------------------------------------------
// gather: codebook[best] -> out_codes; ids as float.
// ---------------------------------------------------------------------------
__global__ void gather_kernel(const float* __restrict__ cb,
                              float* __restrict__ out_codes,
                              float* __restrict__ out_ids,
                              int nq, int write_ids) {
    int t = blockIdx.x * blockDim.x + threadIdx.x;
    if (t < nq * (DIM / 4)) {
        int q = t >> 4, part = t & 15;
        int id = g_ids[q];
        float4 v = *(const float4*)(cb + (size_t)id * DIM + part * 4);
        *(float4*)(out_codes + (size_t)q * DIM + part * 4) = v;
    }
    if (write_ids && t < nq) out_ids[t] = (float)g_ids[t];
}

// ---------------------------------------------------------------------------
extern "C" void kernel_launch(void* const* d_in, const int* in_sizes, int n_in,
                              void* d_out, int out_size) {
    const float* codes = (const float*)d_in[0];
    const float* cb    = (const float*)d_in[1];
    float* out = (float*)d_out;

    int nq = in_sizes[0] / DIM;
    if (nq > MAX_Q) nq = MAX_Q;

    static int attr_done = 0;
    if (!attr_done) {
        cudaFuncSetAttribute(vq_mma_kernel,
                             cudaFuncAttributeMaxDynamicSharedMemorySize, SMEM_TOTAL);
        attr_done = 1;
    }

    prep_kernel<<<(NT * 16 + 255) / 256, 256>>>(cb);
    vq_mma_kernel<<<nq / MQ, 256, SMEM_TOTAL>>>(codes);
    rescue_kernel<<<2048, 256>>>(codes, cb);

    int write_ids = (out_size >= nq * DIM + nq) ? 1 : 0;
    float* out_ids = out + (size_t)nq * DIM;
    int total = nq * (DIM / 4);
    gather_kernel<<<(total + 255) / 256, 256>>>(cb, out, out_ids, nq, write_ids);
}

// round 9
// speedup vs baseline: 2.0854x; 1.4660x over previous
#include <cuda_runtime.h>
#include <cuda_bf16.h>
#include <stdint.h>

#define DIM 64
#define NT 1024
#define MQ 128
#define NCH 128
#define NCHUNKS (NT / NCH)
#define MAX_Q (64 * 4096)
// 2-pass bf16 score-err std ~1.3e-3; DELTA = certified decision window.
#define DELTA 0.015f

__device__ int           g_ids[MAX_Q];
__device__ float         g_hcsq[NT];
__device__ __nv_bfloat16 g_Bh[NT * DIM];
__device__ int           g_nrescue;
__device__ int           g_rescue[MAX_Q];

// ---------------- helpers ----------------
__device__ __forceinline__ uint32_t smem_u32(const void* p) {
    uint32_t a;
    asm("{ .reg .u64 t; cvta.to.shared.u64 t, %1; cvt.u32.u64 %0, t; }"
        : "=r"(a) : "l"(p));
    return a;
}
__device__ __forceinline__ void ldm_x4(uint32_t* r, uint32_t addr) {
    asm volatile("ldmatrix.sync.aligned.m8n8.x4.shared.b16 {%0,%1,%2,%3}, [%4];"
                 : "=r"(r[0]), "=r"(r[1]), "=r"(r[2]), "=r"(r[3]) : "r"(addr));
}
__device__ __forceinline__ void mma_bf16(float* c, const uint32_t* a,
                                         uint32_t b0, uint32_t b1) {
    asm volatile(
        "mma.sync.aligned.m16n8k16.row.col.f32.bf16.bf16.f32 "
        "{%0,%1,%2,%3}, {%4,%5,%6,%7}, {%8,%9}, {%0,%1,%2,%3};"
        : "+f"(c[0]), "+f"(c[1]), "+f"(c[2]), "+f"(c[3])
        : "r"(a[0]), "r"(a[1]), "r"(a[2]), "r"(a[3]), "r"(b0), "r"(b1));
}
__device__ __forceinline__ void cpa16(uint32_t dst, const void* src) {
    asm volatile("cp.async.cg.shared.global [%0], [%1], 16;" :: "r"(dst), "l"(src));
}
#define CPA_COMMIT() asm volatile("cp.async.commit_group;" ::: "memory")
#define CPA_WAIT0()  asm volatile("cp.async.wait_group 0;" ::: "memory")

__device__ __forceinline__ uint32_t sw_off(int row, int chunk) {
    return (uint32_t)row * 128u + (uint32_t)((chunk ^ (row & 7)) << 4);
}
__device__ __forceinline__ void split2(float x, __nv_bfloat16& h, __nv_bfloat16& l) {
    h = __float2bfloat16_rn(x);
    l = __float2bfloat16_rn(x - __bfloat162float(h));
}

// top-3 insertion with index tracking for ranks 1-2 (lex tie-break at rank 1)
struct Top3 { float v1, v2, v3; int i1, i2; };
__device__ __forceinline__ void t3_ins(Top3& t, float v, int i) {
    bool g1 = (v > t.v1) || (v == t.v1 && i >= 0 && i < t.i1);
    bool g2 = v > t.v2;
    bool g3 = v > t.v3;
    t.v3 = g2 ? t.v2 : (g3 ? v : t.v3);
    t.v2 = g1 ? t.v1 : (g2 ? v : t.v2);
    t.i2 = g1 ? t.i1 : (g2 ? i : t.i2);
    t.v1 = g1 ? v : t.v1;
    t.i1 = g1 ? i : t.i1;
}

// ---------------- smem map (dynamic, 69632 B) ----------------
#define SM_AHI 0
#define SM_ALO 16384
#define SM_B   32768
#define SM_HC  65536
#define SMEM_TOTAL 69632

// ---------------------------------------------------------------------------
__global__ void prep_kernel(const float* __restrict__ cb) {
    int t = blockIdx.x * blockDim.x + threadIdx.x;
    if (t == 0) g_nrescue = 0;
    if (t >= NT * 16) return;
    int n = t >> 4, kq = t & 15;
    float4 v = *(const float4*)(cb + (size_t)n * DIM + kq * 4);
    __nv_bfloat16 h[4];
    h[0] = __float2bfloat16_rn(v.x); h[1] = __float2bfloat16_rn(v.y);
    h[2] = __float2bfloat16_rn(v.z); h[3] = __float2bfloat16_rn(v.w);
    int ch = n >> 7, ln = n & 127;
    uint32_t off = (uint32_t)ch * 16384u + sw_off(ln, kq >> 1) + (kq & 1) * 8;
    *(uint2*)((char*)g_Bh + off) = *(uint2*)h;
    if (kq == 0) {
        const float4* row = (const float4*)(cb + (size_t)n * DIM);
        float s = 0.f;
#pragma unroll
        for (int i = 0; i < 16; i++) {
            float4 w = row[i];
            s += w.x * w.x + w.y * w.y + w.z * w.z + w.w * w.w;
        }
        g_hcsq[n] = 0.5f * s;
    }
}

// ---------------------------------------------------------------------------
// main: 2-pass bf16 mma.sync GEMM + top-3 argmax + inline top-2 exact rescore.
// ---------------------------------------------------------------------------
__global__ void __launch_bounds__(256, 1)
vq_mma_kernel(const float* __restrict__ codes, const float* __restrict__ cb) {
    extern __shared__ char smem[];
    const uint32_t sb = smem_u32(smem);
    const int tid  = threadIdx.x;
    const int wid  = tid >> 5, lane = tid & 31;
    const int wm   = wid >> 2;
    const int wn   = wid & 3;
    const int qbase = blockIdx.x * MQ;

    for (int i = tid; i < 1024; i += 256)
        cpa16(sb + SM_B + i * 16, (const char*)g_Bh + i * 16);
    CPA_COMMIT();

    for (int i = tid; i < NT / 4; i += 256)
        ((float4*)(smem + SM_HC))[i] = ((const float4*)g_hcsq)[i];

    for (int i = tid; i < MQ * 16; i += 256) {
        int m = i >> 4, kq = i & 15;
        float4 v = *(const float4*)(codes + (size_t)(qbase + m) * DIM + kq * 4);
        __nv_bfloat16 h[4], l[4];
        split2(v.x, h[0], l[0]); split2(v.y, h[1], l[1]);
        split2(v.z, h[2], l[2]); split2(v.w, h[3], l[3]);
        uint32_t off = sw_off(m, kq >> 1) + (kq & 1) * 8;
        *(uint2*)(smem + SM_AHI + off) = *(uint2*)h;
        *(uint2*)(smem + SM_ALO + off) = *(uint2*)l;
    }

    Top3 tp[8];
#pragma unroll
    for (int r = 0; r < 8; r++) {
        tp[r].v1 = -1e30f; tp[r].v2 = -1.1e30f; tp[r].v3 = -1.2e30f;
        tp[r].i1 = 0; tp[r].i2 = 0;
    }

    const float* hc = (const float*)(smem + SM_HC);

    for (int c = 0; c < NCHUNKS; c++) {
        const int st = c & 1;
        CPA_WAIT0();
        __syncthreads();

        if (c + 1 < NCHUNKS) {
            const char* bh = (const char*)g_Bh + (size_t)(c + 1) * 16384;
            uint32_t dst = sb + SM_B + (st ^ 1) * 16384;
            for (int i = tid; i < 1024; i += 256)
                cpa16(dst + i * 16, bh + i * 16);
            CPA_COMMIT();
        }

        float acc[4][4][4];
#pragma unroll
        for (int mi = 0; mi < 4; mi++)
#pragma unroll
            for (int nj = 0; nj < 4; nj++)
#pragma unroll
                for (int e = 0; e < 4; e++) acc[mi][nj][e] = 0.f;

        const uint32_t aHi = sb + SM_AHI, aLo = sb + SM_ALO;
        const uint32_t bBase = sb + SM_B + st * 16384;

#pragma unroll
        for (int ks = 0; ks < 4; ks++) {
            uint32_t ah[4][4], al[4][4];
#pragma unroll
            for (int mi = 0; mi < 4; mi++) {
                int ra = wm * 64 + mi * 16 + (lane & 15);
                uint32_t off = sw_off(ra, ks * 2 + (lane >> 4));
                ldm_x4(ah[mi], aHi + off);
                ldm_x4(al[mi], aLo + off);
            }
            uint32_t bfr[2][4];
#pragma unroll
            for (int ni2 = 0; ni2 < 2; ni2++) {
                int rb = wn * 32 + ni2 * 16 + (lane & 7) + ((lane & 16) ? 8 : 0);
                ldm_x4(bfr[ni2], bBase + sw_off(rb, ks * 2 + ((lane >> 3) & 1)));
            }
#pragma unroll
            for (int mi = 0; mi < 4; mi++)
#pragma unroll
                for (int nj = 0; nj < 4; nj++) {
                    uint32_t h0 = bfr[nj >> 1][(nj & 1) * 2];
                    uint32_t h1 = bfr[nj >> 1][(nj & 1) * 2 + 1];
                    mma_bf16(acc[mi][nj], ah[mi], h0, h1);
                    mma_bf16(acc[mi][nj], al[mi], h0, h1);
                }
        }

        // epilogue: top-3 update (n strictly ascending per thread-row scan)
#pragma unroll
        for (int mi = 0; mi < 4; mi++)
#pragma unroll
            for (int h = 0; h < 2; h++) {
                int ri = mi * 2 + h;
                Top3 t = tp[ri];
#pragma unroll
                for (int nj = 0; nj < 4; nj++)
#pragma unroll
                    for (int p = 0; p < 2; p++) {
                        int n = c * NCH + wn * 32 + nj * 8 + (lane & 3) * 2 + p;
                        float v = acc[mi][nj][h * 2 + p] - hc[n];
                        // strict-> keeps first index within a thread's ascending scan
                        bool g1 = v > t.v1;
                        bool g2 = v > t.v2;
                        bool g3 = v > t.v3;
                        t.v3 = g2 ? t.v2 : (g3 ? v : t.v3);
                        t.v2 = g1 ? t.v1 : (g2 ? v : t.v2);
                        t.i2 = g1 ? t.i1 : (g2 ? n : t.i2);
                        t.v1 = g1 ? v : t.v1;
                        t.i1 = g1 ? n : t.i1;
                    }
                tp[ri] = t;
            }
    }

    // intra-warp merge over the 4 lanes sharing each row
#pragma unroll
    for (int r = 0; r < 8; r++) {
#pragma unroll
        for (int d = 1; d <= 2; d <<= 1) {
            float ov1 = __shfl_xor_sync(0xffffffffu, tp[r].v1, d);
            int   oi1 = __shfl_xor_sync(0xffffffffu, tp[r].i1, d);
            float ov2 = __shfl_xor_sync(0xffffffffu, tp[r].v2, d);
            int   oi2 = __shfl_xor_sync(0xffffffffu, tp[r].i2, d);
            float ov3 = __shfl_xor_sync(0xffffffffu, tp[r].v3, d);
            t3_ins(tp[r], ov1, oi1);
            t3_ins(tp[r], ov2, oi2);
            t3_ins(tp[r], ov3, -1);
        }
    }

    // cross-warp (wn) merge via smem
    __syncthreads();
    float* rv1 = (float*)(smem + SM_AHI);           // [128][4]
    int*   ri1 = (int*)(smem + SM_AHI + 2048);
    float* rv2 = (float*)(smem + SM_AHI + 4096);
    int*   ri2 = (int*)(smem + SM_AHI + 6144);
    float* rv3 = (float*)(smem + SM_AHI + 8192);
    if ((lane & 3) == 0) {
#pragma unroll
        for (int mi = 0; mi < 4; mi++)
#pragma unroll
            for (int h = 0; h < 2; h++) {
                int r = mi * 2 + h;
                int row = wm * 64 + mi * 16 + h * 8 + (lane >> 2);
                rv1[row * 4 + wn] = tp[r].v1;
                ri1[row * 4 + wn] = tp[r].i1;
                rv2[row * 4 + wn] = tp[r].v2;
                ri2[row * 4 + wn] = tp[r].i2;
                rv3[row * 4 + wn] = tp[r].v3;
            }
    }
    __syncthreads();

    __shared__ int s_cnt, s_base;
    if (tid == 0) s_cnt = 0;
    __syncthreads();
    int slot = -1;
    if (tid < MQ) {
        Top3 t;
        t.v1 = rv1[tid * 4]; t.i1 = ri1[tid * 4];
        t.v2 = rv2[tid * 4]; t.i2 = ri2[tid * 4];
        t.v3 = rv3[tid * 4];
#pragma unroll
        for (int w = 1; w < 4; w++) {
            t3_ins(t, rv1[tid * 4 + w], ri1[tid * 4 + w]);
            t3_ins(t, rv2[tid * 4 + w], ri2[tid * 4 + w]);
            t3_ins(t, rv3[tid * 4 + w], -1);
        }
        int q = qbase + tid;
        int best = t.i1;
        if (t.v1 - t.v3 < DELTA) {
            slot = atomicAdd(&s_cnt, 1);       // ambiguous beyond top-2: full rescan
        } else if (t.v1 - t.v2 < DELTA) {
            // certified: true argmax in {i1, i2}; exact fp32 rescore (R2 arithmetic)
            const float4* xr = (const float4*)(codes + (size_t)q * DIM);
            const float4* c1 = (const float4*)(cb + (size_t)t.i1 * DIM);
            const float4* c2 = (const float4*)(cb + (size_t)t.i2 * DIM);
            float s1 = 0.f, s2 = 0.f;
#pragma unroll
            for (int kq = 0; kq < 16; kq++) {
                float4 x = xr[kq], a = c1[kq], b = c2[kq];
                s1 = fmaf(x.x, a.x, s1); s1 = fmaf(x.y, a.y, s1);
                s1 = fmaf(x.z, a.z, s1); s1 = fmaf(x.w, a.w, s1);
                s2 = fmaf(x.x, b.x, s2); s2 = fmaf(x.y, b.y, s2);
                s2 = fmaf(x.z, b.z, s2); s2 = fmaf(x.w, b.w, s2);
            }
            s1 -= hc[t.i1]; s2 -= hc[t.i2];
            if ((s2 > s1) || (s2 == s1 && t.i2 < t.i1)) best = t.i2;
        }
        g_ids[q] = best;
    }
    __syncthreads();
    if (tid == 0 && s_cnt > 0) s_base = atomicAdd(&g_nrescue, s_cnt);
    __syncthreads();
    if (slot >= 0) g_rescue[s_base + slot] = qbase + tid;
}

// ---------------------------------------------------------------------------
// rescue: exact fp32 full rescan (only gap13<DELTA queries; ~hundreds).
// ---------------------------------------------------------------------------
#define QB 8
__global__ void rescue_kernel(const float* __restrict__ codes,
                              const float* __restrict__ cb) {
    __shared__ float sx[QB][DIM];
    __shared__ float sv[QB][256];
    __shared__ int   si[QB][256];
    int nres = g_nrescue;
    for (int base = blockIdx.x * QB; base < nres; base += gridDim.x * QB) {
        int cnt = min(QB, nres - base);
        __syncthreads();
        for (int i = threadIdx.x; i < cnt * 16; i += 256) {
            int q = i >> 4, kq = i & 15;
            ((float4*)sx[q])[kq] =
                ((const float4*)(codes + (size_t)g_rescue[base + q] * DIM))[kq];
        }
        __syncthreads();
        float bv[QB]; int bi[QB];
#pragma unroll
        for (int q = 0; q < QB; q++) { bv[q] = -1e30f; bi[q] = 0; }
        for (int j = 0; j < 4; j++) {
            int n = threadIdx.x + j * 256;
            const float4* cr = (const float4*)(cb + (size_t)n * DIM);
            float dot[QB];
#pragma unroll
            for (int q = 0; q < QB; q++) dot[q] = 0.f;
#pragma unroll
            for (int kq = 0; kq < 16; kq++) {
                float4 c4 = __ldg(&cr[kq]);
#pragma unroll
                for (int q = 0; q < QB; q++) {
                    dot[q] = fmaf(sx[q][kq * 4 + 0], c4.x, dot[q]);
                    dot[q] = fmaf(sx[q][kq * 4 + 1], c4.y, dot[q]);
                    dot[q] = fmaf(sx[q][kq * 4 + 2], c4.z, dot[q]);
                    dot[q] = fmaf(sx[q][kq * 4 + 3], c4.w, dot[q]);
                }
            }
            float hcv = g_hcsq[n];
#pragma unroll
            for (int q = 0; q < QB; q++) {
                float s = dot[q] - hcv;
                if (s > bv[q]) { bv[q] = s; bi[q] = n; }
            }
        }
#pragma unroll
        for (int q = 0; q < QB; q++) { sv[q][threadIdx.x] = bv[q]; si[q][threadIdx.x] = bi[q]; }
        __syncthreads();
        int w = threadIdx.x >> 5, lane = threadIdx.x & 31;
        if (w < QB && w < cnt) {
            float v = sv[w][lane]; int ix = si[w][lane];
            for (int t = lane + 32; t < 256; t += 32) {
                float ov = sv[w][t]; int oi = si[w][t];
                if (ov > v || (ov == v && oi < ix)) { v = ov; ix = oi; }
            }
#pragma unroll
            for (int d = 16; d > 0; d >>= 1) {
                float ov = __shfl_down_sync(0xffffffffu, v, d);
                int   oi = __shfl_down_sync(0xffffffffu, ix, d);
                if (ov > v || (ov == v && oi < ix)) { v = ov; ix = oi; }
            }
            if (lane == 0) g_ids[g_rescue[base + w]] = ix;
        }
        __syncthreads();
    }
}

// ---------------------------------------------------------------------------
__global__ void gather_kernel(const float* __restrict__ cb,
                              float* __restrict__ out_codes,
                              float* __restrict__ out_ids,
                              int nq, int write_ids) {
    int t = blockIdx.x * blockDim.x + threadIdx.x;
    if (t < nq * (DIM / 4)) {
        int q = t >> 4, part = t & 15;
        int id = g_ids[q];
        float4 v = *(const float4*)(cb + (size_t)id * DIM + part * 4);
        *(float4*)(out_codes + (size_t)q * DIM + part * 4) = v;
    }
    if (write_ids && t < nq) out_ids[t] = (float)g_ids[t];
}

// ---------------------------------------------------------------------------
extern "C" void kernel_launch(void* const* d_in, const int* in_sizes, int n_in,
                              void* d_out, int out_size) {
    const float* codes = (const float*)d_in[0];
    const float* cb    = (const float*)d_in[1];
    float* out = (float*)d_out;

    int nq = in_sizes[0] / DIM;
    if (nq > MAX_Q) nq = MAX_Q;

    static int attr_done = 0;
    if (!attr_done) {
        cudaFuncSetAttribute(vq_mma_kernel,
                             cudaFuncAttributeMaxDynamicSharedMemorySize, SMEM_TOTAL);
        attr_done = 1;
    }

    prep_kernel<<<(NT * 16 + 255) / 256, 256>>>(cb);
    vq_mma_kernel<<<nq / MQ, 256, SMEM_TOTAL>>>(codes, cb);
    rescue_kernel<<<512, 256>>>(codes, cb);

    int write_ids = (out_size >= nq * DIM + nq) ? 1 : 0;
    float* out_ids = out + (size_t)nq * DIM;
    int total = nq * (DIM / 4);
    gather_kernel<<<(total + 255) / 256, 256>>>(cb, out, out_ids, nq, write_ids);
}

// round 10
// speedup vs baseline: 2.3989x; 1.1503x over previous
#include <cuda_runtime.h>
#include <cuda_bf16.h>
#include <stdint.h>

#define DIM 64
#define NT 1024
#define MQ 128
#define NCH 128
#define NCHUNKS (NT / NCH)
#define MAX_Q (64 * 4096)
// 1-pass bf16 score-err std ~1.6e-3; pairwise 2.3e-3; DELTA = 8.7 sigma.
#define DELTA 0.02f

__device__ int           g_ids[MAX_Q];
__device__ float         g_hcsq[NT];
__device__ __nv_bfloat16 g_Bh[NT * DIM];
__device__ int           g_nrescue;
__device__ int           g_rescue[MAX_Q];
__device__ int           g_npair;
__device__ int2          g_pair[MAX_Q];

// ---------------- helpers ----------------
__device__ __forceinline__ uint32_t smem_u32(const void* p) {
    uint32_t a;
    asm("{ .reg .u64 t; cvta.to.shared.u64 t, %1; cvt.u32.u64 %0, t; }"
        : "=r"(a) : "l"(p));
    return a;
}
__device__ __forceinline__ void ldm_x4(uint32_t* r, uint32_t addr) {
    asm volatile("ldmatrix.sync.aligned.m8n8.x4.shared.b16 {%0,%1,%2,%3}, [%4];"
                 : "=r"(r[0]), "=r"(r[1]), "=r"(r[2]), "=r"(r[3]) : "r"(addr));
}
__device__ __forceinline__ void mma_bf16(float* c, const uint32_t* a,
                                         uint32_t b0, uint32_t b1) {
    asm volatile(
        "mma.sync.aligned.m16n8k16.row.col.f32.bf16.bf16.f32 "
        "{%0,%1,%2,%3}, {%4,%5,%6,%7}, {%8,%9}, {%0,%1,%2,%3};"
        : "+f"(c[0]), "+f"(c[1]), "+f"(c[2]), "+f"(c[3])
        : "r"(a[0]), "r"(a[1]), "r"(a[2]), "r"(a[3]), "r"(b0), "r"(b1));
}
__device__ __forceinline__ void cpa16(uint32_t dst, const void* src) {
    asm volatile("cp.async.cg.shared.global [%0], [%1], 16;" :: "r"(dst), "l"(src));
}
#define CPA_COMMIT() asm volatile("cp.async.commit_group;" ::: "memory")
#define CPA_WAIT0()  asm volatile("cp.async.wait_group 0;" ::: "memory")

__device__ __forceinline__ uint32_t sw_off(int row, int chunk) {
    return (uint32_t)row * 128u + (uint32_t)((chunk ^ (row & 7)) << 4);
}

struct Top3 { float v1, v2, v3; int i1, i2; };

// branchless-ish top-3 insert (hot path; strict > keeps first index per
// thread's ascending scan). ~10 instr.
__device__ __forceinline__ void t3_hot(Top3& t, float v, int n) {
    float vp = fminf(v, t.v1);
    t.v3 = fmaxf(t.v3, fminf(t.v2, vp));
    bool g2 = v > t.v2;
    bool g1 = v > t.v1;
    t.v2 = fmaxf(t.v2, vp);
    t.i2 = g1 ? t.i1 : (g2 ? n : t.i2);
    t.v1 = fmaxf(t.v1, v);
    t.i1 = g1 ? n : t.i1;
}
// merge-path insert with lex tie-break at rank 1 (cold path)
__device__ __forceinline__ void t3_ins(Top3& t, float v, int i) {
    bool g1 = (v > t.v1) || (v == t.v1 && i >= 0 && i < t.i1);
    bool g2 = v > t.v2;
    bool g3 = v > t.v3;
    t.v3 = g2 ? t.v2 : (g3 ? v : t.v3);
    t.v2 = g1 ? t.v1 : (g2 ? v : t.v2);
    t.i2 = g1 ? t.i1 : (g2 ? i : t.i2);
    t.v1 = g1 ? v : t.v1;
    t.i1 = g1 ? i : t.i1;
}

// ---------------- smem map (dynamic, 49152 B) ----------------
#define SM_A 0            // 16 KB query tile (bf16, swizzled)
#define SM_B 16384        // 2 stages x 16 KB
#define SMEM_TOTAL 49152

// ---------------------------------------------------------------------------
__global__ void prep_kernel(const float* __restrict__ cb) {
    int t = blockIdx.x * blockDim.x + threadIdx.x;
    if (t == 0) { g_nrescue = 0; g_npair = 0; }
    if (t >= NT * 16) return;
    int n = t >> 4, kq = t & 15;
    float4 v = *(const float4*)(cb + (size_t)n * DIM + kq * 4);
    __nv_bfloat16 h[4];
    h[0] = __float2bfloat16_rn(v.x); h[1] = __float2bfloat16_rn(v.y);
    h[2] = __float2bfloat16_rn(v.z); h[3] = __float2bfloat16_rn(v.w);
    int ch = n >> 7, ln = n & 127;
    uint32_t off = (uint32_t)ch * 16384u + sw_off(ln, kq >> 1) + (kq & 1) * 8;
    *(uint2*)((char*)g_Bh + off) = *(uint2*)h;
    if (kq == 0) {
        const float4* row = (const float4*)(cb + (size_t)n * DIM);
        float s = 0.f;
#pragma unroll
        for (int i = 0; i < 16; i++) {
            float4 w = row[i];
            s += w.x * w.x + w.y * w.y + w.z * w.z + w.w * w.w;
        }
        g_hcsq[n] = 0.5f * s;
    }
}

// ---------------------------------------------------------------------------
// main: 1-pass bf16 mma.sync + top-3 of raw dot; epilogue overlapped with MMA
// via mi-split groups (G1 = mi 0-1, G2 = mi 2-3).
// ---------------------------------------------------------------------------
__global__ void __launch_bounds__(256, 1)
vq_mma_kernel(const float* __restrict__ codes) {
    extern __shared__ char smem[];
    const uint32_t sb = smem_u32(smem);
    const int tid  = threadIdx.x;
    const int wid  = tid >> 5, lane = tid & 31;
    const int wm   = wid >> 2;
    const int wn   = wid & 3;
    const int qbase = blockIdx.x * MQ;

    for (int i = tid; i < 1024; i += 256)
        cpa16(sb + SM_B + i * 16, (const char*)g_Bh + i * 16);
    CPA_COMMIT();

    // A tile: fp32 -> bf16, swizzled
    for (int i = tid; i < MQ * 16; i += 256) {
        int m = i >> 4, kq = i & 15;
        float4 v = *(const float4*)(codes + (size_t)(qbase + m) * DIM + kq * 4);
        __nv_bfloat16 h[4];
        h[0] = __float2bfloat16_rn(v.x); h[1] = __float2bfloat16_rn(v.y);
        h[2] = __float2bfloat16_rn(v.z); h[3] = __float2bfloat16_rn(v.w);
        uint32_t off = sw_off(m, kq >> 1) + (kq & 1) * 8;
        *(uint2*)(smem + SM_A + off) = *(uint2*)h;
    }

    Top3 tp[8];
#pragma unroll
    for (int r = 0; r < 8; r++) {
        tp[r].v1 = -1e30f; tp[r].v2 = -1e30f; tp[r].v3 = -1e30f;
        tp[r].i1 = 0; tp[r].i2 = 0;
    }

    float acc[4][4][4];
#pragma unroll
    for (int mi = 0; mi < 4; mi++)
#pragma unroll
        for (int nj = 0; nj < 4; nj++)
#pragma unroll
            for (int e = 0; e < 4; e++) acc[mi][nj][e] = 0.f;

    const int nlo = (lane & 3) * 2;     // n offset within 8-col group

    for (int c = 0; c < NCHUNKS; c++) {
        const int st = c & 1;
        CPA_WAIT0();
        __syncthreads();

        if (c + 1 < NCHUNKS) {
            const char* bh = (const char*)g_Bh + (size_t)(c + 1) * 16384;
            uint32_t dst = sb + SM_B + (st ^ 1) * 16384;
            for (int i = tid; i < 1024; i += 256)
                cpa16(dst + i * 16, bh + i * 16);
            CPA_COMMIT();
        }

        const uint32_t aBase = sb + SM_A;
        const uint32_t bBase = sb + SM_B + st * 16384;
        const bool cg = (c > 0);
        const int pb = (c - 1) * NCH + wn * 32 + nlo;   // prev-chunk n base

        // ---------- block X: mma G1 (mi 0-1) + epilogue G2(prev) ----------
        uint32_t bfr[4][2][4];
        {
#pragma unroll
            for (int ks = 0; ks < 4; ks++) {
                uint32_t a0[4], a1[4];
                {
                    int ra = wm * 64 + 0 * 16 + (lane & 15);
                    ldm_x4(a0, aBase + sw_off(ra, ks * 2 + (lane >> 4)));
                    ra = wm * 64 + 1 * 16 + (lane & 15);
                    ldm_x4(a1, aBase + sw_off(ra, ks * 2 + (lane >> 4)));
                }
#pragma unroll
                for (int ni2 = 0; ni2 < 2; ni2++) {
                    int rb = wn * 32 + ni2 * 16 + (lane & 7) + ((lane & 16) ? 8 : 0);
                    ldm_x4(bfr[ks][ni2], bBase + sw_off(rb, ks * 2 + ((lane >> 3) & 1)));
                }
#pragma unroll
                for (int nj = 0; nj < 4; nj++) {
                    uint32_t b0 = bfr[ks][nj >> 1][(nj & 1) * 2];
                    uint32_t b1 = bfr[ks][nj >> 1][(nj & 1) * 2 + 1];
                    mma_bf16(acc[0][nj], a0, b0, b1);
                    mma_bf16(acc[1][nj], a1, b0, b1);
                }
            }
            // epilogue of G2 (mi 2-3) from PREVIOUS chunk; neutralized at c==0
#pragma unroll
            for (int mi = 2; mi < 4; mi++)
#pragma unroll
                for (int h = 0; h < 2; h++) {
                    Top3 t = tp[mi * 2 + h];
#pragma unroll
                    for (int nj = 0; nj < 4; nj++)
#pragma unroll
                        for (int p = 0; p < 2; p++) {
                            float v = cg ? acc[mi][nj][h * 2 + p] : -1e30f;
                            t3_hot(t, v, pb + nj * 8 + p);
                        }
                    tp[mi * 2 + h] = t;
                }
#pragma unroll
            for (int mi = 2; mi < 4; mi++)
#pragma unroll
                for (int nj = 0; nj < 4; nj++)
#pragma unroll
                    for (int e = 0; e < 4; e++) acc[mi][nj][e] = 0.f;
        }

        // ---------- block Y: mma G2 (mi 2-3) + epilogue G1(current) ----------
        {
#pragma unroll
            for (int ks = 0; ks < 4; ks++) {
                uint32_t a2[4], a3[4];
                {
                    int ra = wm * 64 + 2 * 16 + (lane & 15);
                    ldm_x4(a2, aBase + sw_off(ra, ks * 2 + (lane >> 4)));
                    ra = wm * 64 + 3 * 16 + (lane & 15);
                    ldm_x4(a3, aBase + sw_off(ra, ks * 2 + (lane >> 4)));
                }
#pragma unroll
                for (int nj = 0; nj < 4; nj++) {
                    uint32_t b0 = bfr[ks][nj >> 1][(nj & 1) * 2];
                    uint32_t b1 = bfr[ks][nj >> 1][(nj & 1) * 2 + 1];
                    mma_bf16(acc[2][nj], a2, b0, b1);
                    mma_bf16(acc[3][nj], a3, b0, b1);
                }
            }
            const int cb0 = c * NCH + wn * 32 + nlo;
#pragma unroll
            for (int mi = 0; mi < 2; mi++)
#pragma unroll
                for (int h = 0; h < 2; h++) {
                    Top3 t = tp[mi * 2 + h];
#pragma unroll
                    for (int nj = 0; nj < 4; nj++)
#pragma unroll
                        for (int p = 0; p < 2; p++)
                            t3_hot(t, acc[mi][nj][h * 2 + p], cb0 + nj * 8 + p);
                    tp[mi * 2 + h] = t;
                }
#pragma unroll
            for (int mi = 0; mi < 2; mi++)
#pragma unroll
                for (int nj = 0; nj < 4; nj++)
#pragma unroll
                    for (int e = 0; e < 4; e++) acc[mi][nj][e] = 0.f;
        }
    }

    // tail: epilogue G2 of last chunk
    {
        const int pb = (NCHUNKS - 1) * NCH + wn * 32 + nlo;
#pragma unroll
        for (int mi = 2; mi < 4; mi++)
#pragma unroll
            for (int h = 0; h < 2; h++) {
                Top3 t = tp[mi * 2 + h];
#pragma unroll
                for (int nj = 0; nj < 4; nj++)
#pragma unroll
                    for (int p = 0; p < 2; p++)
                        t3_hot(t, acc[mi][nj][h * 2 + p], pb + nj * 8 + p);
                tp[mi * 2 + h] = t;
            }
    }

    // intra-warp merge over the 4 lanes sharing each row
#pragma unroll
    for (int r = 0; r < 8; r++) {
#pragma unroll
        for (int d = 1; d <= 2; d <<= 1) {
            float ov1 = __shfl_xor_sync(0xffffffffu, tp[r].v1, d);
            int   oi1 = __shfl_xor_sync(0xffffffffu, tp[r].i1, d);
            float ov2 = __shfl_xor_sync(0xffffffffu, tp[r].v2, d);
            int   oi2 = __shfl_xor_sync(0xffffffffu, tp[r].i2, d);
            float ov3 = __shfl_xor_sync(0xffffffffu, tp[r].v3, d);
            t3_ins(tp[r], ov1, oi1);
            t3_ins(tp[r], ov2, oi2);
            t3_ins(tp[r], ov3, -1);
        }
    }

    // cross-warp (wn) merge via smem
    __syncthreads();
    float* rv1 = (float*)(smem + SM_A);
    int*   ri1 = (int*)(smem + SM_A + 2048);
    float* rv2 = (float*)(smem + SM_A + 4096);
    int*   ri2 = (int*)(smem + SM_A + 6144);
    float* rv3 = (float*)(smem + SM_A + 8192);
    if ((lane & 3) == 0) {
#pragma unroll
        for (int mi = 0; mi < 4; mi++)
#pragma unroll
            for (int h = 0; h < 2; h++) {
                int r = mi * 2 + h;
                int row = wm * 64 + mi * 16 + h * 8 + (lane >> 2);
                rv1[row * 4 + wn] = tp[r].v1;
                ri1[row * 4 + wn] = tp[r].i1;
                rv2[row * 4 + wn] = tp[r].v2;
                ri2[row * 4 + wn] = tp[r].i2;
                rv3[row * 4 + wn] = tp[r].v3;
            }
    }
    __syncthreads();

    __shared__ int s_cnt, s_base, s_pcnt, s_pbase;
    if (tid == 0) { s_cnt = 0; s_pcnt = 0; }
    __syncthreads();
    int slot = -1, pslot = -1;
    int pi1 = 0, pi2 = 0;
    if (tid < MQ) {
        Top3 t;
        t.v1 = rv1[tid * 4]; t.i1 = ri1[tid * 4];
        t.v2 = rv2[tid * 4]; t.i2 = ri2[tid * 4];
        t.v3 = rv3[tid * 4];
#pragma unroll
        for (int w = 1; w < 4; w++) {
            t3_ins(t, rv1[tid * 4 + w], ri1[tid * 4 + w]);
            t3_ins(t, rv2[tid * 4 + w], ri2[tid * 4 + w]);
            t3_ins(t, rv3[tid * 4 + w], -1);
        }
        g_ids[qbase + tid] = t.i1;
        if (t.v1 - t.v3 < DELTA) {
            slot = atomicAdd(&s_cnt, 1);               // full exact rescan
        } else if (t.v1 - t.v2 < DELTA) {
            pslot = atomicAdd(&s_pcnt, 1);             // exact pair rescore
            pi1 = t.i1; pi2 = t.i2;
        }
    }
    __syncthreads();
    if (tid == 0) {
        if (s_cnt > 0)  s_base  = atomicAdd(&g_nrescue, s_cnt);
        if (s_pcnt > 0) s_pbase = atomicAdd(&g_npair, s_pcnt);
    }
    __syncthreads();
    if (slot >= 0)  g_rescue[s_base + slot] = qbase + tid;
    if (pslot >= 0) g_pair[s_pbase + pslot] = make_int2(qbase + tid, pi1 | (pi2 << 16));
}

// ---------------------------------------------------------------------------
// pair rescore: exact fp32 on the two candidates (gap12 < DELTA <= gap13).
// ---------------------------------------------------------------------------
__global__ void pair_kernel(const float* __restrict__ codes,
                            const float* __restrict__ cb) {
    int i = blockIdx.x * blockDim.x + threadIdx.x;
    if (i >= g_npair) return;
    int2 e = g_pair[i];
    int q = e.x, i1 = e.y & 0xFFFF, i2 = e.y >> 16;
    const float4* xr = (const float4*)(codes + (size_t)q * DIM);
    const float4* c1 = (const float4*)(cb + (size_t)i1 * DIM);
    const float4* c2 = (const float4*)(cb + (size_t)i2 * DIM);
    float s1 = 0.f, s2 = 0.f;
#pragma unroll
    for (int kq = 0; kq < 16; kq++) {
        float4 x = xr[kq], a = __ldg(&c1[kq]), b = __ldg(&c2[kq]);
        s1 = fmaf(x.x, a.x, s1); s1 = fmaf(x.y, a.y, s1);
        s1 = fmaf(x.z, a.z, s1); s1 = fmaf(x.w, a.w, s1);
        s2 = fmaf(x.x, b.x, s2); s2 = fmaf(x.y, b.y, s2);
        s2 = fmaf(x.z, b.z, s2); s2 = fmaf(x.w, b.w, s2);
    }
    s1 -= g_hcsq[i1]; s2 -= g_hcsq[i2];
    int best = ((s2 > s1) || (s2 == s1 && i2 < i1)) ? i2 : i1;
    g_ids[q] = best;
}

// ---------------------------------------------------------------------------
// full rescue: exact fp32 rescan (gap13 < DELTA; ~hundreds of queries).
// ---------------------------------------------------------------------------
#define QB 8
__global__ void rescue_kernel(const float* __restrict__ codes,
                              const float* __restrict__ cb) {
    __shared__ float sx[QB][DIM];
    __shared__ float sv[QB][256];
    __shared__ int   si[QB][256];
    int nres = g_nrescue;
    for (int base = blockIdx.x * QB; base < nres; base += gridDim.x * QB) {
        int cnt = min(QB, nres - base);
        __syncthreads();
        for (int i = threadIdx.x; i < cnt * 16; i += 256) {
            int q = i >> 4, kq = i & 15;
            ((float4*)sx[q])[kq] =
                ((const float4*)(codes + (size_t)g_rescue[base + q] * DIM))[kq];
        }
        __syncthreads();
        float bv[QB]; int bi[QB];
#pragma unroll
        for (int q = 0; q < QB; q++) { bv[q] = -1e30f; bi[q] = 0; }
        for (int j = 0; j < 4; j++) {
            int n = threadIdx.x + j * 256;
            const float4* cr = (const float4*)(cb + (size_t)n * DIM);
            float dot[QB];
#pragma unroll
            for (int q = 0; q < QB; q++) dot[q] = 0.f;
#pragma unroll
            for (int kq = 0; kq < 16; kq++) {
                float4 c4 = __ldg(&cr[kq]);
#pragma unroll
                for (int q = 0; q < QB; q++) {
                    dot[q] = fmaf(sx[q][kq * 4 + 0], c4.x, dot[q]);
                    dot[q] = fmaf(sx[q][kq * 4 + 1], c4.y, dot[q]);
                    dot[q] = fmaf(sx[q][kq * 4 + 2], c4.z, dot[q]);
                    dot[q] = fmaf(sx[q][kq * 4 + 3], c4.w, dot[q]);
                }
            }
            float hcv = g_hcsq[n];
#pragma unroll
            for (int q = 0; q < QB; q++) {
                float s = dot[q] - hcv;
                if (s > bv[q]) { bv[q] = s; bi[q] = n; }
            }
        }
#pragma unroll
        for (int q = 0; q < QB; q++) { sv[q][threadIdx.x] = bv[q]; si[q][threadIdx.x] = bi[q]; }
        __syncthreads();
        int w = threadIdx.x >> 5, lane = threadIdx.x & 31;
        if (w < QB && w < cnt) {
            float v = sv[w][lane]; int ix = si[w][lane];
            for (int t = lane + 32; t < 256; t += 32) {
                float ov = sv[w][t]; int oi = si[w][t];
                if (ov > v || (ov == v && oi < ix)) { v = ov; ix = oi; }
            }
#pragma unroll
            for (int d = 16; d > 0; d >>= 1) {
                float ov = __shfl_down_sync(0xffffffffu, v, d);
                int   oi = __shfl_down_sync(0xffffffffu, ix, d);
                if (ov > v || (ov == v && oi < ix)) { v = ov; ix = oi; }
            }
            if (lane == 0) g_ids[g_rescue[base + w]] = ix;
        }
        __syncthreads();
    }
}

// ---------------------------------------------------------------------------
__global__ void gather_kernel(const float* __restrict__ cb,
                              float* __restrict__ out_codes,
                              float* __restrict__ out_ids,
                              int nq, int write_ids) {
    int t = blockIdx.x * blockDim.x + threadIdx.x;
    if (t < nq * (DIM / 4)) {
        int q = t >> 4, part = t & 15;
        int id = g_ids[q];
        float4 v = *(const float4*)(cb + (size_t)id * DIM + part * 4);
        *(float4*)(out_codes + (size_t)q * DIM + part * 4) = v;
    }
    if (write_ids && t < nq) out_ids[t] = (float)g_ids[t];
}

// ---------------------------------------------------------------------------
extern "C" void kernel_launch(void* const* d_in, const int* in_sizes, int n_in,
                              void* d_out, int out_size) {
    const float* codes = (const float*)d_in[0];
    const float* cb    = (const float*)d_in[1];
    float* out = (float*)d_out;

    int nq = in_sizes[0] / DIM;
    if (nq > MAX_Q) nq = MAX_Q;

    static int attr_done = 0;
    if (!attr_done) {
        cudaFuncSetAttribute(vq_mma_kernel,
                             cudaFuncAttributeMaxDynamicSharedMemorySize, SMEM_TOTAL);
        attr_done = 1;
    }

    prep_kernel<<<(NT * 16 + 255) / 256, 256>>>(cb);
    vq_mma_kernel<<<nq / MQ, 256, SMEM_TOTAL>>>(codes);
    pair_kernel<<<1024, 256>>>(codes, cb);
    rescue_kernel<<<512, 256>>>(codes, cb);

    int write_ids = (out_size >= nq * DIM + nq) ? 1 : 0;
    float* out_ids = out + (size_t)nq * DIM;
    int total = nq * (DIM / 4);
    gather_kernel<<<(total + 255) / 256, 256>>>(cb, out, out_ids, nq, write_ids);
}

// round 11
// speedup vs baseline: 3.1987x; 1.3334x over previous
#include <cuda_runtime.h>
#include <cuda_bf16.h>
#include <stdint.h>

#define DIM 64
#define NT 1024
#define MQ 128
#define NCH 128
#define NCHUNKS (NT / NCH)
#define MAX_Q (64 * 4096)
// 1-pass bf16 pairwise err std ~2.3e-3 + 2x mantissa-stomp (<=2.6e-3 bound).
#define DELTA 0.022f

__device__ int           g_ids[MAX_Q];
__device__ float         g_hcsq[NT];
__device__ __nv_bfloat16 g_Bh[NT * DIM];
__device__ int           g_nrescue;
__device__ int           g_rescue[MAX_Q];
__device__ int           g_npair;
__device__ int2          g_pair[MAX_Q];
__device__ float         g_pv[MAX_Q * 4];
__device__ int           g_pi[MAX_Q * 4];

// ---------------- helpers ----------------
__device__ __forceinline__ uint32_t smem_u32(const void* p) {
    uint32_t a;
    asm("{ .reg .u64 t; cvta.to.shared.u64 t, %1; cvt.u32.u64 %0, t; }"
        : "=r"(a) : "l"(p));
    return a;
}
__device__ __forceinline__ void ldm_x4(uint32_t* r, uint32_t addr) {
    asm volatile("ldmatrix.sync.aligned.m8n8.x4.shared.b16 {%0,%1,%2,%3}, [%4];"
                 : "=r"(r[0]), "=r"(r[1]), "=r"(r[2]), "=r"(r[3]) : "r"(addr));
}
__device__ __forceinline__ void mma_bf16(float* c, const uint32_t* a,
                                         uint32_t b0, uint32_t b1) {
    asm volatile(
        "mma.sync.aligned.m16n8k16.row.col.f32.bf16.bf16.f32 "
        "{%0,%1,%2,%3}, {%4,%5,%6,%7}, {%8,%9}, {%0,%1,%2,%3};"
        : "+f"(c[0]), "+f"(c[1]), "+f"(c[2]), "+f"(c[3])
        : "r"(a[0]), "r"(a[1]), "r"(a[2]), "r"(a[3]), "r"(b0), "r"(b1));
}
__device__ __forceinline__ void cpa16(uint32_t dst, const void* src) {
    asm volatile("cp.async.cg.shared.global [%0], [%1], 16;" :: "r"(dst), "l"(src));
}
#define CPA_COMMIT() asm volatile("cp.async.commit_group;" ::: "memory")
#define CPA_WAIT0()  asm volatile("cp.async.wait_group 0;" ::: "memory")

__device__ __forceinline__ uint32_t sw_off(int row, int chunk) {
    return (uint32_t)row * 128u + (uint32_t)((chunk ^ (row & 7)) << 4);
}

// packed top-3: value's low 10 mantissa bits hold (1023 - n). Pure FMNMX.
struct T3 { float v1, v2, v3; };
__device__ __forceinline__ void t3p(T3& t, float s) {
    float lo  = fminf(s, t.v1);
    t.v1 = fmaxf(s, t.v1);
    float lo2 = fminf(lo, t.v2);
    t.v2 = fmaxf(lo, t.v2);
    t.v3 = fmaxf(lo2, t.v3);
}
__device__ __forceinline__ float pk(float v, uint32_t idxc) {
    return __uint_as_float((__float_as_uint(v) & 0xFFFFFC00u) | idxc);
}
__device__ __forceinline__ int dec_idx(float v) {
    return 1023 - (int)(__float_as_uint(v) & 1023u);
}

// ---------------- smem map (dynamic, 49152 B) ----------------
#define SM_A 0
#define SM_B 16384
#define SMEM_TOTAL 49152

// ---------------------------------------------------------------------------
__global__ void prep_kernel(const float* __restrict__ cb) {
    int t = blockIdx.x * blockDim.x + threadIdx.x;
    if (t == 0) { g_nrescue = 0; g_npair = 0; }
    if (t >= NT * 16) return;
    int n = t >> 4, kq = t & 15;
    float4 v = *(const float4*)(cb + (size_t)n * DIM + kq * 4);
    __nv_bfloat16 h[4];
    h[0] = __float2bfloat16_rn(v.x); h[1] = __float2bfloat16_rn(v.y);
    h[2] = __float2bfloat16_rn(v.z); h[3] = __float2bfloat16_rn(v.w);
    int ch = n >> 7, ln = n & 127;
    uint32_t off = (uint32_t)ch * 16384u + sw_off(ln, kq >> 1) + (kq & 1) * 8;
    *(uint2*)((char*)g_Bh + off) = *(uint2*)h;
    if (kq == 0) {
        const float4* row = (const float4*)(cb + (size_t)n * DIM);
        float s = 0.f;
#pragma unroll
        for (int i = 0; i < 16; i++) {
            float4 w = row[i];
            s += w.x * w.x + w.y * w.y + w.z * w.z + w.w * w.w;
        }
        g_hcsq[n] = 0.5f * s;
    }
}

// ---------------------------------------------------------------------------
// main: 1-pass bf16 mma.sync + packed top-3; mi-split MMA/epilogue overlap.
// ---------------------------------------------------------------------------
__global__ void __launch_bounds__(256, 1)
vq_mma_kernel(const float* __restrict__ codes) {
    extern __shared__ char smem[];
    const uint32_t sb = smem_u32(smem);
    const int tid  = threadIdx.x;
    const int wid  = tid >> 5, lane = tid & 31;
    const int wm   = wid >> 2;
    const int wn   = wid & 3;
    const int qbase = blockIdx.x * MQ;

    for (int i = tid; i < 1024; i += 256)
        cpa16(sb + SM_B + i * 16, (const char*)g_Bh + i * 16);
    CPA_COMMIT();

    for (int i = tid; i < MQ * 16; i += 256) {
        int m = i >> 4, kq = i & 15;
        float4 v = *(const float4*)(codes + (size_t)(qbase + m) * DIM + kq * 4);
        __nv_bfloat16 h[4];
        h[0] = __float2bfloat16_rn(v.x); h[1] = __float2bfloat16_rn(v.y);
        h[2] = __float2bfloat16_rn(v.z); h[3] = __float2bfloat16_rn(v.w);
        uint32_t off = sw_off(m, kq >> 1) + (kq & 1) * 8;
        *(uint2*)(smem + SM_A + off) = *(uint2*)h;
    }

    T3 tp[8];
#pragma unroll
    for (int r = 0; r < 8; r++) { tp[r].v1 = -1e30f; tp[r].v2 = -1e30f; tp[r].v3 = -1e30f; }

    float acc[4][4][4];
#pragma unroll
    for (int mi = 0; mi < 4; mi++)
#pragma unroll
        for (int nj = 0; nj < 4; nj++)
#pragma unroll
            for (int e = 0; e < 4; e++) acc[mi][nj][e] = 0.f;

    const int nlo = (lane & 3) * 2;

    for (int c = 0; c < NCHUNKS; c++) {
        const int st = c & 1;
        CPA_WAIT0();
        __syncthreads();

        if (c + 1 < NCHUNKS) {
            const char* bh = (const char*)g_Bh + (size_t)(c + 1) * 16384;
            uint32_t dst = sb + SM_B + (st ^ 1) * 16384;
            for (int i = tid; i < 1024; i += 256)
                cpa16(dst + i * 16, bh + i * 16);
            CPA_COMMIT();
        }

        const uint32_t aBase = sb + SM_A;
        const uint32_t bBase = sb + SM_B + st * 16384;
        const bool cg = (c > 0);
        // index complements for this warp's 8 n-positions (prev & cur chunk)
        uint32_t icp[8], icc[8];
#pragma unroll
        for (int nj = 0; nj < 4; nj++)
#pragma unroll
            for (int p = 0; p < 2; p++) {
                int npos = wn * 32 + nj * 8 + nlo + p;
                icp[nj * 2 + p] = (uint32_t)(1023 - ((c - 1) * NCH + npos));
                icc[nj * 2 + p] = (uint32_t)(1023 - (c * NCH + npos));
            }

        uint32_t bfr[4][2][4];
        // ---------- block X: mma G1 (mi 0-1) + epilogue G2(prev) ----------
        {
#pragma unroll
            for (int ks = 0; ks < 4; ks++) {
                uint32_t a0[4], a1[4];
                {
                    int ra = wm * 64 + 0 * 16 + (lane & 15);
                    ldm_x4(a0, aBase + sw_off(ra, ks * 2 + (lane >> 4)));
                    ra = wm * 64 + 1 * 16 + (lane & 15);
                    ldm_x4(a1, aBase + sw_off(ra, ks * 2 + (lane >> 4)));
                }
#pragma unroll
                for (int ni2 = 0; ni2 < 2; ni2++) {
                    int rb = wn * 32 + ni2 * 16 + (lane & 7) + ((lane & 16) ? 8 : 0);
                    ldm_x4(bfr[ks][ni2], bBase + sw_off(rb, ks * 2 + ((lane >> 3) & 1)));
                }
#pragma unroll
                for (int nj = 0; nj < 4; nj++) {
                    uint32_t b0 = bfr[ks][nj >> 1][(nj & 1) * 2];
                    uint32_t b1 = bfr[ks][nj >> 1][(nj & 1) * 2 + 1];
                    mma_bf16(acc[0][nj], a0, b0, b1);
                    mma_bf16(acc[1][nj], a1, b0, b1);
                }
            }
#pragma unroll
            for (int mi = 2; mi < 4; mi++)
#pragma unroll
                for (int h = 0; h < 2; h++) {
                    T3 t = tp[mi * 2 + h];
#pragma unroll
                    for (int nj = 0; nj < 4; nj++)
#pragma unroll
                        for (int p = 0; p < 2; p++) {
                            float s = cg ? pk(acc[mi][nj][h * 2 + p], icp[nj * 2 + p])
                                         : -1e30f;
                            t3p(t, s);
                        }
                    tp[mi * 2 + h] = t;
                }
#pragma unroll
            for (int mi = 2; mi < 4; mi++)
#pragma unroll
                for (int nj = 0; nj < 4; nj++)
#pragma unroll
                    for (int e = 0; e < 4; e++) acc[mi][nj][e] = 0.f;
        }

        // ---------- block Y: mma G2 (mi 2-3) + epilogue G1(current) ----------
        {
#pragma unroll
            for (int ks = 0; ks < 4; ks++) {
                uint32_t a2[4], a3[4];
                {
                    int ra = wm * 64 + 2 * 16 + (lane & 15);
                    ldm_x4(a2, aBase + sw_off(ra, ks * 2 + (lane >> 4)));
                    ra = wm * 64 + 3 * 16 + (lane & 15);
                    ldm_x4(a3, aBase + sw_off(ra, ks * 2 + (lane >> 4)));
                }
#pragma unroll
                for (int nj = 0; nj < 4; nj++) {
                    uint32_t b0 = bfr[ks][nj >> 1][(nj & 1) * 2];
                    uint32_t b1 = bfr[ks][nj >> 1][(nj & 1) * 2 + 1];
                    mma_bf16(acc[2][nj], a2, b0, b1);
                    mma_bf16(acc[3][nj], a3, b0, b1);
                }
            }
#pragma unroll
            for (int mi = 0; mi < 2; mi++)
#pragma unroll
                for (int h = 0; h < 2; h++) {
                    T3 t = tp[mi * 2 + h];
#pragma unroll
                    for (int nj = 0; nj < 4; nj++)
#pragma unroll
                        for (int p = 0; p < 2; p++)
                            t3p(t, pk(acc[mi][nj][h * 2 + p], icc[nj * 2 + p]));
                    tp[mi * 2 + h] = t;
                }
#pragma unroll
            for (int mi = 0; mi < 2; mi++)
#pragma unroll
                for (int nj = 0; nj < 4; nj++)
#pragma unroll
                    for (int e = 0; e < 4; e++) acc[mi][nj][e] = 0.f;
        }
    }

    // tail: epilogue G2 of last chunk
    {
#pragma unroll
        for (int nj = 0; nj < 4; nj++) { /* recompute last-chunk complements */ }
        uint32_t ict[8];
#pragma unroll
        for (int nj = 0; nj < 4; nj++)
#pragma unroll
            for (int p = 0; p < 2; p++)
                ict[nj * 2 + p] =
                    (uint32_t)(1023 - ((NCHUNKS - 1) * NCH + wn * 32 + nj * 8 + nlo + p));
#pragma unroll
        for (int mi = 2; mi < 4; mi++)
#pragma unroll
            for (int h = 0; h < 2; h++) {
                T3 t = tp[mi * 2 + h];
#pragma unroll
                for (int nj = 0; nj < 4; nj++)
#pragma unroll
                    for (int p = 0; p < 2; p++)
                        t3p(t, pk(acc[mi][nj][h * 2 + p], ict[nj * 2 + p]));
                tp[mi * 2 + h] = t;
            }
    }

    // intra-warp merge (lanes sharing each row differ in bits 0-1)
#pragma unroll
    for (int r = 0; r < 8; r++) {
#pragma unroll
        for (int d = 1; d <= 2; d <<= 1) {
            float o1 = __shfl_xor_sync(0xffffffffu, tp[r].v1, d);
            float o2 = __shfl_xor_sync(0xffffffffu, tp[r].v2, d);
            float o3 = __shfl_xor_sync(0xffffffffu, tp[r].v3, d);
            t3p(tp[r], o1); t3p(tp[r], o2); t3p(tp[r], o3);
        }
    }

    // cross-warp (wn) merge via smem
    __syncthreads();
    float* rv1 = (float*)(smem + SM_A);
    float* rv2 = (float*)(smem + SM_A + 2048);
    float* rv3 = (float*)(smem + SM_A + 4096);
    if ((lane & 3) == 0) {
#pragma unroll
        for (int mi = 0; mi < 4; mi++)
#pragma unroll
            for (int h = 0; h < 2; h++) {
                int r = mi * 2 + h;
                int row = wm * 64 + mi * 16 + h * 8 + (lane >> 2);
                rv1[row * 4 + wn] = tp[r].v1;
                rv2[row * 4 + wn] = tp[r].v2;
                rv3[row * 4 + wn] = tp[r].v3;
            }
    }
    __syncthreads();

    __shared__ int s_cnt, s_base, s_pcnt, s_pbase;
    if (tid == 0) { s_cnt = 0; s_pcnt = 0; }
    __syncthreads();
    int slot = -1, pslot = -1;
    int pi1 = 0, pi2 = 0;
    if (tid < MQ) {
        T3 t;
        t.v1 = rv1[tid * 4]; t.v2 = rv2[tid * 4]; t.v3 = rv3[tid * 4];
#pragma unroll
        for (int w = 1; w < 4; w++) {
            t3p(t, rv1[tid * 4 + w]);
            t3p(t, rv2[tid * 4 + w]);
            t3p(t, rv3[tid * 4 + w]);
        }
        g_ids[qbase + tid] = dec_idx(t.v1);
        if (t.v1 - t.v3 < DELTA) {
            slot = atomicAdd(&s_cnt, 1);
        } else if (t.v1 - t.v2 < DELTA) {
            pslot = atomicAdd(&s_pcnt, 1);
            pi1 = dec_idx(t.v1); pi2 = dec_idx(t.v2);
        }
    }
    __syncthreads();
    if (tid == 0) {
        if (s_cnt > 0)  s_base  = atomicAdd(&g_nrescue, s_cnt);
        if (s_pcnt > 0) s_pbase = atomicAdd(&g_npair, s_pcnt);
    }
    __syncthreads();
    if (slot >= 0)  g_rescue[s_base + slot] = qbase + tid;
    if (pslot >= 0) g_pair[s_pbase + pslot] = make_int2(qbase + tid, pi1 | (pi2 << 16));
}

// ---------------------------------------------------------------------------
// pair rescore: exact fp32 on two candidates.
// ---------------------------------------------------------------------------
__global__ void pair_kernel(const float* __restrict__ codes,
                            const float* __restrict__ cb) {
    int i = blockIdx.x * blockDim.x + threadIdx.x;
    if (i >= g_npair) return;
    int2 e = g_pair[i];
    int q = e.x, i1 = e.y & 0xFFFF, i2 = e.y >> 16;
    const float4* xr = (const float4*)(codes + (size_t)q * DIM);
    const float4* c1 = (const float4*)(cb + (size_t)i1 * DIM);
    const float4* c2 = (const float4*)(cb + (size_t)i2 * DIM);
    float s1 = 0.f, s2 = 0.f;
#pragma unroll
    for (int kq = 0; kq < 16; kq++) {
        float4 x = xr[kq], a = __ldg(&c1[kq]), b = __ldg(&c2[kq]);
        s1 = fmaf(x.x, a.x, s1); s1 = fmaf(x.y, a.y, s1);
        s1 = fmaf(x.z, a.z, s1); s1 = fmaf(x.w, a.w, s1);
        s2 = fmaf(x.x, b.x, s2); s2 = fmaf(x.y, b.y, s2);
        s2 = fmaf(x.z, b.z, s2); s2 = fmaf(x.w, b.w, s2);
    }
    s1 -= g_hcsq[i1]; s2 -= g_hcsq[i2];
    int best = ((s2 > s1) || (s2 == s1 && i2 < i1)) ? i2 : i1;
    g_ids[q] = best;
}

// ---------------------------------------------------------------------------
// full rescue, split 4 ways: block (group, quarter) scans 256 codes for 8
// queries; partial (val, idx) to global; merge kernel finalizes.
// ---------------------------------------------------------------------------
#define QB 8
__global__ void rescue_part(const float* __restrict__ codes,
                            const float* __restrict__ cb) {
    __shared__ float sx[QB][DIM];
    __shared__ float sv[QB][256];
    int nres = g_nrescue;
    int ngb = ((nres + QB - 1) / QB) * 4;
    for (int gb = blockIdx.x; gb < ngb; gb += gridDim.x) {
        int grp = gb >> 2, quar = gb & 3;
        int base = grp * QB;
        int cnt = min(QB, nres - base);
        __syncthreads();
        for (int i = threadIdx.x; i < cnt * 16; i += 256) {
            int q = i >> 4, kq = i & 15;
            ((float4*)sx[q])[kq] =
                ((const float4*)(codes + (size_t)g_rescue[base + q] * DIM))[kq];
        }
        __syncthreads();
        int n = quar * 256 + threadIdx.x;
        const float4* cr = (const float4*)(cb + (size_t)n * DIM);
        float dot[QB];
#pragma unroll
        for (int q = 0; q < QB; q++) dot[q] = 0.f;
#pragma unroll
        for (int kq = 0; kq < 16; kq++) {
            float4 c4 = __ldg(&cr[kq]);
#pragma unroll
            for (int q = 0; q < QB; q++) {
                dot[q] = fmaf(sx[q][kq * 4 + 0], c4.x, dot[q]);
                dot[q] = fmaf(sx[q][kq * 4 + 1], c4.y, dot[q]);
                dot[q] = fmaf(sx[q][kq * 4 + 2], c4.z, dot[q]);
                dot[q] = fmaf(sx[q][kq * 4 + 3], c4.w, dot[q]);
            }
        }
        float hcv = g_hcsq[n];
#pragma unroll
        for (int q = 0; q < QB; q++) sv[q][threadIdx.x] = dot[q] - hcv;
        __syncthreads();
        int w = threadIdx.x >> 5, lane = threadIdx.x & 31;
        if (w < cnt) {
            float v = sv[w][lane]; int ix = lane;
            for (int t = lane + 32; t < 256; t += 32) {
                float ov = sv[w][t];
                if (ov > v || (ov == v && t < ix)) { v = ov; ix = t; }
            }
#pragma unroll
            for (int d = 16; d > 0; d >>= 1) {
                float ov = __shfl_down_sync(0xffffffffu, v, d);
                int   oi = __shfl_down_sync(0xffffffffu, ix, d);
                if (ov > v || (ov == v && oi < ix)) { v = ov; ix = oi; }
            }
            if (lane == 0) {
                g_pv[(base + w) * 4 + quar] = v;
                g_pi[(base + w) * 4 + quar] = quar * 256 + ix;
            }
        }
        __syncthreads();
    }
}

__global__ void rescue_merge() {
    for (int i = blockIdx.x * blockDim.x + threadIdx.x; i < g_nrescue;
         i += gridDim.x * blockDim.x) {
        float bv = g_pv[i * 4]; int bi = g_pi[i * 4];
#pragma unroll
        for (int q = 1; q < 4; q++) {
            float v = g_pv[i * 4 + q]; int ix = g_pi[i * 4 + q];
            if (v > bv || (v == bv && ix < bi)) { bv = v; bi = ix; }
        }
        g_ids[g_rescue[i]] = bi;
    }
}

// ---------------------------------------------------------------------------
__global__ void gather_kernel(const float* __restrict__ cb,
                              float* __restrict__ out_codes,
                              float* __restrict__ out_ids,
                              int nq, int write_ids) {
    int t = blockIdx.x * blockDim.x + threadIdx.x;
    if (t < nq * (DIM / 4)) {
        int q = t >> 4, part = t & 15;
        int id = g_ids[q];
        float4 v = *(const float4*)(cb + (size_t)id * DIM + part * 4);
        *(float4*)(out_codes + (size_t)q * DIM + part * 4) = v;
    }
    if (write_ids && t < nq) out_ids[t] = (float)g_ids[t];
}

// ---------------------------------------------------------------------------
extern "C" void kernel_launch(void* const* d_in, const int* in_sizes, int n_in,
                              void* d_out, int out_size) {
    const float* codes = (const float*)d_in[0];
    const float* cb    = (const float*)d_in[1];
    float* out = (float*)d_out;

    int nq = in_sizes[0] / DIM;
    if (nq > MAX_Q) nq = MAX_Q;

    static int attr_done = 0;
    if (!attr_done) {
        cudaFuncSetAttribute(vq_mma_kernel,
                             cudaFuncAttributeMaxDynamicSharedMemorySize, SMEM_TOTAL);
        attr_done = 1;
    }

    prep_kernel<<<(NT * 16 + 255) / 256, 256>>>(cb);
    vq_mma_kernel<<<nq / MQ, 256, SMEM_TOTAL>>>(codes);
    pair_kernel<<<1024, 256>>>(codes, cb);
    rescue_part<<<2048, 256>>>(codes, cb);
    rescue_merge<<<64, 256>>>();

    int write_ids = (out_size >= nq * DIM + nq) ? 1 : 0;
    float* out_ids = out + (size_t)nq * DIM;
    int total = nq * (DIM / 4);
    gather_kernel<<<(total + 255) / 256, 256>>>(cb, out, out_ids, nq, write_ids);
}

// round 12
// speedup vs baseline: 3.9181x; 1.2249x over previous
#include <cuda_runtime.h>
#include <cuda_bf16.h>
#include <stdint.h>

#define DIM 64
#define NT 1024
#define MQ 128
#define NCH 64
#define NCHUNKS (NT / NCH)      // 16
#define MAX_Q (64 * 4096)
// 1-pass bf16 pairwise err std ~2.3e-3 + 2x mantissa-stomp (<=2.6e-3 bound).
#define DELTA 0.022f

__device__ int           g_ids[MAX_Q];
__device__ float         g_hcsq[NT];
__device__ __nv_bfloat16 g_Bh[NT * DIM];     // 16 chunk tiles of 64 rows x 128B
__device__ int           g_nrescue;
__device__ int           g_rescue[MAX_Q];
__device__ int           g_npair;
__device__ int2          g_pair[MAX_Q];
__device__ float         g_pv[MAX_Q * 4];
__device__ int           g_pi[MAX_Q * 4];

// ---------------- helpers ----------------
__device__ __forceinline__ uint32_t smem_u32(const void* p) {
    uint32_t a;
    asm("{ .reg .u64 t; cvta.to.shared.u64 t, %1; cvt.u32.u64 %0, t; }"
        : "=r"(a) : "l"(p));
    return a;
}
__device__ __forceinline__ void ldm_x4(uint32_t* r, uint32_t addr) {
    asm volatile("ldmatrix.sync.aligned.m8n8.x4.shared.b16 {%0,%1,%2,%3}, [%4];"
                 : "=r"(r[0]), "=r"(r[1]), "=r"(r[2]), "=r"(r[3]) : "r"(addr));
}
__device__ __forceinline__ void mma_bf16(float* c, const uint32_t* a,
                                         uint32_t b0, uint32_t b1) {
    asm volatile(
        "mma.sync.aligned.m16n8k16.row.col.f32.bf16.bf16.f32 "
        "{%0,%1,%2,%3}, {%4,%5,%6,%7}, {%8,%9}, {%0,%1,%2,%3};"
        : "+f"(c[0]), "+f"(c[1]), "+f"(c[2]), "+f"(c[3])
        : "r"(a[0]), "r"(a[1]), "r"(a[2]), "r"(a[3]), "r"(b0), "r"(b1));
}
__device__ __forceinline__ void cpa16(uint32_t dst, const void* src) {
    asm volatile("cp.async.cg.shared.global [%0], [%1], 16;" :: "r"(dst), "l"(src));
}
#define CPA_COMMIT() asm volatile("cp.async.commit_group;" ::: "memory")
#define CPA_WAIT0()  asm volatile("cp.async.wait_group 0;" ::: "memory")

__device__ __forceinline__ uint32_t sw_off(int row, int chunk) {
    return (uint32_t)row * 128u + (uint32_t)((chunk ^ (row & 7)) << 4);
}

// packed top-3: value's low 10 mantissa bits hold (1023 - n). Pure FMNMX.
struct T3 { float v1, v2, v3; };
__device__ __forceinline__ void t3p(T3& t, float s) {
    float lo  = fminf(s, t.v1);
    t.v1 = fmaxf(s, t.v1);
    float lo2 = fminf(lo, t.v2);
    t.v2 = fmaxf(lo, t.v2);
    t.v3 = fmaxf(lo2, t.v3);
}
__device__ __forceinline__ float pk(float v, uint32_t idxc) {
    return __uint_as_float((__float_as_uint(v) & 0xFFFFFC00u) | idxc);
}
__device__ __forceinline__ int dec_idx(float v) {
    return 1023 - (int)(__float_as_uint(v) & 1023u);
}

// ---------------- smem map (dynamic, 32768 B -> 2 CTAs/SM) ----------------
#define SM_A 0            // 16 KB query tile; reused for merge arrays
#define SM_B 16384        // 2 stages x 8 KB
#define SMEM_TOTAL 32768

// ---------------------------------------------------------------------------
__global__ void prep_kernel(const float* __restrict__ cb) {
    int t = blockIdx.x * blockDim.x + threadIdx.x;
    if (t == 0) { g_nrescue = 0; g_npair = 0; }
    if (t >= NT * 16) return;
    int n = t >> 4, kq = t & 15;
    float4 v = *(const float4*)(cb + (size_t)n * DIM + kq * 4);
    __nv_bfloat16 h[4];
    h[0] = __float2bfloat16_rn(v.x); h[1] = __float2bfloat16_rn(v.y);
    h[2] = __float2bfloat16_rn(v.z); h[3] = __float2bfloat16_rn(v.w);
    int ch = n >> 6, ln = n & 63;
    uint32_t off = (uint32_t)ch * 8192u + sw_off(ln, kq >> 1) + (kq & 1) * 8;
    *(uint2*)((char*)g_Bh + off) = *(uint2*)h;
    if (kq == 0) {
        const float4* row = (const float4*)(cb + (size_t)n * DIM);
        float s = 0.f;
#pragma unroll
        for (int i = 0; i < 16; i++) {
            float4 w = row[i];
            s += w.x * w.x + w.y * w.y + w.z * w.z + w.w * w.w;
        }
        g_hcsq[n] = 0.5f * s;
    }
}

// ---------------------------------------------------------------------------
// main: 1-pass bf16 mma.sync + packed top-3; mi-split overlap; NCH=64;
// occupancy 2; fused output write.
// ---------------------------------------------------------------------------
__global__ void __launch_bounds__(256, 2)
vq_mma_kernel(const float* __restrict__ codes, const float* __restrict__ cb,
              float* __restrict__ out_codes, float* __restrict__ out_ids,
              int write_ids) {
    extern __shared__ char smem[];
    const uint32_t sb = smem_u32(smem);
    const int tid  = threadIdx.x;
    const int wid  = tid >> 5, lane = tid & 31;
    const int wm   = wid >> 2;          // m offset 0/64
    const int wn   = wid & 3;           // n offset 0/16/32/48
    const int qbase = blockIdx.x * MQ;

    for (int i = tid; i < 512; i += 256)
        cpa16(sb + SM_B + i * 16, (const char*)g_Bh + i * 16);
    CPA_COMMIT();

    for (int i = tid; i < MQ * 16; i += 256) {
        int m = i >> 4, kq = i & 15;
        float4 v = *(const float4*)(codes + (size_t)(qbase + m) * DIM + kq * 4);
        __nv_bfloat16 h[4];
        h[0] = __float2bfloat16_rn(v.x); h[1] = __float2bfloat16_rn(v.y);
        h[2] = __float2bfloat16_rn(v.z); h[3] = __float2bfloat16_rn(v.w);
        uint32_t off = sw_off(m, kq >> 1) + (kq & 1) * 8;
        *(uint2*)(smem + SM_A + off) = *(uint2*)h;
    }

    T3 tp[8];
#pragma unroll
    for (int r = 0; r < 8; r++) { tp[r].v1 = -1e30f; tp[r].v2 = -1e30f; tp[r].v3 = -1e30f; }

    float acc[4][2][4];
#pragma unroll
    for (int mi = 0; mi < 4; mi++)
#pragma unroll
        for (int nj = 0; nj < 2; nj++)
#pragma unroll
            for (int e = 0; e < 4; e++) acc[mi][nj][e] = 0.f;

    const int nlo = (lane & 3) * 2;
    // per-thread n positions within a chunk (4 values: nj x p)
    int npos[4];
#pragma unroll
    for (int nj = 0; nj < 2; nj++)
#pragma unroll
        for (int p = 0; p < 2; p++)
            npos[nj * 2 + p] = wn * 16 + nj * 8 + nlo + p;

    for (int c = 0; c < NCHUNKS; c++) {
        const int st = c & 1;
        CPA_WAIT0();
        __syncthreads();

        if (c + 1 < NCHUNKS) {
            const char* bh = (const char*)g_Bh + (size_t)(c + 1) * 8192;
            uint32_t dst = sb + SM_B + (st ^ 1) * 8192;
            for (int i = tid; i < 512; i += 256)
                cpa16(dst + i * 16, bh + i * 16);
            CPA_COMMIT();
        }

        const uint32_t aBase = sb + SM_A;
        const uint32_t bBase = sb + SM_B + st * 8192;
        const bool cg = (c > 0);

        uint32_t bfr[4][4];
        // ---------- block X: mma G1 (mi 0-1) + epilogue G2(prev) ----------
        {
#pragma unroll
            for (int ks = 0; ks < 4; ks++) {
                uint32_t a0[4], a1[4];
                {
                    int ra = wm * 64 + 0 * 16 + (lane & 15);
                    ldm_x4(a0, aBase + sw_off(ra, ks * 2 + (lane >> 4)));
                    ra = wm * 64 + 1 * 16 + (lane & 15);
                    ldm_x4(a1, aBase + sw_off(ra, ks * 2 + (lane >> 4)));
                }
                {
                    int rb = wn * 16 + (lane & 7) + ((lane & 16) ? 8 : 0);
                    ldm_x4(bfr[ks], bBase + sw_off(rb, ks * 2 + ((lane >> 3) & 1)));
                }
#pragma unroll
                for (int nj = 0; nj < 2; nj++) {
                    uint32_t b0 = bfr[ks][nj * 2], b1 = bfr[ks][nj * 2 + 1];
                    mma_bf16(acc[0][nj], a0, b0, b1);
                    mma_bf16(acc[1][nj], a1, b0, b1);
                }
            }
#pragma unroll
            for (int mi = 2; mi < 4; mi++)
#pragma unroll
                for (int h = 0; h < 2; h++) {
                    T3 t = tp[mi * 2 + h];
#pragma unroll
                    for (int j = 0; j < 4; j++) {
                        uint32_t ic = (uint32_t)(1023 - ((c - 1) * NCH + npos[j]));
                        float s = cg ? pk(acc[mi][(j >> 1)][h * 2 + (j & 1)], ic)
                                     : -1e30f;
                        t3p(t, s);
                    }
                    tp[mi * 2 + h] = t;
                }
#pragma unroll
            for (int mi = 2; mi < 4; mi++)
#pragma unroll
                for (int nj = 0; nj < 2; nj++)
#pragma unroll
                    for (int e = 0; e < 4; e++) acc[mi][nj][e] = 0.f;
        }

        // ---------- block Y: mma G2 (mi 2-3) + epilogue G1(current) ----------
        {
#pragma unroll
            for (int ks = 0; ks < 4; ks++) {
                uint32_t a2[4], a3[4];
                {
                    int ra = wm * 64 + 2 * 16 + (lane & 15);
                    ldm_x4(a2, aBase + sw_off(ra, ks * 2 + (lane >> 4)));
                    ra = wm * 64 + 3 * 16 + (lane & 15);
                    ldm_x4(a3, aBase + sw_off(ra, ks * 2 + (lane >> 4)));
                }
#pragma unroll
                for (int nj = 0; nj < 2; nj++) {
                    uint32_t b0 = bfr[ks][nj * 2], b1 = bfr[ks][nj * 2 + 1];
                    mma_bf16(acc[2][nj], a2, b0, b1);
                    mma_bf16(acc[3][nj], a3, b0, b1);
                }
            }
#pragma unroll
            for (int mi = 0; mi < 2; mi++)
#pragma unroll
                for (int h = 0; h < 2; h++) {
                    T3 t = tp[mi * 2 + h];
#pragma unroll
                    for (int j = 0; j < 4; j++) {
                        uint32_t ic = (uint32_t)(1023 - (c * NCH + npos[j]));
                        t3p(t, pk(acc[mi][(j >> 1)][h * 2 + (j & 1)], ic));
                    }
                    tp[mi * 2 + h] = t;
                }
#pragma unroll
            for (int mi = 0; mi < 2; mi++)
#pragma unroll
                for (int nj = 0; nj < 2; nj++)
#pragma unroll
                    for (int e = 0; e < 4; e++) acc[mi][nj][e] = 0.f;
        }
    }

    // tail: epilogue G2 of last chunk
    {
#pragma unroll
        for (int mi = 2; mi < 4; mi++)
#pragma unroll
            for (int h = 0; h < 2; h++) {
                T3 t = tp[mi * 2 + h];
#pragma unroll
                for (int j = 0; j < 4; j++) {
                    uint32_t ic = (uint32_t)(1023 - ((NCHUNKS - 1) * NCH + npos[j]));
                    t3p(t, pk(acc[mi][(j >> 1)][h * 2 + (j & 1)], ic));
                }
                tp[mi * 2 + h] = t;
            }
    }

    // intra-warp merge (lanes sharing each row differ in bits 0-1)
#pragma unroll
    for (int r = 0; r < 8; r++) {
#pragma unroll
        for (int d = 1; d <= 2; d <<= 1) {
            float o1 = __shfl_xor_sync(0xffffffffu, tp[r].v1, d);
            float o2 = __shfl_xor_sync(0xffffffffu, tp[r].v2, d);
            float o3 = __shfl_xor_sync(0xffffffffu, tp[r].v3, d);
            t3p(tp[r], o1); t3p(tp[r], o2); t3p(tp[r], o3);
        }
    }

    // cross-warp (wn) merge via smem
    __syncthreads();
    float* rv1 = (float*)(smem + SM_A);
    float* rv2 = (float*)(smem + SM_A + 2048);
    float* rv3 = (float*)(smem + SM_A + 4096);
    if ((lane & 3) == 0) {
#pragma unroll
        for (int mi = 0; mi < 4; mi++)
#pragma unroll
            for (int h = 0; h < 2; h++) {
                int r = mi * 2 + h;
                int row = wm * 64 + mi * 16 + h * 8 + (lane >> 2);
                rv1[row * 4 + wn] = tp[r].v1;
                rv2[row * 4 + wn] = tp[r].v2;
                rv3[row * 4 + wn] = tp[r].v3;
            }
    }
    __syncthreads();

    __shared__ int s_cnt, s_base, s_pcnt, s_pbase;
    __shared__ int s_ids[MQ];
    if (tid == 0) { s_cnt = 0; s_pcnt = 0; }
    __syncthreads();
    int slot = -1, pslot = -1;
    int pi1 = 0, pi2 = 0;
    if (tid < MQ) {
        T3 t;
        t.v1 = rv1[tid * 4]; t.v2 = rv2[tid * 4]; t.v3 = rv3[tid * 4];
#pragma unroll
        for (int w = 1; w < 4; w++) {
            t3p(t, rv1[tid * 4 + w]);
            t3p(t, rv2[tid * 4 + w]);
            t3p(t, rv3[tid * 4 + w]);
        }
        int id = dec_idx(t.v1);
        s_ids[tid] = id;
        g_ids[qbase + tid] = id;
        if (t.v1 - t.v3 < DELTA) {
            slot = atomicAdd(&s_cnt, 1);
        } else if (t.v1 - t.v2 < DELTA) {
            pslot = atomicAdd(&s_pcnt, 1);
            pi1 = id; pi2 = dec_idx(t.v2);
        }
    }
    __syncthreads();
    if (tid == 0) {
        if (s_cnt > 0)  s_base  = atomicAdd(&g_nrescue, s_cnt);
        if (s_pcnt > 0) s_pbase = atomicAdd(&g_npair, s_pcnt);
    }
    __syncthreads();
    if (slot >= 0)  g_rescue[s_base + slot] = qbase + tid;
    if (pslot >= 0) g_pair[s_pbase + pslot] = make_int2(qbase + tid, pi1 | (pi2 << 16));

    // fused output write (pair/rescue rows are overwritten by later kernels)
    for (int i = tid; i < MQ * 16; i += 256) {
        int m = i >> 4, part = i & 15;
        int id = s_ids[m];
        float4 v = __ldg((const float4*)(cb + (size_t)id * DIM) + part);
        *(float4*)(out_codes + (size_t)(qbase + m) * DIM + part * 4) = v;
    }
    if (write_ids && tid < MQ)
        out_ids[qbase + tid] = (float)s_ids[tid];
}

// ---------------------------------------------------------------------------
// pair rescore: exact fp32 on two candidates; writes ids + codes.
// ---------------------------------------------------------------------------
__global__ void pair_kernel(const float* __restrict__ codes,
                            const float* __restrict__ cb,
                            float* __restrict__ out_codes,
                            float* __restrict__ out_ids, int write_ids) {
    int np = g_npair;
    for (int i = blockIdx.x * blockDim.x + threadIdx.x; i < np;
         i += gridDim.x * blockDim.x) {
        int2 e = g_pair[i];
        int q = e.x, i1 = e.y & 0xFFFF, i2 = e.y >> 16;
        const float4* xr = (const float4*)(codes + (size_t)q * DIM);
        const float4* c1 = (const float4*)(cb + (size_t)i1 * DIM);
        const float4* c2 = (const float4*)(cb + (size_t)i2 * DIM);
        float s1 = 0.f, s2 = 0.f;
#pragma unroll
        for (int kq = 0; kq < 16; kq++) {
            float4 x = xr[kq], a = __ldg(&c1[kq]), b = __ldg(&c2[kq]);
            s1 = fmaf(x.x, a.x, s1); s1 = fmaf(x.y, a.y, s1);
            s1 = fmaf(x.z, a.z, s1); s1 = fmaf(x.w, a.w, s1);
            s2 = fmaf(x.x, b.x, s2); s2 = fmaf(x.y, b.y, s2);
            s2 = fmaf(x.z, b.z, s2); s2 = fmaf(x.w, b.w, s2);
        }
        s1 -= g_hcsq[i1]; s2 -= g_hcsq[i2];
        int best = ((s2 > s1) || (s2 == s1 && i2 < i1)) ? i2 : i1;
        g_ids[q] = best;
        if (write_ids) out_ids[q] = (float)best;
        const float4* cr = (const float4*)(cb + (size_t)best * DIM);
#pragma unroll
        for (int kq = 0; kq < 16; kq++)
            *(float4*)(out_codes + (size_t)q * DIM + kq * 4) = __ldg(&cr[kq]);
    }
}

// ---------------------------------------------------------------------------
// full rescue, split 4 ways + merge (writes ids + codes).
// ---------------------------------------------------------------------------
#define QB 8
__global__ void rescue_part(const float* __restrict__ codes,
                            const float* __restrict__ cb) {
    __shared__ float sx[QB][DIM];
    __shared__ float sv[QB][256];
    int nres = g_nrescue;
    int ngb = ((nres + QB - 1) / QB) * 4;
    for (int gb = blockIdx.x; gb < ngb; gb += gridDim.x) {
        int grp = gb >> 2, quar = gb & 3;
        int base = grp * QB;
        int cnt = min(QB, nres - base);
        __syncthreads();
        for (int i = threadIdx.x; i < cnt * 16; i += 256) {
            int q = i >> 4, kq = i & 15;
            ((float4*)sx[q])[kq] =
                ((const float4*)(codes + (size_t)g_rescue[base + q] * DIM))[kq];
        }
        __syncthreads();
        int n = quar * 256 + threadIdx.x;
        const float4* cr = (const float4*)(cb + (size_t)n * DIM);
        float dot[QB];
#pragma unroll
        for (int q = 0; q < QB; q++) dot[q] = 0.f;
#pragma unroll
        for (int kq = 0; kq < 16; kq++) {
            float4 c4 = __ldg(&cr[kq]);
#pragma unroll
            for (int q = 0; q < QB; q++) {
                dot[q] = fmaf(sx[q][kq * 4 + 0], c4.x, dot[q]);
                dot[q] = fmaf(sx[q][kq * 4 + 1], c4.y, dot[q]);
                dot[q] = fmaf(sx[q][kq * 4 + 2], c4.z, dot[q]);
                dot[q] = fmaf(sx[q][kq * 4 + 3], c4.w, dot[q]);
            }
        }
        float hcv = g_hcsq[n];
#pragma unroll
        for (int q = 0; q < QB; q++) sv[q][threadIdx.x] = dot[q] - hcv;
        __syncthreads();
        int w = threadIdx.x >> 5, lane = threadIdx.x & 31;
        if (w < cnt) {
            float v = sv[w][lane]; int ix = lane;
            for (int t = lane + 32; t < 256; t += 32) {
                float ov = sv[w][t];
                if (ov > v || (ov == v && t < ix)) { v = ov; ix = t; }
            }
#pragma unroll
            for (int d = 16; d > 0; d >>= 1) {
                float ov = __shfl_down_sync(0xffffffffu, v, d);
                int   oi = __shfl_down_sync(0xffffffffu, ix, d);
                if (ov > v || (ov == v && oi < ix)) { v = ov; ix = oi; }
            }
            if (lane == 0) {
                g_pv[(base + w) * 4 + quar] = v;
                g_pi[(base + w) * 4 + quar] = quar * 256 + ix;
            }
        }
        __syncthreads();
    }
}

__global__ void rescue_merge(const float* __restrict__ cb,
                             float* __restrict__ out_codes,
                             float* __restrict__ out_ids, int write_ids) {
    for (int i = blockIdx.x * blockDim.x + threadIdx.x; i < g_nrescue;
         i += gridDim.x * blockDim.x) {
        float bv = g_pv[i * 4]; int bi = g_pi[i * 4];
#pragma unroll
        for (int q = 1; q < 4; q++) {
            float v = g_pv[i * 4 + q]; int ix = g_pi[i * 4 + q];
            if (v > bv || (v == bv && ix < bi)) { bv = v; bi = ix; }
        }
        int q = g_rescue[i];
        g_ids[q] = bi;
        if (write_ids) out_ids[q] = (float)bi;
        const float4* cr = (const float4*)(cb + (size_t)bi * DIM);
#pragma unroll
        for (int kq = 0; kq < 16; kq++)
            *(float4*)(out_codes + (size_t)q * DIM + kq * 4) = __ldg(&cr[kq]);
    }
}

// ---------------------------------------------------------------------------
extern "C" void kernel_launch(void* const* d_in, const int* in_sizes, int n_in,
                              void* d_out, int out_size) {
    const float* codes = (const float*)d_in[0];
    const float* cb    = (const float*)d_in[1];
    float* out = (float*)d_out;

    int nq = in_sizes[0] / DIM;
    if (nq > MAX_Q) nq = MAX_Q;

    int write_ids = (out_size >= nq * DIM + nq) ? 1 : 0;
    float* out_ids = out + (size_t)nq * DIM;

    prep_kernel<<<(NT * 16 + 255) / 256, 256>>>(cb);
    vq_mma_kernel<<<nq / MQ, 256, SMEM_TOTAL>>>(codes, cb, out, out_ids, write_ids);
    pair_kernel<<<256, 256>>>(codes, cb, out, out_ids, write_ids);
    rescue_part<<<1024, 256>>>(codes, cb);
    rescue_merge<<<64, 256>>>(cb, out, out_ids, write_ids);
}

// round 13
// speedup vs baseline: 4.1703x; 1.0643x over previous
#include <cuda_runtime.h>
#include <cuda_fp16.h>
#include <stdint.h>

#define DIM 64
#define NT 1024
#define MQ 128
#define NCH 64
#define NCHUNKS (NT / NCH)      // 16
#define MAX_Q (64 * 4096)
// 1-pass fp16 pairwise err std ~0.6e-3 + mantissa-stomp (<=2.6e-3 worst) -> 0.01
#define DELTA 0.010f

__device__ int    g_ids[MAX_Q];
__device__ float  g_hcsq[NT];
__device__ __half g_Bh[NT * DIM];     // 16 chunk tiles of 64 rows x 128B
__device__ int    g_nrescue;
__device__ int    g_rescue[MAX_Q];
__device__ int    g_npair;
__device__ int2   g_pair[MAX_Q];
__device__ float  g_pv[MAX_Q * 8];
__device__ int    g_pi[MAX_Q * 8];

// ---------------- helpers ----------------
__device__ __forceinline__ uint32_t smem_u32(const void* p) {
    uint32_t a;
    asm("{ .reg .u64 t; cvta.to.shared.u64 t, %1; cvt.u32.u64 %0, t; }"
        : "=r"(a) : "l"(p));
    return a;
}
__device__ __forceinline__ void ldm_x4(uint32_t* r, uint32_t addr) {
    asm volatile("ldmatrix.sync.aligned.m8n8.x4.shared.b16 {%0,%1,%2,%3}, [%4];"
                 : "=r"(r[0]), "=r"(r[1]), "=r"(r[2]), "=r"(r[3]) : "r"(addr));
}
__device__ __forceinline__ void mma_f16(float* c, const uint32_t* a,
                                        uint32_t b0, uint32_t b1) {
    asm volatile(
        "mma.sync.aligned.m16n8k16.row.col.f32.f16.f16.f32 "
        "{%0,%1,%2,%3}, {%4,%5,%6,%7}, {%8,%9}, {%0,%1,%2,%3};"
        : "+f"(c[0]), "+f"(c[1]), "+f"(c[2]), "+f"(c[3])
        : "r"(a[0]), "r"(a[1]), "r"(a[2]), "r"(a[3]), "r"(b0), "r"(b1));
}
__device__ __forceinline__ void cpa16(uint32_t dst, const void* src) {
    asm volatile("cp.async.cg.shared.global [%0], [%1], 16;" :: "r"(dst), "l"(src));
}
#define CPA_COMMIT() asm volatile("cp.async.commit_group;" ::: "memory")
#define CPA_WAIT0()  asm volatile("cp.async.wait_group 0;" ::: "memory")

__device__ __forceinline__ uint32_t sw_off(int row, int chunk) {
    return (uint32_t)row * 128u + (uint32_t)((chunk ^ (row & 7)) << 4);
}

// packed top-3: value's low 10 mantissa bits hold (1023 - n). Pure FMNMX.
struct T3 { float v1, v2, v3; };
__device__ __forceinline__ void t3p(T3& t, float s) {
    float lo  = fminf(s, t.v1);
    t.v1 = fmaxf(s, t.v1);
    float lo2 = fminf(lo, t.v2);
    t.v2 = fmaxf(lo, t.v2);
    t.v3 = fmaxf(lo2, t.v3);
}
__device__ __forceinline__ float pk(float v, uint32_t idxc) {
    return __uint_as_float((__float_as_uint(v) & 0xFFFFFC00u) | idxc);
}
__device__ __forceinline__ int dec_idx(float v) {
    return 1023 - (int)(__float_as_uint(v) & 1023u);
}

// ---------------- smem map (dynamic, 32768 B -> 2 CTAs/SM) ----------------
#define SM_A 0            // 16 KB query tile; reused for merge arrays
#define SM_B 16384        // 2 stages x 8 KB
#define SMEM_TOTAL 32768

// ---------------------------------------------------------------------------
__global__ void prep_kernel(const float* __restrict__ cb) {
    int t = blockIdx.x * blockDim.x + threadIdx.x;
    if (t == 0) { g_nrescue = 0; g_npair = 0; }
    if (t >= NT * 16) return;
    int n = t >> 4, kq = t & 15;
    float4 v = *(const float4*)(cb + (size_t)n * DIM + kq * 4);
    __half h[4];
    h[0] = __float2half_rn(v.x); h[1] = __float2half_rn(v.y);
    h[2] = __float2half_rn(v.z); h[3] = __float2half_rn(v.w);
    int ch = n >> 6, ln = n & 63;
    uint32_t off = (uint32_t)ch * 8192u + sw_off(ln, kq >> 1) + (kq & 1) * 8;
    *(uint2*)((char*)g_Bh + off) = *(uint2*)h;
    if (kq == 0) {
        const float4* row = (const float4*)(cb + (size_t)n * DIM);
        float s = 0.f;
#pragma unroll
        for (int i = 0; i < 16; i++) {
            float4 w = row[i];
            s += w.x * w.x + w.y * w.y + w.z * w.z + w.w * w.w;
        }
        g_hcsq[n] = 0.5f * s;
    }
}

// ---------------------------------------------------------------------------
// main: 1-pass fp16 mma.sync + packed top-3; mi-split overlap; NCH=64;
// occupancy 2; fused output write.
// ---------------------------------------------------------------------------
__global__ void __launch_bounds__(256, 2)
vq_mma_kernel(const float* __restrict__ codes, const float* __restrict__ cb,
              float* __restrict__ out_codes, float* __restrict__ out_ids,
              int write_ids) {
    extern __shared__ char smem[];
    const uint32_t sb = smem_u32(smem);
    const int tid  = threadIdx.x;
    const int wid  = tid >> 5, lane = tid & 31;
    const int wm   = wid >> 2;          // m offset 0/64
    const int wn   = wid & 3;           // n offset 0/16/32/48
    const int qbase = blockIdx.x * MQ;

    for (int i = tid; i < 512; i += 256)
        cpa16(sb + SM_B + i * 16, (const char*)g_Bh + i * 16);
    CPA_COMMIT();

    for (int i = tid; i < MQ * 16; i += 256) {
        int m = i >> 4, kq = i & 15;
        float4 v = *(const float4*)(codes + (size_t)(qbase + m) * DIM + kq * 4);
        __half h[4];
        h[0] = __float2half_rn(v.x); h[1] = __float2half_rn(v.y);
        h[2] = __float2half_rn(v.z); h[3] = __float2half_rn(v.w);
        uint32_t off = sw_off(m, kq >> 1) + (kq & 1) * 8;
        *(uint2*)(smem + SM_A + off) = *(uint2*)h;
    }

    T3 tp[8];
#pragma unroll
    for (int r = 0; r < 8; r++) { tp[r].v1 = -1e30f; tp[r].v2 = -1e30f; tp[r].v3 = -1e30f; }

    float acc[4][2][4];
#pragma unroll
    for (int mi = 0; mi < 4; mi++)
#pragma unroll
        for (int nj = 0; nj < 2; nj++)
#pragma unroll
            for (int e = 0; e < 4; e++) acc[mi][nj][e] = 0.f;

    const int nlo = (lane & 3) * 2;
    int npos[4];
#pragma unroll
    for (int nj = 0; nj < 2; nj++)
#pragma unroll
        for (int p = 0; p < 2; p++)
            npos[nj * 2 + p] = wn * 16 + nj * 8 + nlo + p;

    for (int c = 0; c < NCHUNKS; c++) {
        const int st = c & 1;
        CPA_WAIT0();
        __syncthreads();

        if (c + 1 < NCHUNKS) {
            const char* bh = (const char*)g_Bh + (size_t)(c + 1) * 8192;
            uint32_t dst = sb + SM_B + (st ^ 1) * 8192;
            for (int i = tid; i < 512; i += 256)
                cpa16(dst + i * 16, bh + i * 16);
            CPA_COMMIT();
        }

        const uint32_t aBase = sb + SM_A;
        const uint32_t bBase = sb + SM_B + st * 8192;
        const bool cg = (c > 0);

        uint32_t bfr[4][4];
        // ---------- block X: mma G1 (mi 0-1) + epilogue G2(prev) ----------
        {
#pragma unroll
            for (int ks = 0; ks < 4; ks++) {
                uint32_t a0[4], a1[4];
                {
                    int ra = wm * 64 + 0 * 16 + (lane & 15);
                    ldm_x4(a0, aBase + sw_off(ra, ks * 2 + (lane >> 4)));
                    ra = wm * 64 + 1 * 16 + (lane & 15);
                    ldm_x4(a1, aBase + sw_off(ra, ks * 2 + (lane >> 4)));
                }
                {
                    int rb = wn * 16 + (lane & 7) + ((lane & 16) ? 8 : 0);
                    ldm_x4(bfr[ks], bBase + sw_off(rb, ks * 2 + ((lane >> 3) & 1)));
                }
#pragma unroll
                for (int nj = 0; nj < 2; nj++) {
                    uint32_t b0 = bfr[ks][nj * 2], b1 = bfr[ks][nj * 2 + 1];
                    mma_f16(acc[0][nj], a0, b0, b1);
                    mma_f16(acc[1][nj], a1, b0, b1);
                }
            }
#pragma unroll
            for (int mi = 2; mi < 4; mi++)
#pragma unroll
                for (int h = 0; h < 2; h++) {
                    T3 t = tp[mi * 2 + h];
#pragma unroll
                    for (int j = 0; j < 4; j++) {
                        uint32_t ic = (uint32_t)(1023 - ((c - 1) * NCH + npos[j]));
                        float s = cg ? pk(acc[mi][(j >> 1)][h * 2 + (j & 1)], ic)
                                     : -1e30f;
                        t3p(t, s);
                    }
                    tp[mi * 2 + h] = t;
                }
#pragma unroll
            for (int mi = 2; mi < 4; mi++)
#pragma unroll
                for (int nj = 0; nj < 2; nj++)
#pragma unroll
                    for (int e = 0; e < 4; e++) acc[mi][nj][e] = 0.f;
        }

        // ---------- block Y: mma G2 (mi 2-3) + epilogue G1(current) ----------
        {
#pragma unroll
            for (int ks = 0; ks < 4; ks++) {
                uint32_t a2[4], a3[4];
                {
                    int ra = wm * 64 + 2 * 16 + (lane & 15);
                    ldm_x4(a2, aBase + sw_off(ra, ks * 2 + (lane >> 4)));
                    ra = wm * 64 + 3 * 16 + (lane & 15);
                    ldm_x4(a3, aBase + sw_off(ra, ks * 2 + (lane >> 4)));
                }
#pragma unroll
                for (int nj = 0; nj < 2; nj++) {
                    uint32_t b0 = bfr[ks][nj * 2], b1 = bfr[ks][nj * 2 + 1];
                    mma_f16(acc[2][nj], a2, b0, b1);
                    mma_f16(acc[3][nj], a3, b0, b1);
                }
            }
#pragma unroll
            for (int mi = 0; mi < 2; mi++)
#pragma unroll
                for (int h = 0; h < 2; h++) {
                    T3 t = tp[mi * 2 + h];
#pragma unroll
                    for (int j = 0; j < 4; j++) {
                        uint32_t ic = (uint32_t)(1023 - (c * NCH + npos[j]));
                        t3p(t, pk(acc[mi][(j >> 1)][h * 2 + (j & 1)], ic));
                    }
                    tp[mi * 2 + h] = t;
                }
#pragma unroll
            for (int mi = 0; mi < 2; mi++)
#pragma unroll
                for (int nj = 0; nj < 2; nj++)
#pragma unroll
                    for (int e = 0; e < 4; e++) acc[mi][nj][e] = 0.f;
        }
    }

    // tail: epilogue G2 of last chunk
    {
#pragma unroll
        for (int mi = 2; mi < 4; mi++)
#pragma unroll
            for (int h = 0; h < 2; h++) {
                T3 t = tp[mi * 2 + h];
#pragma unroll
                for (int j = 0; j < 4; j++) {
                    uint32_t ic = (uint32_t)(1023 - ((NCHUNKS - 1) * NCH + npos[j]));
                    t3p(t, pk(acc[mi][(j >> 1)][h * 2 + (j & 1)], ic));
                }
                tp[mi * 2 + h] = t;
            }
    }

    // intra-warp merge (lanes sharing each row differ in bits 0-1)
#pragma unroll
    for (int r = 0; r < 8; r++) {
#pragma unroll
        for (int d = 1; d <= 2; d <<= 1) {
            float o1 = __shfl_xor_sync(0xffffffffu, tp[r].v1, d);
            float o2 = __shfl_xor_sync(0xffffffffu, tp[r].v2, d);
            float o3 = __shfl_xor_sync(0xffffffffu, tp[r].v3, d);
            t3p(tp[r], o1); t3p(tp[r], o2); t3p(tp[r], o3);
        }
    }

    // cross-warp (wn) merge via smem
    __syncthreads();
    float* rv1 = (float*)(smem + SM_A);
    float* rv2 = (float*)(smem + SM_A + 2048);
    float* rv3 = (float*)(smem + SM_A + 4096);
    if ((lane & 3) == 0) {
#pragma unroll
        for (int mi = 0; mi < 4; mi++)
#pragma unroll
            for (int h = 0; h < 2; h++) {
                int r = mi * 2 + h;
                int row = wm * 64 + mi * 16 + h * 8 + (lane >> 2);
                rv1[row * 4 + wn] = tp[r].v1;
                rv2[row * 4 + wn] = tp[r].v2;
                rv3[row * 4 + wn] = tp[r].v3;
            }
    }
    __syncthreads();

    __shared__ int s_cnt, s_base, s_pcnt, s_pbase;
    __shared__ int s_ids[MQ];
    if (tid == 0) { s_cnt = 0; s_pcnt = 0; }
    __syncthreads();
    int slot = -1, pslot = -1;
    int pi1 = 0, pi2 = 0;
    if (tid < MQ) {
        T3 t;
        t.v1 = rv1[tid * 4]; t.v2 = rv2[tid * 4]; t.v3 = rv3[tid * 4];
#pragma unroll
        for (int w = 1; w < 4; w++) {
            t3p(t, rv1[tid * 4 + w]);
            t3p(t, rv2[tid * 4 + w]);
            t3p(t, rv3[tid * 4 + w]);
        }
        int id = dec_idx(t.v1);
        s_ids[tid] = id;
        g_ids[qbase + tid] = id;
        if (t.v1 - t.v3 < DELTA) {
            slot = atomicAdd(&s_cnt, 1);
        } else if (t.v1 - t.v2 < DELTA) {
            pslot = atomicAdd(&s_pcnt, 1);
            pi1 = id; pi2 = dec_idx(t.v2);
        }
    }
    __syncthreads();
    if (tid == 0) {
        if (s_cnt > 0)  s_base  = atomicAdd(&g_nrescue, s_cnt);
        if (s_pcnt > 0) s_pbase = atomicAdd(&g_npair, s_pcnt);
    }
    __syncthreads();
    if (slot >= 0)  g_rescue[s_base + slot] = qbase + tid;
    if (pslot >= 0) g_pair[s_pbase + pslot] = make_int2(qbase + tid, pi1 | (pi2 << 16));

    // fused output write (pair/rescue rows overwritten by later kernels)
    for (int i = tid; i < MQ * 16; i += 256) {
        int m = i >> 4, part = i & 15;
        int id = s_ids[m];
        float4 v = __ldg((const float4*)(cb + (size_t)id * DIM) + part);
        *(float4*)(out_codes + (size_t)(qbase + m) * DIM + part * 4) = v;
    }
    if (write_ids && tid < MQ)
        out_ids[qbase + tid] = (float)s_ids[tid];
}

// ---------------------------------------------------------------------------
// pair rescore: exact fp32 on two candidates; writes ids + codes.
// ---------------------------------------------------------------------------
__global__ void pair_kernel(const float* __restrict__ codes,
                            const float* __restrict__ cb,
                            float* __restrict__ out_codes,
                            float* __restrict__ out_ids, int write_ids) {
    int np = g_npair;
    for (int i = blockIdx.x * blockDim.x + threadIdx.x; i < np;
         i += gridDim.x * blockDim.x) {
        int2 e = g_pair[i];
        int q = e.x, i1 = e.y & 0xFFFF, i2 = e.y >> 16;
        const float4* xr = (const float4*)(codes + (size_t)q * DIM);
        const float4* c1 = (const float4*)(cb + (size_t)i1 * DIM);
        const float4* c2 = (const float4*)(cb + (size_t)i2 * DIM);
        float s1 = 0.f, s2 = 0.f;
#pragma unroll
        for (int kq = 0; kq < 16; kq++) {
            float4 x = xr[kq], a = __ldg(&c1[kq]), b = __ldg(&c2[kq]);
            s1 = fmaf(x.x, a.x, s1); s1 = fmaf(x.y, a.y, s1);
            s1 = fmaf(x.z, a.z, s1); s1 = fmaf(x.w, a.w, s1);
            s2 = fmaf(x.x, b.x, s2); s2 = fmaf(x.y, b.y, s2);
            s2 = fmaf(x.z, b.z, s2); s2 = fmaf(x.w, b.w, s2);
        }
        s1 -= g_hcsq[i1]; s2 -= g_hcsq[i2];
        int best = ((s2 > s1) || (s2 == s1 && i2 < i1)) ? i2 : i1;
        g_ids[q] = best;
        if (write_ids) out_ids[q] = (float)best;
        const float4* cr = (const float4*)(cb + (size_t)best * DIM);
#pragma unroll
        for (int kq = 0; kq < 16; kq++)
            *(float4*)(out_codes + (size_t)q * DIM + kq * 4) = __ldg(&cr[kq]);
    }
}

// ---------------------------------------------------------------------------
// full rescue, split 8 ways + merge (writes ids + codes).
// ---------------------------------------------------------------------------
#define QB 8
__global__ void rescue_part(const float* __restrict__ codes,
                            const float* __restrict__ cb) {
    __shared__ float sx[QB][DIM];
    __shared__ float sv[QB][128];
    int nres = g_nrescue;
    int ngb = ((nres + QB - 1) / QB) * 8;
    for (int gb = blockIdx.x; gb < ngb; gb += gridDim.x) {
        int grp = gb >> 3, oct = gb & 7;
        int base = grp * QB;
        int cnt = min(QB, nres - base);
        __syncthreads();
        for (int i = threadIdx.x; i < cnt * 16; i += 128) {
            int q = i >> 4, kq = i & 15;
            ((float4*)sx[q])[kq] =
                ((const float4*)(codes + (size_t)g_rescue[base + q] * DIM))[kq];
        }
        __syncthreads();
        int n = oct * 128 + threadIdx.x;
        const float4* cr = (const float4*)(cb + (size_t)n * DIM);
        float dot[QB];
#pragma unroll
        for (int q = 0; q < QB; q++) dot[q] = 0.f;
#pragma unroll
        for (int kq = 0; kq < 16; kq++) {
            float4 c4 = __ldg(&cr[kq]);
#pragma unroll
            for (int q = 0; q < QB; q++) {
                dot[q] = fmaf(sx[q][kq * 4 + 0], c4.x, dot[q]);
                dot[q] = fmaf(sx[q][kq * 4 + 1], c4.y, dot[q]);
                dot[q] = fmaf(sx[q][kq * 4 + 2], c4.z, dot[q]);
                dot[q] = fmaf(sx[q][kq * 4 + 3], c4.w, dot[q]);
            }
        }
        float hcv = g_hcsq[n];
#pragma unroll
        for (int q = 0; q < QB; q++) sv[q][threadIdx.x] = dot[q] - hcv;
        __syncthreads();
        int w = threadIdx.x >> 5, lane = threadIdx.x & 31;
        if (w < 4) {
#pragma unroll
            for (int qq = 0; qq < 2; qq++) {
                int q = w * 2 + qq;
                if (q < cnt) {
                    float v = sv[q][lane]; int ix = lane;
                    float v2 = sv[q][lane + 32]; int ix2 = lane + 32;
                    float v3 = sv[q][lane + 64]; int ix3 = lane + 64;
                    float v4 = sv[q][lane + 96]; int ix4 = lane + 96;
                    if (v2 > v || (v2 == v && ix2 < ix)) { v = v2; ix = ix2; }
                    if (v3 > v || (v3 == v && ix3 < ix)) { v = v3; ix = ix3; }
                    if (v4 > v || (v4 == v && ix4 < ix)) { v = v4; ix = ix4; }
#pragma unroll
                    for (int d = 16; d > 0; d >>= 1) {
                        float ov = __shfl_down_sync(0xffffffffu, v, d);
                        int   oi = __shfl_down_sync(0xffffffffu, ix, d);
                        if (ov > v || (ov == v && oi < ix)) { v = ov; ix = oi; }
                    }
                    if (lane == 0) {
                        g_pv[(base + q) * 8 + oct] = v;
                        g_pi[(base + q) * 8 + oct] = oct * 128 + ix;
                    }
                }
            }
        }
        __syncthreads();
    }
}

__global__ void rescue_merge(const float* __restrict__ cb,
                             float* __restrict__ out_codes,
                             float* __restrict__ out_ids, int write_ids) {
    for (int i = blockIdx.x * blockDim.x + threadIdx.x; i < g_nrescue;
         i += gridDim.x * blockDim.x) {
        float bv = g_pv[i * 8]; int bi = g_pi[i * 8];
#pragma unroll
        for (int q = 1; q < 8; q++) {
            float v = g_pv[i * 8 + q]; int ix = g_pi[i * 8 + q];
            if (v > bv || (v == bv && ix < bi)) { bv = v; bi = ix; }
        }
        int q = g_rescue[i];
        g_ids[q] = bi;
        if (write_ids) out_ids[q] = (float)bi;
        const float4* cr = (const float4*)(cb + (size_t)bi * DIM);
#pragma unroll
        for (int kq = 0; kq < 16; kq++)
            *(float4*)(out_codes + (size_t)q * DIM + kq * 4) = __ldg(&cr[kq]);
    }
}

// ---------------------------------------------------------------------------
extern "C" void kernel_launch(void* const* d_in, const int* in_sizes, int n_in,
                              void* d_out, int out_size) {
    const float* codes = (const float*)d_in[0];
    const float* cb    = (const float*)d_in[1];
    float* out = (float*)d_out;

    int nq = in_sizes[0] / DIM;
    if (nq > MAX_Q) nq = MAX_Q;

    int write_ids = (out_size >= nq * DIM + nq) ? 1 : 0;
    float* out_ids = out + (size_t)nq * DIM;

    prep_kernel<<<(NT * 16 + 255) / 256, 256>>>(cb);
    vq_mma_kernel<<<nq / MQ, 256, SMEM_TOTAL>>>(codes, cb, out, out_ids, write_ids);
    pair_kernel<<<256, 256>>>(codes, cb, out, out_ids, write_ids);
    rescue_part<<<1024, 128>>>(codes, cb);
    rescue_merge<<<64, 256>>>(cb, out, out_ids, write_ids);
}

// round 15
// speedup vs baseline: 4.3548x; 1.0442x over previous
#include <cuda_runtime.h>
#include <cuda_fp16.h>
#include <stdint.h>

#define DIM 64
#define NT 1024
#define MQ 128
#define NCH 64
#define NCHUNKS (NT / NCH)      // 16
#define MAX_Q (64 * 4096)
// 1-pass fp16 pairwise err std ~0.6e-3 + mantissa-stomp (<=2.6e-3 worst) -> 0.01
#define DELTA 0.010f

__device__ int    g_ids[MAX_Q];
__device__ float  g_hcsq[NT];
__device__ __half g_Bh[NT * DIM];     // 16 chunk tiles of 64 rows x 128B
__device__ int    g_nrescue;
__device__ int    g_rescue[MAX_Q];
__device__ int    g_npair;
__device__ int2   g_pair[MAX_Q];
__device__ float  g_pv[MAX_Q * 8];
__device__ int    g_pi[MAX_Q * 8];

// ---------------- helpers ----------------
__device__ __forceinline__ uint32_t smem_u32(const void* p) {
    uint32_t a;
    asm("{ .reg .u64 t; cvta.to.shared.u64 t, %1; cvt.u32.u64 %0, t; }"
        : "=r"(a) : "l"(p));
    return a;
}
__device__ __forceinline__ void ldm_x4(uint32_t* r, uint32_t addr) {
    asm volatile("ldmatrix.sync.aligned.m8n8.x4.shared.b16 {%0,%1,%2,%3}, [%4];"
                 : "=r"(r[0]), "=r"(r[1]), "=r"(r[2]), "=r"(r[3]) : "r"(addr));
}
__device__ __forceinline__ void mma_f16(float* c, const uint32_t* a,
                                        uint32_t b0, uint32_t b1) {
    asm volatile(
        "mma.sync.aligned.m16n8k16.row.col.f32.f16.f16.f32 "
        "{%0,%1,%2,%3}, {%4,%5,%6,%7}, {%8,%9}, {%0,%1,%2,%3};"
        : "+f"(c[0]), "+f"(c[1]), "+f"(c[2]), "+f"(c[3])
        : "r"(a[0]), "r"(a[1]), "r"(a[2]), "r"(a[3]), "r"(b0), "r"(b1));
}
// first-ks variant: C operand = 0 (kills per-chunk acc reinit movs)
__device__ __forceinline__ void mma_f16_z(float* c, const uint32_t* a,
                                          uint32_t b0, uint32_t b1) {
    asm volatile(
        "mma.sync.aligned.m16n8k16.row.col.f32.f16.f16.f32 "
        "{%0,%1,%2,%3}, {%4,%5,%6,%7}, {%8,%9}, {%10,%10,%10,%10};"
        : "=f"(c[0]), "=f"(c[1]), "=f"(c[2]), "=f"(c[3])
        : "r"(a[0]), "r"(a[1]), "r"(a[2]), "r"(a[3]), "r"(b0), "r"(b1),
          "f"(0.f));
}
__device__ __forceinline__ void cpa16(uint32_t dst, const void* src) {
    asm volatile("cp.async.cg.shared.global [%0], [%1], 16;" :: "r"(dst), "l"(src));
}
#define CPA_COMMIT() asm volatile("cp.async.commit_group;" ::: "memory")
#define CPA_WAIT0()  asm volatile("cp.async.wait_group 0;" ::: "memory")

__device__ __forceinline__ uint32_t sw_off(int row, int chunk) {
    return (uint32_t)row * 128u + (uint32_t)((chunk ^ (row & 7)) << 4);
}

// packed top-3: value's low 10 mantissa bits hold (1023 - n). Pure FMNMX.
struct T3 { float v1, v2, v3; };
__device__ __forceinline__ void t3p(T3& t, float s) {
    float lo  = fminf(s, t.v1);
    t.v1 = fmaxf(s, t.v1);
    float lo2 = fminf(lo, t.v2);
    t.v2 = fmaxf(lo, t.v2);
    t.v3 = fmaxf(lo2, t.v3);
}
__device__ __forceinline__ float pk(float v, uint32_t idxc) {
    return __uint_as_float((__float_as_uint(v) & 0xFFFFFC00u) | idxc);
}
__device__ __forceinline__ int dec_idx(float v) {
    return 1023 - (int)(__float_as_uint(v) & 1023u);
}

// ---------------- smem map (dynamic, 32768 B -> 2 CTAs/SM) ----------------
#define SM_A 0            // 16 KB query tile; reused for merge arrays
#define SM_B 16384        // 2 stages x 8 KB
#define SMEM_TOTAL 32768

// ---------------------------------------------------------------------------
__global__ void prep_kernel(const float* __restrict__ cb) {
    int t = blockIdx.x * blockDim.x + threadIdx.x;
    if (t == 0) { g_nrescue = 0; g_npair = 0; }
    if (t >= NT * 16) return;
    int n = t >> 4, kq = t & 15;
    float4 v = *(const float4*)(cb + (size_t)n * DIM + kq * 4);
    __half h[4];
    h[0] = __float2half_rn(v.x); h[1] = __float2half_rn(v.y);
    h[2] = __float2half_rn(v.z); h[3] = __float2half_rn(v.w);
    int ch = n >> 6, ln = n & 63;
    uint32_t off = (uint32_t)ch * 8192u + sw_off(ln, kq >> 1) + (kq & 1) * 8;
    *(uint2*)((char*)g_Bh + off) = *(uint2*)h;
    if (kq == 0) {
        const float4* row = (const float4*)(cb + (size_t)n * DIM);
        float s = 0.f;
#pragma unroll
        for (int i = 0; i < 16; i++) {
            float4 w = row[i];
            s += w.x * w.x + w.y * w.y + w.z * w.z + w.w * w.w;
        }
        g_hcsq[n] = 0.5f * s;
    }
}

// ---------------------------------------------------------------------------
// main: 1-pass fp16 mma.sync + packed top-3; mi-split overlap; NCH=64;
// occupancy 2; zero-C first MMA; fused output write. (R13 body, proven.)
// ---------------------------------------------------------------------------
__global__ void __launch_bounds__(256, 2)
vq_mma_kernel(const float* __restrict__ codes, const float* __restrict__ cb,
              float* __restrict__ out_codes, float* __restrict__ out_ids,
              int write_ids) {
    extern __shared__ char smem[];
    const uint32_t sb = smem_u32(smem);
    const int tid  = threadIdx.x;
    const int wid  = tid >> 5, lane = tid & 31;
    const int wm   = wid >> 2;          // m offset 0/64
    const int wn   = wid & 3;           // n offset 0/16/32/48
    const int qbase = blockIdx.x * MQ;

    for (int i = tid; i < 512; i += 256)
        cpa16(sb + SM_B + i * 16, (const char*)g_Bh + i * 16);
    CPA_COMMIT();

    for (int i = tid; i < MQ * 16; i += 256) {
        int m = i >> 4, kq = i & 15;
        float4 v = *(const float4*)(codes + (size_t)(qbase + m) * DIM + kq * 4);
        __half h[4];
        h[0] = __float2half_rn(v.x); h[1] = __float2half_rn(v.y);
        h[2] = __float2half_rn(v.z); h[3] = __float2half_rn(v.w);
        uint32_t off = sw_off(m, kq >> 1) + (kq & 1) * 8;
        *(uint2*)(smem + SM_A + off) = *(uint2*)h;
    }

    T3 tp[8];
#pragma unroll
    for (int r = 0; r < 8; r++) { tp[r].v1 = -1e30f; tp[r].v2 = -1e30f; tp[r].v3 = -1e30f; }

    float acc[4][2][4];

    const int nlo = (lane & 3) * 2;
    int npos[4];
#pragma unroll
    for (int nj = 0; nj < 2; nj++)
#pragma unroll
        for (int p = 0; p < 2; p++)
            npos[nj * 2 + p] = wn * 16 + nj * 8 + nlo + p;

    for (int c = 0; c < NCHUNKS; c++) {
        const int st = c & 1;
        CPA_WAIT0();
        __syncthreads();

        if (c + 1 < NCHUNKS) {
            const char* bh = (const char*)g_Bh + (size_t)(c + 1) * 8192;
            uint32_t dst = sb + SM_B + (st ^ 1) * 8192;
            for (int i = tid; i < 512; i += 256)
                cpa16(dst + i * 16, bh + i * 16);
            CPA_COMMIT();
        }

        const uint32_t aBase = sb + SM_A;
        const uint32_t bBase = sb + SM_B + st * 8192;
        const bool cg = (c > 0);

        uint32_t bfr[4][4];
        // ---------- block X: mma G1 (mi 0-1) + epilogue G2(prev) ----------
        {
#pragma unroll
            for (int ks = 0; ks < 4; ks++) {
                uint32_t a0[4], a1[4];
                {
                    int ra = wm * 64 + 0 * 16 + (lane & 15);
                    ldm_x4(a0, aBase + sw_off(ra, ks * 2 + (lane >> 4)));
                    ra = wm * 64 + 1 * 16 + (lane & 15);
                    ldm_x4(a1, aBase + sw_off(ra, ks * 2 + (lane >> 4)));
                }
                {
                    int rb = wn * 16 + (lane & 7) + ((lane & 16) ? 8 : 0);
                    ldm_x4(bfr[ks], bBase + sw_off(rb, ks * 2 + ((lane >> 3) & 1)));
                }
#pragma unroll
                for (int nj = 0; nj < 2; nj++) {
                    uint32_t b0 = bfr[ks][nj * 2], b1 = bfr[ks][nj * 2 + 1];
                    if (ks == 0) {
                        mma_f16_z(acc[0][nj], a0, b0, b1);
                        mma_f16_z(acc[1][nj], a1, b0, b1);
                    } else {
                        mma_f16(acc[0][nj], a0, b0, b1);
                        mma_f16(acc[1][nj], a1, b0, b1);
                    }
                }
            }
#pragma unroll
            for (int mi = 2; mi < 4; mi++)
#pragma unroll
                for (int h = 0; h < 2; h++) {
                    T3 t = tp[mi * 2 + h];
#pragma unroll
                    for (int j = 0; j < 4; j++) {
                        uint32_t ic = (uint32_t)(1023 - ((c - 1) * NCH + npos[j]));
                        float s = cg ? pk(acc[mi][(j >> 1)][h * 2 + (j & 1)], ic)
                                     : -1e30f;
                        t3p(t, s);
                    }
                    tp[mi * 2 + h] = t;
                }
        }

        // ---------- block Y: mma G2 (mi 2-3) + epilogue G1(current) ----------
        {
#pragma unroll
            for (int ks = 0; ks < 4; ks++) {
                uint32_t a2[4], a3[4];
                {
                    int ra = wm * 64 + 2 * 16 + (lane & 15);
                    ldm_x4(a2, aBase + sw_off(ra, ks * 2 + (lane >> 4)));
                    ra = wm * 64 + 3 * 16 + (lane & 15);
                    ldm_x4(a3, aBase + sw_off(ra, ks * 2 + (lane >> 4)));
                }
#pragma unroll
                for (int nj = 0; nj < 2; nj++) {
                    uint32_t b0 = bfr[ks][nj * 2], b1 = bfr[ks][nj * 2 + 1];
                    if (ks == 0) {
                        mma_f16_z(acc[2][nj], a2, b0, b1);
                        mma_f16_z(acc[3][nj], a3, b0, b1);
                    } else {
                        mma_f16(acc[2][nj], a2, b0, b1);
                        mma_f16(acc[3][nj], a3, b0, b1);
                    }
                }
            }
#pragma unroll
            for (int mi = 0; mi < 2; mi++)
#pragma unroll
                for (int h = 0; h < 2; h++) {
                    T3 t = tp[mi * 2 + h];
#pragma unroll
                    for (int j = 0; j < 4; j++) {
                        uint32_t ic = (uint32_t)(1023 - (c * NCH + npos[j]));
                        t3p(t, pk(acc[mi][(j >> 1)][h * 2 + (j & 1)], ic));
                    }
                    tp[mi * 2 + h] = t;
                }
        }
    }

    // tail: epilogue G2 of last chunk
    {
#pragma unroll
        for (int mi = 2; mi < 4; mi++)
#pragma unroll
            for (int h = 0; h < 2; h++) {
                T3 t = tp[mi * 2 + h];
#pragma unroll
                for (int j = 0; j < 4; j++) {
                    uint32_t ic = (uint32_t)(1023 - ((NCHUNKS - 1) * NCH + npos[j]));
                    t3p(t, pk(acc[mi][(j >> 1)][h * 2 + (j & 1)], ic));
                }
                tp[mi * 2 + h] = t;
            }
    }

    // intra-warp merge (lanes sharing each row differ in bits 0-1)
#pragma unroll
    for (int r = 0; r < 8; r++) {
#pragma unroll
        for (int d = 1; d <= 2; d <<= 1) {
            float o1 = __shfl_xor_sync(0xffffffffu, tp[r].v1, d);
            float o2 = __shfl_xor_sync(0xffffffffu, tp[r].v2, d);
            float o3 = __shfl_xor_sync(0xffffffffu, tp[r].v3, d);
            t3p(tp[r], o1); t3p(tp[r], o2); t3p(tp[r], o3);
        }
    }

    // cross-warp (wn) merge via smem
    __syncthreads();
    float* rv1 = (float*)(smem + SM_A);
    float* rv2 = (float*)(smem + SM_A + 2048);
    float* rv3 = (float*)(smem + SM_A + 4096);
    if ((lane & 3) == 0) {
#pragma unroll
        for (int mi = 0; mi < 4; mi++)
#pragma unroll
            for (int h = 0; h < 2; h++) {
                int r = mi * 2 + h;
                int row = wm * 64 + mi * 16 + h * 8 + (lane >> 2);
                rv1[row * 4 + wn] = tp[r].v1;
                rv2[row * 4 + wn] = tp[r].v2;
                rv3[row * 4 + wn] = tp[r].v3;
            }
    }
    __syncthreads();

    __shared__ int s_cnt, s_base, s_pcnt, s_pbase;
    __shared__ int s_ids[MQ];
    if (tid == 0) { s_cnt = 0; s_pcnt = 0; }
    __syncthreads();
    int slot = -1, pslot = -1;
    int pi1 = 0, pi2 = 0;
    if (tid < MQ) {
        T3 t;
        t.v1 = rv1[tid * 4]; t.v2 = rv2[tid * 4]; t.v3 = rv3[tid * 4];
#pragma unroll
        for (int w = 1; w < 4; w++) {
            t3p(t, rv1[tid * 4 + w]);
            t3p(t, rv2[tid * 4 + w]);
            t3p(t, rv3[tid * 4 + w]);
        }
        int id = dec_idx(t.v1);
        s_ids[tid] = id;
        g_ids[qbase + tid] = id;
        if (t.v1 - t.v3 < DELTA) {
            slot = atomicAdd(&s_cnt, 1);
        } else if (t.v1 - t.v2 < DELTA) {
            pslot = atomicAdd(&s_pcnt, 1);
            pi1 = id; pi2 = dec_idx(t.v2);
        }
    }
    __syncthreads();
    if (tid == 0) {
        if (s_cnt > 0)  s_base  = atomicAdd(&g_nrescue, s_cnt);
        if (s_pcnt > 0) s_pbase = atomicAdd(&g_npair, s_pcnt);
    }
    __syncthreads();
    if (slot >= 0)  g_rescue[s_base + slot] = qbase + tid;
    if (pslot >= 0) g_pair[s_pbase + pslot] = make_int2(qbase + tid, pi1 | (pi2 << 16));

    // fused output write (pair/rescue rows overwritten by later kernels)
    for (int i = tid; i < MQ * 16; i += 256) {
        int m = i >> 4, part = i & 15;
        int id = s_ids[m];
        float4 v = __ldg((const float4*)(cb + (size_t)id * DIM) + part);
        *(float4*)(out_codes + (size_t)(qbase + m) * DIM + part * 4) = v;
    }
    if (write_ids && tid < MQ)
        out_ids[qbase + tid] = (float)s_ids[tid];
}

// ---------------------------------------------------------------------------
// fused fixup: pair rescoring (grid-stride prologue) + 8-way split rescue.
// ---------------------------------------------------------------------------
#define QB 8
__global__ void fixup_kernel(const float* __restrict__ codes,
                             const float* __restrict__ cb,
                             float* __restrict__ out_codes,
                             float* __restrict__ out_ids, int write_ids) {
    // --- pair rescoring (exact fp32 on two candidates) ---
    int np = g_npair;
    for (int i = blockIdx.x * blockDim.x + threadIdx.x; i < np;
         i += gridDim.x * blockDim.x) {
        int2 e = g_pair[i];
        int q = e.x, i1 = e.y & 0xFFFF, i2 = e.y >> 16;
        const float4* xr = (const float4*)(codes + (size_t)q * DIM);
        const float4* c1 = (const float4*)(cb + (size_t)i1 * DIM);
        const float4* c2 = (const float4*)(cb + (size_t)i2 * DIM);
        float s1 = 0.f, s2 = 0.f;
#pragma unroll
        for (int kq = 0; kq < 16; kq++) {
            float4 x = xr[kq], a = __ldg(&c1[kq]), b = __ldg(&c2[kq]);
            s1 = fmaf(x.x, a.x, s1); s1 = fmaf(x.y, a.y, s1);
            s1 = fmaf(x.z, a.z, s1); s1 = fmaf(x.w, a.w, s1);
            s2 = fmaf(x.x, b.x, s2); s2 = fmaf(x.y, b.y, s2);
            s2 = fmaf(x.z, b.z, s2); s2 = fmaf(x.w, b.w, s2);
        }
        s1 -= g_hcsq[i1]; s2 -= g_hcsq[i2];
        int best = ((s2 > s1) || (s2 == s1 && i2 < i1)) ? i2 : i1;
        g_ids[q] = best;
        if (write_ids) out_ids[q] = (float)best;
        const float4* cr = (const float4*)(cb + (size_t)best * DIM);
#pragma unroll
        for (int kq = 0; kq < 16; kq++)
            *(float4*)(out_codes + (size_t)q * DIM + kq * 4) = __ldg(&cr[kq]);
    }

    // --- 8-way split full rescue ---
    __shared__ float sx[QB][DIM];
    __shared__ float sv[QB][128];
    int nres = g_nrescue;
    int ngb = ((nres + QB - 1) / QB) * 8;
    for (int gb = blockIdx.x; gb < ngb; gb += gridDim.x) {
        int grp = gb >> 3, oct = gb & 7;
        int base = grp * QB;
        int cnt = min(QB, nres - base);
        __syncthreads();
        for (int i = threadIdx.x; i < cnt * 16; i += 128) {
            int q = i >> 4, kq = i & 15;
            ((float4*)sx[q])[kq] =
                ((const float4*)(codes + (size_t)g_rescue[base + q] * DIM))[kq];
        }
        __syncthreads();
        int n = oct * 128 + threadIdx.x;
        const float4* cr = (const float4*)(cb + (size_t)n * DIM);
        float dot[QB];
#pragma unroll
        for (int q = 0; q < QB; q++) dot[q] = 0.f;
#pragma unroll
        for (int kq = 0; kq < 16; kq++) {
            float4 c4 = __ldg(&cr[kq]);
#pragma unroll
            for (int q = 0; q < QB; q++) {
                dot[q] = fmaf(sx[q][kq * 4 + 0], c4.x, dot[q]);
                dot[q] = fmaf(sx[q][kq * 4 + 1], c4.y, dot[q]);
                dot[q] = fmaf(sx[q][kq * 4 + 2], c4.z, dot[q]);
                dot[q] = fmaf(sx[q][kq * 4 + 3], c4.w, dot[q]);
            }
        }
        float hcv = g_hcsq[n];
#pragma unroll
        for (int q = 0; q < QB; q++) sv[q][threadIdx.x] = dot[q] - hcv;
        __syncthreads();
        int w = threadIdx.x >> 5, lane = threadIdx.x & 31;
#pragma unroll
        for (int qq = 0; qq < 2; qq++) {
            int q = w * 2 + qq;
            if (q < cnt) {
                float v = sv[q][lane]; int ix = lane;
                float v2 = sv[q][lane + 32]; int ix2 = lane + 32;
                float v3 = sv[q][lane + 64]; int ix3 = lane + 64;
                float v4 = sv[q][lane + 96]; int ix4 = lane + 96;
                if (v2 > v || (v2 == v && ix2 < ix)) { v = v2; ix = ix2; }
                if (v3 > v || (v3 == v && ix3 < ix)) { v = v3; ix = ix3; }
                if (v4 > v || (v4 == v && ix4 < ix)) { v = v4; ix = ix4; }
#pragma unroll
                for (int d = 16; d > 0; d >>= 1) {
                    float ov = __shfl_down_sync(0xffffffffu, v, d);
                    int   oi = __shfl_down_sync(0xffffffffu, ix, d);
                    if (ov > v || (ov == v && oi < ix)) { v = ov; ix = oi; }
                }
                if (lane == 0) {
                    g_pv[(base + q) * 8 + oct] = v;
                    g_pi[(base + q) * 8 + oct] = oct * 128 + ix;
                }
            }
        }
        __syncthreads();
    }
}

__global__ void rescue_merge(const float* __restrict__ cb,
                             float* __restrict__ out_codes,
                             float* __restrict__ out_ids, int write_ids) {
    for (int i = blockIdx.x * blockDim.x + threadIdx.x; i < g_nrescue;
         i += gridDim.x * blockDim.x) {
        float bv = g_pv[i * 8]; int bi = g_pi[i * 8];
#pragma unroll
        for (int q = 1; q < 8; q++) {
            float v = g_pv[i * 8 + q]; int ix = g_pi[i * 8 + q];
            if (v > bv || (v == bv && ix < bi)) { bv = v; bi = ix; }
        }
        int q = g_rescue[i];
        g_ids[q] = bi;
        if (write_ids) out_ids[q] = (float)bi;
        const float4* cr = (const float4*)(cb + (size_t)bi * DIM);
#pragma unroll
        for (int kq = 0; kq < 16; kq++)
            *(float4*)(out_codes + (size_t)q * DIM + kq * 4) = __ldg(&cr[kq]);
    }
}

// ---------------------------------------------------------------------------
extern "C" void kernel_launch(void* const* d_in, const int* in_sizes, int n_in,
                              void* d_out, int out_size) {
    const float* codes = (const float*)d_in[0];
    const float* cb    = (const float*)d_in[1];
    float* out = (float*)d_out;

    int nq = in_sizes[0] / DIM;
    if (nq > MAX_Q) nq = MAX_Q;

    int write_ids = (out_size >= nq * DIM + nq) ? 1 : 0;
    float* out_ids = out + (size_t)nq * DIM;

    prep_kernel<<<(NT * 16 + 255) / 256, 256>>>(cb);
    vq_mma_kernel<<<nq / MQ, 256, SMEM_TOTAL>>>(codes, cb, out, out_ids, write_ids);
    fixup_kernel<<<1024, 128>>>(codes, cb, out, out_ids, write_ids);
    rescue_merge<<<64, 256>>>(cb, out, out_ids, write_ids);
}

// round 16
// speedup vs baseline: 4.4332x; 1.0180x over previous
#include <cuda_runtime.h>
#include <cuda_fp16.h>
#include <stdint.h>

#define DIM 64
#define NT 1024
#define MQ 128
#define NCH 64
#define NCHUNKS (NT / NCH)      // 16
#define MAX_Q (64 * 4096)
// 1-pass fp16 pairwise err std ~0.6e-3 + mantissa-stomp (<=2.6e-3 worst) -> 0.01
#define DELTA 0.010f
#define QB 8
#define NGRP (MAX_Q / QB)

__device__ int    g_ids[MAX_Q];
__device__ float  g_hcsq[NT];
__device__ __half g_Bh[NT * DIM];     // 16 chunk tiles of 64 rows x 128B
__device__ int    g_nrescue;
__device__ int    g_rescue[MAX_Q];
__device__ int    g_npair;
__device__ int2   g_pair[MAX_Q];
__device__ float  g_pv[MAX_Q * 8];
__device__ int    g_pi[MAX_Q * 8];
__device__ int    g_done[NGRP];

// ---------------- helpers ----------------
__device__ __forceinline__ uint32_t smem_u32(const void* p) {
    uint32_t a;
    asm("{ .reg .u64 t; cvta.to.shared.u64 t, %1; cvt.u32.u64 %0, t; }"
        : "=r"(a) : "l"(p));
    return a;
}
__device__ __forceinline__ void ldm_x4(uint32_t* r, uint32_t addr) {
    asm volatile("ldmatrix.sync.aligned.m8n8.x4.shared.b16 {%0,%1,%2,%3}, [%4];"
                 : "=r"(r[0]), "=r"(r[1]), "=r"(r[2]), "=r"(r[3]) : "r"(addr));
}
__device__ __forceinline__ void mma_f16(float* c, const uint32_t* a,
                                        uint32_t b0, uint32_t b1) {
    asm volatile(
        "mma.sync.aligned.m16n8k16.row.col.f32.f16.f16.f32 "
        "{%0,%1,%2,%3}, {%4,%5,%6,%7}, {%8,%9}, {%0,%1,%2,%3};"
        : "+f"(c[0]), "+f"(c[1]), "+f"(c[2]), "+f"(c[3])
        : "r"(a[0]), "r"(a[1]), "r"(a[2]), "r"(a[3]), "r"(b0), "r"(b1));
}
// first-ks variant: C operand = 0 (kills per-chunk acc reinit movs)
__device__ __forceinline__ void mma_f16_z(float* c, const uint32_t* a,
                                          uint32_t b0, uint32_t b1) {
    asm volatile(
        "mma.sync.aligned.m16n8k16.row.col.f32.f16.f16.f32 "
        "{%0,%1,%2,%3}, {%4,%5,%6,%7}, {%8,%9}, {%10,%10,%10,%10};"
        : "=f"(c[0]), "=f"(c[1]), "=f"(c[2]), "=f"(c[3])
        : "r"(a[0]), "r"(a[1]), "r"(a[2]), "r"(a[3]), "r"(b0), "r"(b1),
          "f"(0.f));
}
__device__ __forceinline__ void cpa16(uint32_t dst, const void* src) {
    asm volatile("cp.async.cg.shared.global [%0], [%1], 16;" :: "r"(dst), "l"(src));
}
#define CPA_COMMIT() asm volatile("cp.async.commit_group;" ::: "memory")
#define CPA_WAIT0()  asm volatile("cp.async.wait_group 0;" ::: "memory")

__device__ __forceinline__ uint32_t sw_off(int row, int chunk) {
    return (uint32_t)row * 128u + (uint32_t)((chunk ^ (row & 7)) << 4);
}

// packed top-3: value's low 10 mantissa bits hold (1023 - n). Pure FMNMX.
struct T3 { float v1, v2, v3; };
__device__ __forceinline__ void t3p(T3& t, float s) {
    float lo  = fminf(s, t.v1);
    t.v1 = fmaxf(s, t.v1);
    float lo2 = fminf(lo, t.v2);
    t.v2 = fmaxf(lo, t.v2);
    t.v3 = fmaxf(lo2, t.v3);
}
__device__ __forceinline__ float pk(float v, uint32_t idxc) {
    return __uint_as_float((__float_as_uint(v) & 0xFFFFFC00u) | idxc);
}
__device__ __forceinline__ int dec_idx(float v) {
    return 1023 - (int)(__float_as_uint(v) & 1023u);
}

// ---------------- smem map (dynamic, 32768 B -> 2 CTAs/SM) ----------------
#define SM_A 0            // 16 KB query tile; reused for merge arrays
#define SM_B 16384        // 2 stages x 8 KB
#define SMEM_TOTAL 32768

// ---------------------------------------------------------------------------
__global__ void prep_kernel(const float* __restrict__ cb) {
    int t = blockIdx.x * blockDim.x + threadIdx.x;
    if (t == 0) { g_nrescue = 0; g_npair = 0; }
    // zero the group-completion counters (graph replay safe)
    if (t < NGRP / 2) { g_done[t] = 0; g_done[t + NGRP / 2] = 0; }
    if (t >= NT * 16) return;
    int n = t >> 4, kq = t & 15;
    float4 v = *(const float4*)(cb + (size_t)n * DIM + kq * 4);
    __half h[4];
    h[0] = __float2half_rn(v.x); h[1] = __float2half_rn(v.y);
    h[2] = __float2half_rn(v.z); h[3] = __float2half_rn(v.w);
    int ch = n >> 6, ln = n & 63;
    uint32_t off = (uint32_t)ch * 8192u + sw_off(ln, kq >> 1) + (kq & 1) * 8;
    *(uint2*)((char*)g_Bh + off) = *(uint2*)h;
    if (kq == 0) {
        const float4* row = (const float4*)(cb + (size_t)n * DIM);
        float s = 0.f;
#pragma unroll
        for (int i = 0; i < 16; i++) {
            float4 w = row[i];
            s += w.x * w.x + w.y * w.y + w.z * w.z + w.w * w.w;
        }
        g_hcsq[n] = 0.5f * s;
    }
}

// ---------------------------------------------------------------------------
// main: 1-pass fp16 mma.sync + packed top-3; mi-split overlap; NCH=64;
// occupancy 2; zero-C first MMA; fused output write. (Proven body.)
// ---------------------------------------------------------------------------
__global__ void __launch_bounds__(256, 2)
vq_mma_kernel(const float* __restrict__ codes, const float* __restrict__ cb,
              float* __restrict__ out_codes, float* __restrict__ out_ids,
              int write_ids) {
    extern __shared__ char smem[];
    const uint32_t sb = smem_u32(smem);
    const int tid  = threadIdx.x;
    const int wid  = tid >> 5, lane = tid & 31;
    const int wm   = wid >> 2;          // m offset 0/64
    const int wn   = wid & 3;           // n offset 0/16/32/48
    const int qbase = blockIdx.x * MQ;

    for (int i = tid; i < 512; i += 256)
        cpa16(sb + SM_B + i * 16, (const char*)g_Bh + i * 16);
    CPA_COMMIT();

    for (int i = tid; i < MQ * 16; i += 256) {
        int m = i >> 4, kq = i & 15;
        float4 v = *(const float4*)(codes + (size_t)(qbase + m) * DIM + kq * 4);
        __half h[4];
        h[0] = __float2half_rn(v.x); h[1] = __float2half_rn(v.y);
        h[2] = __float2half_rn(v.z); h[3] = __float2half_rn(v.w);
        uint32_t off = sw_off(m, kq >> 1) + (kq & 1) * 8;
        *(uint2*)(smem + SM_A + off) = *(uint2*)h;
    }

    T3 tp[8];
#pragma unroll
    for (int r = 0; r < 8; r++) { tp[r].v1 = -1e30f; tp[r].v2 = -1e30f; tp[r].v3 = -1e30f; }

    float acc[4][2][4];

    const int nlo = (lane & 3) * 2;
    int npos[4];
#pragma unroll
    for (int nj = 0; nj < 2; nj++)
#pragma unroll
        for (int p = 0; p < 2; p++)
            npos[nj * 2 + p] = wn * 16 + nj * 8 + nlo + p;

    for (int c = 0; c < NCHUNKS; c++) {
        const int st = c & 1;
        CPA_WAIT0();
        __syncthreads();

        if (c + 1 < NCHUNKS) {
            const char* bh = (const char*)g_Bh + (size_t)(c + 1) * 8192;
            uint32_t dst = sb + SM_B + (st ^ 1) * 8192;
            for (int i = tid; i < 512; i += 256)
                cpa16(dst + i * 16, bh + i * 16);
            CPA_COMMIT();
        }

        const uint32_t aBase = sb + SM_A;
        const uint32_t bBase = sb + SM_B + st * 8192;
        const bool cg = (c > 0);

        uint32_t bfr[4][4];
        // ---------- block X: mma G1 (mi 0-1) + epilogue G2(prev) ----------
        {
#pragma unroll
            for (int ks = 0; ks < 4; ks++) {
                uint32_t a0[4], a1[4];
                {
                    int ra = wm * 64 + 0 * 16 + (lane & 15);
                    ldm_x4(a0, aBase + sw_off(ra, ks * 2 + (lane >> 4)));
                    ra = wm * 64 + 1 * 16 + (lane & 15);
                    ldm_x4(a1, aBase + sw_off(ra, ks * 2 + (lane >> 4)));
                }
                {
                    int rb = wn * 16 + (lane & 7) + ((lane & 16) ? 8 : 0);
                    ldm_x4(bfr[ks], bBase + sw_off(rb, ks * 2 + ((lane >> 3) & 1)));
                }
#pragma unroll
                for (int nj = 0; nj < 2; nj++) {
                    uint32_t b0 = bfr[ks][nj * 2], b1 = bfr[ks][nj * 2 + 1];
                    if (ks == 0) {
                        mma_f16_z(acc[0][nj], a0, b0, b1);
                        mma_f16_z(acc[1][nj], a1, b0, b1);
                    } else {
                        mma_f16(acc[0][nj], a0, b0, b1);
                        mma_f16(acc[1][nj], a1, b0, b1);
                    }
                }
            }
#pragma unroll
            for (int mi = 2; mi < 4; mi++)
#pragma unroll
                for (int h = 0; h < 2; h++) {
                    T3 t = tp[mi * 2 + h];
#pragma unroll
                    for (int j = 0; j < 4; j++) {
                        uint32_t ic = (uint32_t)(1023 - ((c - 1) * NCH + npos[j]));
                        float s = cg ? pk(acc[mi][(j >> 1)][h * 2 + (j & 1)], ic)
                                     : -1e30f;
                        t3p(t, s);
                    }
                    tp[mi * 2 + h] = t;
                }
        }

        // ---------- block Y: mma G2 (mi 2-3) + epilogue G1(current) ----------
        {
#pragma unroll
            for (int ks = 0; ks < 4; ks++) {
                uint32_t a2[4], a3[4];
                {
                    int ra = wm * 64 + 2 * 16 + (lane & 15);
                    ldm_x4(a2, aBase + sw_off(ra, ks * 2 + (lane >> 4)));
                    ra = wm * 64 + 3 * 16 + (lane & 15);
                    ldm_x4(a3, aBase + sw_off(ra, ks * 2 + (lane >> 4)));
                }
#pragma unroll
                for (int nj = 0; nj < 2; nj++) {
                    uint32_t b0 = bfr[ks][nj * 2], b1 = bfr[ks][nj * 2 + 1];
                    if (ks == 0) {
                        mma_f16_z(acc[2][nj], a2, b0, b1);
                        mma_f16_z(acc[3][nj], a3, b0, b1);
                    } else {
                        mma_f16(acc[2][nj], a2, b0, b1);
                        mma_f16(acc[3][nj], a3, b0, b1);
                    }
                }
            }
#pragma unroll
            for (int mi = 0; mi < 2; mi++)
#pragma unroll
                for (int h = 0; h < 2; h++) {
                    T3 t = tp[mi * 2 + h];
#pragma unroll
                    for (int j = 0; j < 4; j++) {
                        uint32_t ic = (uint32_t)(1023 - (c * NCH + npos[j]));
                        t3p(t, pk(acc[mi][(j >> 1)][h * 2 + (j & 1)], ic));
                    }
                    tp[mi * 2 + h] = t;
                }
        }
    }

    // tail: epilogue G2 of last chunk
    {
#pragma unroll
        for (int mi = 2; mi < 4; mi++)
#pragma unroll
            for (int h = 0; h < 2; h++) {
                T3 t = tp[mi * 2 + h];
#pragma unroll
                for (int j = 0; j < 4; j++) {
                    uint32_t ic = (uint32_t)(1023 - ((NCHUNKS - 1) * NCH + npos[j]));
                    t3p(t, pk(acc[mi][(j >> 1)][h * 2 + (j & 1)], ic));
                }
                tp[mi * 2 + h] = t;
            }
    }

    // intra-warp merge (lanes sharing each row differ in bits 0-1)
#pragma unroll
    for (int r = 0; r < 8; r++) {
#pragma unroll
        for (int d = 1; d <= 2; d <<= 1) {
            float o1 = __shfl_xor_sync(0xffffffffu, tp[r].v1, d);
            float o2 = __shfl_xor_sync(0xffffffffu, tp[r].v2, d);
            float o3 = __shfl_xor_sync(0xffffffffu, tp[r].v3, d);
            t3p(tp[r], o1); t3p(tp[r], o2); t3p(tp[r], o3);
        }
    }

    // cross-warp (wn) merge via smem
    __syncthreads();
    float* rv1 = (float*)(smem + SM_A);
    float* rv2 = (float*)(smem + SM_A + 2048);
    float* rv3 = (float*)(smem + SM_A + 4096);
    if ((lane & 3) == 0) {
#pragma unroll
        for (int mi = 0; mi < 4; mi++)
#pragma unroll
            for (int h = 0; h < 2; h++) {
                int r = mi * 2 + h;
                int row = wm * 64 + mi * 16 + h * 8 + (lane >> 2);
                rv1[row * 4 + wn] = tp[r].v1;
                rv2[row * 4 + wn] = tp[r].v2;
                rv3[row * 4 + wn] = tp[r].v3;
            }
    }
    __syncthreads();

    __shared__ int s_cnt, s_base, s_pcnt, s_pbase;
    __shared__ int s_ids[MQ];
    if (tid == 0) { s_cnt = 0; s_pcnt = 0; }
    __syncthreads();
    int slot = -1, pslot = -1;
    int pi1 = 0, pi2 = 0;
    if (tid < MQ) {
        T3 t;
        t.v1 = rv1[tid * 4]; t.v2 = rv2[tid * 4]; t.v3 = rv3[tid * 4];
#pragma unroll
        for (int w = 1; w < 4; w++) {
            t3p(t, rv1[tid * 4 + w]);
            t3p(t, rv2[tid * 4 + w]);
            t3p(t, rv3[tid * 4 + w]);
        }
        int id = dec_idx(t.v1);
        s_ids[tid] = id;
        g_ids[qbase + tid] = id;
        if (t.v1 - t.v3 < DELTA) {
            slot = atomicAdd(&s_cnt, 1);
        } else if (t.v1 - t.v2 < DELTA) {
            pslot = atomicAdd(&s_pcnt, 1);
            pi1 = id; pi2 = dec_idx(t.v2);
        }
    }
    __syncthreads();
    if (tid == 0) {
        if (s_cnt > 0)  s_base  = atomicAdd(&g_nrescue, s_cnt);
        if (s_pcnt > 0) s_pbase = atomicAdd(&g_npair, s_pcnt);
    }
    __syncthreads();
    if (slot >= 0)  g_rescue[s_base + slot] = qbase + tid;
    if (pslot >= 0) g_pair[s_pbase + pslot] = make_int2(qbase + tid, pi1 | (pi2 << 16));

    // fused output write (pair/rescue rows overwritten by fixup)
    for (int i = tid; i < MQ * 16; i += 256) {
        int m = i >> 4, part = i & 15;
        int id = s_ids[m];
        float4 v = __ldg((const float4*)(cb + (size_t)id * DIM) + part);
        *(float4*)(out_codes + (size_t)(qbase + m) * DIM + part * 4) = v;
    }
    if (write_ids && tid < MQ)
        out_ids[qbase + tid] = (float)s_ids[tid];
}

// ---------------------------------------------------------------------------
// fused fixup: pair rescoring + 8-way split rescue + last-block-done merge.
// ---------------------------------------------------------------------------
__global__ void fixup_kernel(const float* __restrict__ codes,
                             const float* __restrict__ cb,
                             float* __restrict__ out_codes,
                             float* __restrict__ out_ids, int write_ids) {
    // --- pair rescoring (exact fp32 on two candidates) ---
    int np = g_npair;
    for (int i = blockIdx.x * blockDim.x + threadIdx.x; i < np;
         i += gridDim.x * blockDim.x) {
        int2 e = g_pair[i];
        int q = e.x, i1 = e.y & 0xFFFF, i2 = e.y >> 16;
        const float4* xr = (const float4*)(codes + (size_t)q * DIM);
        const float4* c1 = (const float4*)(cb + (size_t)i1 * DIM);
        const float4* c2 = (const float4*)(cb + (size_t)i2 * DIM);
        float s1 = 0.f, s2 = 0.f;
#pragma unroll
        for (int kq = 0; kq < 16; kq++) {
            float4 x = xr[kq], a = __ldg(&c1[kq]), b = __ldg(&c2[kq]);
            s1 = fmaf(x.x, a.x, s1); s1 = fmaf(x.y, a.y, s1);
            s1 = fmaf(x.z, a.z, s1); s1 = fmaf(x.w, a.w, s1);
            s2 = fmaf(x.x, b.x, s2); s2 = fmaf(x.y, b.y, s2);
            s2 = fmaf(x.z, b.z, s2); s2 = fmaf(x.w, b.w, s2);
        }
        s1 -= g_hcsq[i1]; s2 -= g_hcsq[i2];
        int best = ((s2 > s1) || (s2 == s1 && i2 < i1)) ? i2 : i1;
        g_ids[q] = best;
        if (write_ids) out_ids[q] = (float)best;
        const float4* cr = (const float4*)(cb + (size_t)best * DIM);
#pragma unroll
        for (int kq = 0; kq < 16; kq++)
            *(float4*)(out_codes + (size_t)q * DIM + kq * 4) = __ldg(&cr[kq]);
    }

    // --- 8-way split full rescue with last-block-done merge ---
    __shared__ float sx[QB][DIM];
    __shared__ float sv[QB][128];
    __shared__ int   s_tick;
    __shared__ int   s_bi[QB];
    int nres = g_nrescue;
    int ngb = ((nres + QB - 1) / QB) * 8;
    for (int gb = blockIdx.x; gb < ngb; gb += gridDim.x) {
        int grp = gb >> 3, oct = gb & 7;
        int base = grp * QB;
        int cnt = min(QB, nres - base);
        __syncthreads();
        for (int i = threadIdx.x; i < cnt * 16; i += 128) {
            int q = i >> 4, kq = i & 15;
            ((float4*)sx[q])[kq] =
                ((const float4*)(codes + (size_t)g_rescue[base + q] * DIM))[kq];
        }
        __syncthreads();
        int n = oct * 128 + threadIdx.x;
        const float4* cr = (const float4*)(cb + (size_t)n * DIM);
        float dot[QB];
#pragma unroll
        for (int q = 0; q < QB; q++) dot[q] = 0.f;
#pragma unroll
        for (int kq = 0; kq < 16; kq++) {
            float4 c4 = __ldg(&cr[kq]);
#pragma unroll
            for (int q = 0; q < QB; q++) {
                dot[q] = fmaf(sx[q][kq * 4 + 0], c4.x, dot[q]);
                dot[q] = fmaf(sx[q][kq * 4 + 1], c4.y, dot[q]);
                dot[q] = fmaf(sx[q][kq * 4 + 2], c4.z, dot[q]);
                dot[q] = fmaf(sx[q][kq * 4 + 3], c4.w, dot[q]);
            }
        }
        float hcv = g_hcsq[n];
#pragma unroll
        for (int q = 0; q < QB; q++) sv[q][threadIdx.x] = dot[q] - hcv;
        __syncthreads();
        int w = threadIdx.x >> 5, lane = threadIdx.x & 31;
#pragma unroll
        for (int qq = 0; qq < 2; qq++) {
            int q = w * 2 + qq;
            if (q < cnt) {
                float v = sv[q][lane]; int ix = lane;
                float v2 = sv[q][lane + 32]; int ix2 = lane + 32;
                float v3 = sv[q][lane + 64]; int ix3 = lane + 64;
                float v4 = sv[q][lane + 96]; int ix4 = lane + 96;
                if (v2 > v || (v2 == v && ix2 < ix)) { v = v2; ix = ix2; }
                if (v3 > v || (v3 == v && ix3 < ix)) { v = v3; ix = ix3; }
                if (v4 > v || (v4 == v && ix4 < ix)) { v = v4; ix = ix4; }
#pragma unroll
                for (int d = 16; d > 0; d >>= 1) {
                    float ov = __shfl_down_sync(0xffffffffu, v, d);
                    int   oi = __shfl_down_sync(0xffffffffu, ix, d);
                    if (ov > v || (ov == v && oi < ix)) { v = ov; ix = oi; }
                }
                if (lane == 0) {
                    g_pv[(base + q) * 8 + oct] = v;
                    g_pi[(base + q) * 8 + oct] = oct * 128 + ix;
                }
            }
        }
        // last block to finish this group performs the merge
        __threadfence();
        __syncthreads();
        if (threadIdx.x == 0) s_tick = atomicAdd(&g_done[grp], 1);
        __syncthreads();
        if (s_tick == 7) {
            if (threadIdx.x < cnt) {
                int i = base + threadIdx.x;
                volatile float* pv = g_pv + (size_t)i * 8;
                volatile int*   pi = g_pi + (size_t)i * 8;
                float bv = pv[0]; int bi = pi[0];
#pragma unroll
                for (int o = 1; o < 8; o++) {
                    float v = pv[o]; int ix = pi[o];
                    if (v > bv || (v == bv && ix < bi)) { bv = v; bi = ix; }
                }
                int q = g_rescue[i];
                g_ids[q] = bi;
                if (write_ids) out_ids[q] = (float)bi;
                s_bi[threadIdx.x] = bi;
            }
            __syncthreads();
            for (int i = threadIdx.x; i < cnt * 16; i += 128) {
                int qq = i >> 4, kq = i & 15;
                int q = g_rescue[base + qq];
                float4 v = __ldg((const float4*)(cb + (size_t)s_bi[qq] * DIM) + kq);
                *(float4*)(out_codes + (size_t)q * DIM + kq * 4) = v;
            }
        }
        __syncthreads();
    }
}

// ---------------------------------------------------------------------------
extern "C" void kernel_launch(void* const* d_in, const int* in_sizes, int n_in,
                              void* d_out, int out_size) {
    const float* codes = (const float*)d_in[0];
    const float* cb    = (const float*)d_in[1];
    float* out = (float*)d_out;

    int nq = in_sizes[0] / DIM;
    if (nq > MAX_Q) nq = MAX_Q;

    int write_ids = (out_size >= nq * DIM + nq) ? 1 : 0;
    float* out_ids = out + (size_t)nq * DIM;

    prep_kernel<<<(NT * 16 + 255) / 256, 256>>>(cb);
    vq_mma_kernel<<<nq / MQ, 256, SMEM_TOTAL>>>(codes, cb, out, out_ids, write_ids);
    fixup_kernel<<<1024, 128>>>(codes, cb, out, out_ids, write_ids);
}